// round 1
// baseline (speedup 1.0000x reference)
#include <cuda_runtime.h>
#include <math.h>

#define NNODE 6000
#define DIM   128
#define RREL  1000
#define NHEAD 2
#define LSEQ  3
#define KMAX  128
#define MAXNF 0.996f

// ---------------- scratch pool (single __device__ symbol) ----------------
// offsets in floats (all multiples of 32 for alignment)
#define O_ECOLS 0L                           // int [2][NNODE][KMAX]
#define O_EVALS (O_ECOLS + 1536000L)         // float[2][NNODE][KMAX]
#define O_ECNT  (O_EVALS + 1536000L)         // int [2][NNODE]  (12032 slots)
#define O_REL   (O_ECNT + 12032L)            // float[2][NNODE][DIM]
#define O_SEQ   (O_REL + 1536000L)           // float[NNODE][LSEQ][DIM]
#define O_HF    (O_SEQ + 2304000L)           // float[NHEAD][NNODE][DIM]
#define O_ES    (O_HF + 1536000L)            // float[NHEAD][NNODE]
#define O_ED    (O_ES + 12032L)
#define O_Q     (O_ED + 12032L)              // float[NNODE*LSEQ*256]
#define O_K     (O_Q + 4608000L)
#define O_V     (O_K + 4608000L)
#define O_OU    (O_V + 4608000L)
#define O_OP    (O_OU + 4608000L)            // float[NNODE*LSEQ*DIM]
#define O_HH    (O_OP + 2304000L)            // float[NNODE*DIM]
#define O_HT    (O_HH + 768000L)
#define O_HMV   (O_HT + 768000L)
#define O_WT    (O_HMV + 768000L)            // float[2*DIM*DIM]
#define O_HB    (O_WT + 32768L)              // float[2*DIM]
#define O_HBN2  (O_HB + 256L)                // float[2]
#define TOTALF  (O_HBN2 + 32L)

__device__ __align__(256) float g_buf[TOTALF];

// ---------------- block reduction helpers (blockDim == 128) ----------------
__device__ __forceinline__ float bsum(float v, float* sh) {
#pragma unroll
    for (int o = 16; o; o >>= 1) v += __shfl_xor_sync(0xffffffffu, v, o);
    int w = threadIdx.x >> 5;
    if ((threadIdx.x & 31) == 0) sh[w] = v;
    __syncthreads();
    float r = sh[0] + sh[1] + sh[2] + sh[3];
    __syncthreads();
    return r;
}

__device__ __forceinline__ void bsum2(float a, float b, float* sh, float* ra, float* rb) {
#pragma unroll
    for (int o = 16; o; o >>= 1) {
        a += __shfl_xor_sync(0xffffffffu, a, o);
        b += __shfl_xor_sync(0xffffffffu, b, o);
    }
    int w = threadIdx.x >> 5;
    if ((threadIdx.x & 31) == 0) { sh[w] = a; sh[4 + w] = b; }
    __syncthreads();
    *ra = sh[0] + sh[1] + sh[2] + sh[3];
    *rb = sh[4] + sh[5] + sh[6] + sh[7];
    __syncthreads();
}

// ---------------- ELL build: ordered warp-ballot compaction ----------------
__global__ void build_ell_k(const float* __restrict__ adj, int* __restrict__ cols,
                            float* __restrict__ vals, int* __restrict__ cnt) {
    int row = blockIdx.x * 8 + (threadIdx.x >> 5);
    if (row >= NNODE) return;
    int lane = threadIdx.x & 31;
    const float* arow = adj + (long)row * NNODE;
    int c = 0;
    for (int base = 0; base < NNODE; base += 32) {
        int col = base + lane;
        float v = (col < NNODE) ? arow[col] : 0.f;
        unsigned m = __ballot_sync(0xffffffffu, v != 0.f);
        if (v != 0.f) {
            int pos = c + __popc(m & ((1u << lane) - 1u));
            if (pos < KMAX) {
                cols[(long)row * KMAX + pos] = col;
                vals[(long)row * KMAX + pos] = v;
            }
        }
        c += __popc(m);
    }
    if (lane == 0) cnt[row] = (c < KMAX) ? c : KMAX;
}

// ---------------- relation aggregation (rowsum-normalized sparse mean) -----
__global__ void rel_agg_k(const float* __restrict__ radj, const float* __restrict__ rel,
                          float* __restrict__ out) {
    __shared__ int sidx[KMAX];
    __shared__ int scnt;
    int row = blockIdx.x, tid = threadIdx.x;
    if (tid < 32) {
        int c = 0;
        for (int base = 0; base < RREL; base += 32) {
            int col = base + tid;
            float v = (col < RREL) ? radj[(long)row * RREL + col] : 0.f;
            unsigned m = __ballot_sync(0xffffffffu, v != 0.f);
            if (v != 0.f) {
                int pos = c + __popc(m & ((1u << tid) - 1u));
                if (pos < KMAX) sidx[pos] = col;
            }
            c += __popc(m);
        }
        if (tid == 0) scnt = (c < KMAX) ? c : KMAX;
    }
    __syncthreads();
    int c = scnt;
    float acc = 0.f;
    for (int j = 0; j < c; j++) acc += rel[(long)sidx[j] * DIM + tid];
    out[(long)row * DIM + tid] = acc / (float)c;
}

// ---------------- generic fp32 tiled GEMM: C = A[MxK] @ B[KxN] -------------
// Requires: Ncols % 64 == 0, K % 16 == 0. Only M is bounds-checked.
__global__ __launch_bounds__(256) void gemm_k(
    const float* __restrict__ A, const float* __restrict__ B, float* __restrict__ C,
    int M, int Ncols, int K, int lda, int ldb, int ldc, long sB, long sC) {
    B += (long)blockIdx.z * sB;
    C += (long)blockIdx.z * sC;
    __shared__ float As[16][64];
    __shared__ float Bs[16][64];
    int tid = threadIdx.x;
    int brow = blockIdx.y * 64;
    int bcol = blockIdx.x * 64;
    int tr = (tid >> 4) * 4;
    int tc = (tid & 15) * 4;
    int a_row = tid >> 2;
    int a_k = (tid & 3) * 4;
    int b_k = tid >> 4;
    int b_col = (tid & 15) * 4;
    float acc[4][4] = {};
    for (int k0 = 0; k0 < K; k0 += 16) {
        int gr = brow + a_row;
        float4 av = make_float4(0.f, 0.f, 0.f, 0.f);
        if (gr < M) av = *reinterpret_cast<const float4*>(A + (long)gr * lda + k0 + a_k);
        As[a_k + 0][a_row] = av.x;
        As[a_k + 1][a_row] = av.y;
        As[a_k + 2][a_row] = av.z;
        As[a_k + 3][a_row] = av.w;
        float4 bv = *reinterpret_cast<const float4*>(B + (long)(k0 + b_k) * ldb + bcol + b_col);
        *reinterpret_cast<float4*>(&Bs[b_k][b_col]) = bv;
        __syncthreads();
#pragma unroll
        for (int kk = 0; kk < 16; kk++) {
            float ar[4], br[4];
#pragma unroll
            for (int i = 0; i < 4; i++) ar[i] = As[kk][tr + i];
#pragma unroll
            for (int j = 0; j < 4; j++) br[j] = Bs[kk][tc + j];
#pragma unroll
            for (int i = 0; i < 4; i++)
#pragma unroll
                for (int j = 0; j < 4; j++) acc[i][j] += ar[i] * br[j];
        }
        __syncthreads();
    }
#pragma unroll
    for (int i = 0; i < 4; i++) {
        int gr = brow + tr + i;
        if (gr < M) {
#pragma unroll
            for (int j = 0; j < 4; j++) C[(long)gr * ldc + bcol + tc + j] = acc[i][j];
        }
    }
}

// ---------------- GAT: es/ed dot products (block = 64 threads) -------------
__global__ void esd_k(const float* __restrict__ hf, const float* __restrict__ as,
                      const float* __restrict__ ad, float* __restrict__ es,
                      float* __restrict__ ed) {
    int n = blockIdx.x;
    int h = threadIdx.x >> 5, lane = threadIdx.x & 31;
    const float* r = hf + ((long)h * NNODE + n) * DIM;
    float s = 0.f, t = 0.f;
#pragma unroll
    for (int d = lane; d < DIM; d += 32) {
        float v = r[d];
        s += v * as[h * DIM + d];
        t += v * ad[h * DIM + d];
    }
#pragma unroll
    for (int o = 16; o; o >>= 1) {
        s += __shfl_xor_sync(0xffffffffu, s, o);
        t += __shfl_xor_sync(0xffffffffu, t, o);
    }
    if (!lane) {
        es[h * NNODE + n] = s;
        ed[h * NNODE + n] = t;
    }
}

// ---------------- GAT: sparse softmax attention + aggregate + elu + norm ---
__global__ void gat_agg_k(const int* __restrict__ cols, const int* __restrict__ cnt,
                          const float* __restrict__ hf, const float* __restrict__ es,
                          const float* __restrict__ ed, float* __restrict__ outp, int ldo) {
    __shared__ int sc[KMAX];
    __shared__ float sw[NHEAD][KMAX];
    __shared__ float sh[8];
    int n = blockIdx.x, tid = threadIdx.x;
    int c = cnt[n];
    for (int j = tid; j < c; j += DIM) sc[j] = cols[(long)n * KMAX + j];
    __syncthreads();
    int w = tid >> 5, lane = tid & 31;
    if (w < NHEAD) {
        float e0 = es[w * NNODE + n];
        float m = -1e30f;
        for (int j = lane; j < c; j += 32) {
            float e = e0 + ed[w * NNODE + sc[j]];
            e = e > 0.f ? e : 0.2f * e;
            sw[w][j] = e;
            m = fmaxf(m, e);
        }
#pragma unroll
        for (int o = 16; o; o >>= 1) m = fmaxf(m, __shfl_xor_sync(0xffffffffu, m, o));
        float s = 0.f;
        for (int j = lane; j < c; j += 32) {
            float e = expf(sw[w][j] - m);
            sw[w][j] = e;
            s += e;
        }
#pragma unroll
        for (int o = 16; o; o >>= 1) s += __shfl_xor_sync(0xffffffffu, s, o);
        float inv = 1.f / s;
        for (int j = lane; j < c; j += 32) sw[w][j] *= inv;
    }
    __syncthreads();
    float a0 = 0.f, a1 = 0.f;
    for (int j = 0; j < c; j++) {
        long cc = sc[j];
        a0 += sw[0][j] * hf[cc * DIM + tid];
        a1 += sw[1][j] * hf[(long)NNODE * DIM + cc * DIM + tid];
    }
    float v = 0.5f * (a0 + a1);
    v = v > 0.f ? v : expm1f(v);
    float ss = bsum(v * v, sh);
    float nrm = fmaxf(sqrtf(ss), 1e-12f);
    outp[(long)n * ldo + tid] = v / nrm;
}

// ---------------- seq slot 0 copy ----------------
__global__ void copy_seq0_k(const float* __restrict__ x, float* __restrict__ seq) {
    int n = blockIdx.x, d = threadIdx.x;
    seq[(long)n * (LSEQ * DIM) + d] = x[(long)n * DIM + d];
}

// ---------------- MHA attention over LSEQ=3 ----------------
__global__ void mha_attn_k(const float* __restrict__ q, const float* __restrict__ k,
                           const float* __restrict__ v, float* __restrict__ o) {
    __shared__ float sq[LSEQ * 2 * DIM];
    __shared__ float sk[LSEQ * 2 * DIM];
    __shared__ float sv[LSEQ * 2 * DIM];
    __shared__ float se[NHEAD][LSEQ][LSEQ];
    int n = blockIdx.x, tid = threadIdx.x;
    long base = (long)n * LSEQ * 2 * DIM;
    for (int i = tid; i < LSEQ * 2 * DIM; i += 128) {
        sq[i] = q[base + i];
        sk[i] = k[base + i];
        sv[i] = v[base + i];
    }
    __syncthreads();
    if (tid < NHEAD * LSEQ * LSEQ) {
        int h = tid / 9, rem = tid % 9, l = rem / 3, m = rem % 3;
        const float* qp = sq + l * 2 * DIM + h * DIM;
        const float* kp = sk + m * 2 * DIM + h * DIM;
        float s = 0.f;
        for (int d = 0; d < DIM; d++) s += qp[d] * kp[d];
        se[h][l][m] = s / 11.313708498984761f;
    }
    __syncthreads();
    if (tid < NHEAD * LSEQ) {
        int h = tid / 3, l = tid % 3;
        float m = fmaxf(se[h][l][0], fmaxf(se[h][l][1], se[h][l][2]));
        float e0 = expf(se[h][l][0] - m), e1 = expf(se[h][l][1] - m), e2 = expf(se[h][l][2] - m);
        float inv = 1.f / (e0 + e1 + e2);
        se[h][l][0] = e0 * inv;
        se[h][l][1] = e1 * inv;
        se[h][l][2] = e2 * inv;
    }
    __syncthreads();
    int d = tid;
    for (int l = 0; l < LSEQ; l++)
#pragma unroll
        for (int h = 0; h < NHEAD; h++) {
            float a = se[h][l][0] * sv[0 * 2 * DIM + h * DIM + d] +
                      se[h][l][1] * sv[1 * 2 * DIM + h * DIM + d] +
                      se[h][l][2] * sv[2 * 2 * DIM + h * DIM + d];
            o[base + l * 2 * DIM + h * DIM + d] = a;
        }
}

// ---------------- MHA epilogue: residual + LayerNorm + mean over L ---------
__global__ void mha_epi_k(const float* __restrict__ op, const float* __restrict__ seq,
                          const float* __restrict__ relb, const float* __restrict__ lng,
                          const float* __restrict__ lnb, float* __restrict__ outsec) {
    __shared__ float sh[8];
    int n = blockIdx.x, d = threadIdx.x;
    float acc = 0.f;
    for (int l = 0; l < LSEQ; l++) {
        long idx = ((long)n * LSEQ + l) * DIM + d;
        float v = op[idx] + seq[idx];
        float mu = bsum(v, sh) * (1.f / DIM);
        float dv = v - mu;
        float var = bsum(dv * dv, sh) * (1.f / DIM);
        acc += lng[d] * dv * rsqrtf(var + 1e-6f) + lnb[d];
    }
    float* row = outsec + (long)n * (2 * DIM);
    row[d] = acc * (1.f / 3.f);
    row[DIM + d] = relb[(long)n * DIM + d];
}

// ---------------- Hyperbolic helpers ----------------
__global__ void expmap0_k(const float* __restrict__ x, float* __restrict__ out) {
    __shared__ float sh[8];
    int n = blockIdx.x, d = threadIdx.x;
    float v = x[(long)n * DIM + d];
    float ss = bsum(v * v, sh);
    float nn = fmaxf(sqrtf(ss), 1e-15f);
    float t = tanhf(nn);
    float a = t / nn;
    if (t > MAXNF) a *= MAXNF / t;
    out[(long)n * DIM + d] = a * v;
}

__global__ void logmap0_k(const float* __restrict__ x, float* __restrict__ out) {
    __shared__ float sh[8];
    int n = blockIdx.x, d = threadIdx.x;
    float v = x[(long)n * DIM + d];
    float ss = bsum(v * v, sh);
    float nn = fmaxf(sqrtf(ss), 1e-15f);
    float s = atanhf(fminf(nn, 1.0f - 1e-7f)) / nn;
    out[(long)n * DIM + d] = s * v;
}

__global__ void hgc_bias_k(const float* __restrict__ b, float* __restrict__ hb,
                           float* __restrict__ hbn2) {
    __shared__ float sh[8];
    int i = blockIdx.x, d = threadIdx.x;
    float v = b[i * DIM + d];
    float ss = bsum(v * v, sh);
    float nn = fmaxf(sqrtf(ss), 1e-15f);
    float t = tanhf(nn);
    float a = t / nn;
    if (t > MAXNF) a *= MAXNF / t;
    float h = a * v;
    hb[i * DIM + d] = h;
    float s2 = bsum(h * h, sh);
    if (!d) hbn2[i] = s2;
}

__global__ void transp_k(const float* __restrict__ W, float* __restrict__ WT) {
    int i = blockIdx.x, e = blockIdx.y, d = threadIdx.x;
    WT[(long)i * DIM * DIM + (long)d * DIM + e] = W[(long)i * DIM * DIM + (long)e * DIM + d];
}

// expmap0+proj, mobius_add(.,hb), proj, logmap0 fused
__global__ void hgc_mid_k(const float* __restrict__ mv, const float* __restrict__ hb,
                          const float* __restrict__ hbn2, int layer, float* __restrict__ t2) {
    __shared__ float sh[8];
    int n = blockIdx.x, d = threadIdx.x;
    float x0 = mv[(long)n * DIM + d];
    float hbv = hb[layer * DIM + d];
    float y2 = hbn2[layer];
    float ss = bsum(x0 * x0, sh);
    float nn = fmaxf(sqrtf(ss), 1e-15f);
    float t = tanhf(nn);
    float a = t / nn;
    if (t > MAXNF) a *= MAXNF / t;
    float xd = a * x0;
    float x2, xy;
    bsum2(xd * xd, xd * hbv, sh, &x2, &xy);
    float num = (1.f + 2.f * xy + y2) * xd + (1.f - x2) * hbv;
    float den = fmaxf(1.f + 2.f * xy + x2 * y2, 1e-15f);
    float h2 = num / den;
    float ss2 = bsum(h2 * h2, sh);
    float nh = fmaxf(sqrtf(ss2), 1e-15f);
    float c = 1.f, npn = nh;
    if (nh > MAXNF) { c = MAXNF / nh; npn = MAXNF; }
    float p = fmaxf(npn, 1e-15f);
    float s = atanhf(fminf(p, 1.0f - 1e-7f)) / p;
    t2[(long)n * DIM + d] = s * c * h2;
}

// sparse agg + expmap0/proj + relu(logmap0) + expmap0/proj fused
__global__ void hgc_agg_k(const int* __restrict__ cols, const float* __restrict__ vals,
                          const int* __restrict__ cnt, const float* __restrict__ tin,
                          float* __restrict__ hout) {
    __shared__ int sc[KMAX];
    __shared__ float svv[KMAX];
    __shared__ float sh[8];
    int n = blockIdx.x, d = threadIdx.x;
    int c = cnt[n];
    for (int j = d; j < c; j += DIM) {
        sc[j] = cols[(long)n * KMAX + j];
        svv[j] = vals[(long)n * KMAX + j];
    }
    __syncthreads();
    float acc = 0.f;
    for (int j = 0; j < c; j++) acc += svv[j] * tin[(long)sc[j] * DIM + d];
    float ss = bsum(acc * acc, sh);
    float nn = fmaxf(sqrtf(ss), 1e-15f);
    float t = tanhf(nn);
    float a = t / nn;
    if (t > MAXNF) a *= MAXNF / t;
    float pd = a * acc;
    float rp = fmaxf(pd, 0.f);
    float p2, r2;
    bsum2(pd * pd, rp * rp, sh, &p2, &r2);
    float npn = fmaxf(sqrtf(p2), 1e-15f);
    float beta = atanhf(fminf(npn, 1.0f - 1e-7f)) / npn;
    float t3 = beta * rp;
    float ss3 = beta * beta * r2;
    float n3 = fmaxf(sqrtf(ss3), 1e-15f);
    float tt = tanhf(n3);
    float aa = tt / n3;
    if (tt > MAXNF) aa *= MAXNF / tt;
    hout[(long)n * DIM + d] = aa * t3;
}

__global__ void hgc_post_k(const float* __restrict__ ent, const float* __restrict__ h,
                           const float* __restrict__ relb, float* __restrict__ outsec) {
    __shared__ float sh[8];
    int n = blockIdx.x, d = threadIdx.x;
    float v = h[(long)n * DIM + d];
    float ss = bsum(v * v, sh);
    float nn = fmaxf(sqrtf(ss), 1e-15f);
    float s = atanhf(fminf(nn, 1.0f - 1e-7f)) / nn;
    float* row = outsec + (long)n * (2 * DIM);
    row[d] = ent[(long)n * DIM + d] + s * v;
    row[DIM + d] = relb[(long)n * DIM + d];
}

// ---------------- host ----------------
static void launch_gemm(const float* A, const float* B, float* C, int M, int Ncols, int K,
                        int lda, int ldb, int ldc, long sB, long sC, int batch) {
    dim3 grid(Ncols / 64, (M + 63) / 64, batch);
    gemm_k<<<grid, 256>>>(A, B, C, M, Ncols, K, lda, ldb, ldc, sB, sC);
}

extern "C" void kernel_launch(void* const* d_in, const int* in_sizes, int n_in,
                              void* d_out, int out_size) {
    (void)in_sizes; (void)n_in; (void)out_size;
    const float* ent[2] = {(const float*)d_in[0], (const float*)d_in[1]};
    const float* rel[2] = {(const float*)d_in[2], (const float*)d_in[3]};
    const float* adj[2] = {(const float*)d_in[4], (const float*)d_in[5]};
    const float* radj[2] = {(const float*)d_in[6], (const float*)d_in[7]};
    const float* gatW = (const float*)d_in[8];
    const float* aS = (const float*)d_in[9];
    const float* aD = (const float*)d_in[10];
    const float* Wq = (const float*)d_in[11];
    const float* Wk = (const float*)d_in[12];
    const float* Wv = (const float*)d_in[13];
    const float* Wfc = (const float*)d_in[14];
    const float* lng = (const float*)d_in[15];
    const float* lnb = (const float*)d_in[16];
    const float* hgcW = (const float*)d_in[17];
    const float* hgcb = (const float*)d_in[18];
    float* out = (float*)d_out;

    float* base = nullptr;
    cudaGetSymbolAddress((void**)&base, g_buf);

    int* ecols = (int*)(base + O_ECOLS);
    float* evals = base + O_EVALS;
    int* ecnt = (int*)(base + O_ECNT);
    float* grel = base + O_REL;
    float* gseq = base + O_SEQ;
    float* ghf = base + O_HF;
    float* ges = base + O_ES;
    float* ged = base + O_ED;
    float* gq = base + O_Q;
    float* gk = base + O_K;
    float* gv = base + O_V;
    float* go = base + O_OU;
    float* gop = base + O_OP;
    float* ghh = base + O_HH;
    float* ght = base + O_HT;
    float* gmv = base + O_HMV;
    float* gwt = base + O_WT;
    float* ghb = base + O_HB;
    float* ghbn2 = base + O_HBN2;

    const long ELLG = (long)NNODE * KMAX;  // per-graph ELL stride

    for (int b = 0; b < 2; b++)
        build_ell_k<<<(NNODE + 7) / 8, 256>>>(adj[b], ecols + b * ELLG, evals + b * ELLG,
                                              ecnt + b * NNODE);
    for (int b = 0; b < 2; b++)
        rel_agg_k<<<NNODE, 128>>>(radj[b], rel[b], grel + (long)b * NNODE * DIM);
    transp_k<<<dim3(2, DIM), DIM>>>(hgcW, gwt);
    hgc_bias_k<<<2, DIM>>>(hgcb, ghb, ghbn2);

    for (int b = 0; b < 2; b++) {
        const int* bcols = ecols + b * ELLG;
        const float* bvals = evals + b * ELLG;
        const int* bcnt = ecnt + b * NNODE;
        const float* brel = grel + (long)b * NNODE * DIM;

        // ---- attentive neighbor aggregator (GAT x2) into seq slots ----
        copy_seq0_k<<<NNODE, DIM>>>(ent[b], gseq);
        for (int layer = 0; layer < 2; layer++) {
            const float* A = (layer == 0) ? ent[b] : (gseq + layer * DIM);
            int lda = (layer == 0) ? DIM : LSEQ * DIM;
            launch_gemm(A, gatW + (long)layer * NHEAD * DIM * DIM, ghf, NNODE, DIM, DIM, lda,
                        DIM, DIM, (long)DIM * DIM, (long)NNODE * DIM, NHEAD);
            esd_k<<<NNODE, 64>>>(ghf, aS + layer * NHEAD * DIM, aD + layer * NHEAD * DIM, ges, ged);
            gat_agg_k<<<NNODE, DIM>>>(bcols, bcnt, ghf, ges, ged, gseq + (layer + 1) * DIM,
                                      LSEQ * DIM);
        }

        // ---- MHA over seq [N,3,128] ----
        launch_gemm(gseq, Wq, gq, NNODE * LSEQ, 2 * DIM, DIM, DIM, 2 * DIM, 2 * DIM, 0, 0, 1);
        launch_gemm(gseq, Wk, gk, NNODE * LSEQ, 2 * DIM, DIM, DIM, 2 * DIM, 2 * DIM, 0, 0, 1);
        launch_gemm(gseq, Wv, gv, NNODE * LSEQ, 2 * DIM, DIM, DIM, 2 * DIM, 2 * DIM, 0, 0, 1);
        mha_attn_k<<<NNODE, 128>>>(gq, gk, gv, go);
        launch_gemm(go, Wfc, gop, NNODE * LSEQ, DIM, 2 * DIM, 2 * DIM, DIM, DIM, 0, 0, 1);
        mha_epi_k<<<NNODE, DIM>>>(gop, gseq, brel, lng, lnb, out + (long)b * NNODE * 2 * DIM);

        // ---- hyperbolic encoder ----
        expmap0_k<<<NNODE, DIM>>>(ent[b], ghh);
        for (int i = 0; i < 2; i++) {
            logmap0_k<<<NNODE, DIM>>>(ghh, ght);
            launch_gemm(ght, gwt + (long)i * DIM * DIM, gmv, NNODE, DIM, DIM, DIM, DIM, DIM, 0,
                        0, 1);
            hgc_mid_k<<<NNODE, DIM>>>(gmv, ghb, ghbn2, i, ght);
            hgc_agg_k<<<NNODE, DIM>>>(bcols, bvals, bcnt, ght, ghh);
        }
        hgc_post_k<<<NNODE, DIM>>>(ent[b], ghh, brel, out + (long)(2 + b) * NNODE * 2 * DIM);
    }
}

// round 2
// speedup vs baseline: 1.3611x; 1.3611x over previous
#include <cuda_runtime.h>
#include <math.h>

#define NNODE 6000
#define DIM   128
#define RREL  1000
#define NHEAD 2
#define LSEQ  3
#define KMAX  128
#define MAXNF 0.996f

// ---------------- scratch pool (single __device__ symbol) ----------------
#define O_ECOLS 0L                           // int [2][NNODE][KMAX]
#define O_EVALS (O_ECOLS + 1536000L)         // float[2][NNODE][KMAX]
#define O_ECNT  (O_EVALS + 1536000L)         // int [2][NNODE]
#define O_REL   (O_ECNT + 12032L)            // float[2][NNODE][DIM]
#define O_SEQ   (O_REL + 1536000L)           // float[NNODE][LSEQ][DIM]
#define O_HF    (O_SEQ + 2304000L)           // float[NHEAD][NNODE][DIM]
#define O_ES    (O_HF + 1536000L)            // float[NHEAD][NNODE]
#define O_ED    (O_ES + 12032L)
#define O_Q     (O_ED + 12032L)              // float[NNODE*LSEQ*256]
#define O_K     (O_Q + 4608000L)
#define O_V     (O_K + 4608000L)
#define O_OU    (O_V + 4608000L)
#define O_OP    (O_OU + 4608000L)            // float[NNODE*LSEQ*DIM]
#define O_HH    (O_OP + 2304000L)            // float[NNODE*DIM]
#define O_HT    (O_HH + 768000L)
#define O_HMV   (O_HT + 768000L)
#define O_WT    (O_HMV + 768000L)            // float[2*DIM*DIM]
#define O_HB    (O_WT + 32768L)              // float[2*DIM]
#define O_HBN2  (O_HB + 256L)                // float[2]
#define TOTALF  (O_HBN2 + 32L)

__device__ __align__(256) float g_buf[TOTALF];

// ---------------- block reduction helpers (blockDim == 128) ----------------
__device__ __forceinline__ float bsum(float v, float* sh) {
#pragma unroll
    for (int o = 16; o; o >>= 1) v += __shfl_xor_sync(0xffffffffu, v, o);
    int w = threadIdx.x >> 5;
    if ((threadIdx.x & 31) == 0) sh[w] = v;
    __syncthreads();
    float r = sh[0] + sh[1] + sh[2] + sh[3];
    __syncthreads();
    return r;
}

__device__ __forceinline__ void bsum2(float a, float b, float* sh, float* ra, float* rb) {
#pragma unroll
    for (int o = 16; o; o >>= 1) {
        a += __shfl_xor_sync(0xffffffffu, a, o);
        b += __shfl_xor_sync(0xffffffffu, b, o);
    }
    int w = threadIdx.x >> 5;
    if ((threadIdx.x & 31) == 0) { sh[w] = a; sh[4 + w] = b; }
    __syncthreads();
    *ra = sh[0] + sh[1] + sh[2] + sh[3];
    *rb = sh[4] + sh[5] + sh[6] + sh[7];
    __syncthreads();
}

// ---------------- ELL build: vectorized ordered compaction -----------------
__global__ void build_ell_k(const float* __restrict__ adj, int* __restrict__ cols,
                            float* __restrict__ vals, int* __restrict__ cnt) {
    int row = blockIdx.x * 8 + (threadIdx.x >> 5);
    int lane = threadIdx.x & 31;
    const float* arow = adj + (long)row * NNODE;
    int c = 0;
    for (int base = 0; base < NNODE; base += 128) {
        int col = base + lane * 4;
        float4 v = make_float4(0.f, 0.f, 0.f, 0.f);
        if (col < NNODE) v = *reinterpret_cast<const float4*>(arow + col);
        float vv[4] = {v.x, v.y, v.z, v.w};
        int lc = (vv[0] != 0.f) + (vv[1] != 0.f) + (vv[2] != 0.f) + (vv[3] != 0.f);
        int pre = lc;
#pragma unroll
        for (int o = 1; o < 32; o <<= 1) {
            int t = __shfl_up_sync(0xffffffffu, pre, o);
            if (lane >= o) pre += t;
        }
        int tot = __shfl_sync(0xffffffffu, pre, 31);
        int p = c + pre - lc;
#pragma unroll
        for (int i = 0; i < 4; i++)
            if (vv[i] != 0.f && p < KMAX) {
                cols[(long)row * KMAX + p] = col + i;
                vals[(long)row * KMAX + p] = vv[i];
                p++;
            }
        c += tot;
    }
    if (!lane) cnt[row] = (c < KMAX) ? c : KMAX;
}

// ---------------- relation aggregation (128-thread scan + compaction) ------
__global__ void rel_agg_k(const float* __restrict__ radj, const float* __restrict__ rel,
                          float* __restrict__ out) {
    __shared__ int sidx[256];
    __shared__ int wsum[4];
    int row = blockIdx.x, t = threadIdx.x, lane = t & 31, w = t >> 5;
    int base = t * 8;
    float e[8];
#pragma unroll
    for (int i = 0; i < 8; i++) e[i] = 0.f;
    if (base < RREL) {
        float4 v0 = *reinterpret_cast<const float4*>(radj + (long)row * RREL + base);
        float4 v1 = *reinterpret_cast<const float4*>(radj + (long)row * RREL + base + 4);
        e[0] = v0.x; e[1] = v0.y; e[2] = v0.z; e[3] = v0.w;
        e[4] = v1.x; e[5] = v1.y; e[6] = v1.z; e[7] = v1.w;
    }
    int lc = 0;
#pragma unroll
    for (int i = 0; i < 8; i++) lc += (e[i] != 0.f);
    int pre = lc;
#pragma unroll
    for (int o = 1; o < 32; o <<= 1) {
        int s = __shfl_up_sync(0xffffffffu, pre, o);
        if (lane >= o) pre += s;
    }
    if (lane == 31) wsum[w] = pre;
    __syncthreads();
    int boff = 0;
    for (int k = 0; k < w; k++) boff += wsum[k];
    int total = wsum[0] + wsum[1] + wsum[2] + wsum[3];
    int p = boff + pre - lc;
#pragma unroll
    for (int i = 0; i < 8; i++)
        if (e[i] != 0.f && p < 256) sidx[p++] = base + i;
    __syncthreads();
    float acc = 0.f;
    for (int j = 0; j < total; j++) acc += rel[(long)sidx[j] * DIM + t];
    out[(long)row * DIM + t] = acc / (float)total;
}

// ---------------- tf32 tensor-core GEMM: C = A[MxK] @ B[KxN] ---------------
// Requires: Ncols % 64 == 0, K % 16 == 0. M bounds-checked.
__device__ __forceinline__ unsigned cvt_tf32(float f) {
    unsigned r;
    asm("cvt.rna.tf32.f32 %0, %1;" : "=r"(r) : "f"(f));
    return r;
}

__device__ __forceinline__ void mma_tf32(float c[4], const unsigned a[4], const unsigned b[2]) {
    asm volatile(
        "mma.sync.aligned.m16n8k8.row.col.f32.tf32.tf32.f32 "
        "{%0,%1,%2,%3}, {%4,%5,%6,%7}, {%8,%9}, {%0,%1,%2,%3};"
        : "+f"(c[0]), "+f"(c[1]), "+f"(c[2]), "+f"(c[3])
        : "r"(a[0]), "r"(a[1]), "r"(a[2]), "r"(a[3]), "r"(b[0]), "r"(b[1]));
}

__global__ __launch_bounds__(128) void gemm_tc_k(
    const float* __restrict__ A, const float* __restrict__ B, float* __restrict__ C,
    int M, int Ncols, int K, int lda, int ldb, int ldc, long sB, long sC) {
    B += (long)blockIdx.z * sB;
    C += (long)blockIdx.z * sC;
    __shared__ unsigned As[16][72];  // [k][m] pad 72 -> conflict-free frag loads
    __shared__ unsigned Bs[16][72];  // [k][n]
    int tid = threadIdx.x;
    int warp = tid >> 5, lane = tid & 31;
    int wr = (warp >> 1) * 32;
    int wc = (warp & 1) * 32;
    int gid = lane >> 2, tig = lane & 3;
    int brow = blockIdx.y * 64, bcol = blockIdx.x * 64;

    int am = tid & 63;
    int ak = (tid >> 6) * 4;
    int bn = (tid & 15) * 4;
    int bk = tid >> 4;

    float acc[2][4][4] = {};

    for (int k0 = 0; k0 < K; k0 += 16) {
#pragma unroll
        for (int h = 0; h < 2; h++) {
            int kk = ak + h * 8;
            int gr = brow + am;
            float4 v = make_float4(0.f, 0.f, 0.f, 0.f);
            if (gr < M) v = *reinterpret_cast<const float4*>(A + (long)gr * lda + k0 + kk);
            As[kk + 0][am] = cvt_tf32(v.x);
            As[kk + 1][am] = cvt_tf32(v.y);
            As[kk + 2][am] = cvt_tf32(v.z);
            As[kk + 3][am] = cvt_tf32(v.w);
        }
#pragma unroll
        for (int h = 0; h < 2; h++) {
            int kk = bk + h * 8;
            float4 v = *reinterpret_cast<const float4*>(B + (long)(k0 + kk) * ldb + bcol + bn);
            Bs[kk][bn + 0] = cvt_tf32(v.x);
            Bs[kk][bn + 1] = cvt_tf32(v.y);
            Bs[kk][bn + 2] = cvt_tf32(v.z);
            Bs[kk][bn + 3] = cvt_tf32(v.w);
        }
        __syncthreads();
#pragma unroll
        for (int kk = 0; kk < 16; kk += 8) {
            unsigned af[2][4];
#pragma unroll
            for (int mi = 0; mi < 2; mi++) {
                int m = wr + mi * 16;
                af[mi][0] = As[kk + tig][m + gid];
                af[mi][1] = As[kk + tig][m + gid + 8];
                af[mi][2] = As[kk + tig + 4][m + gid];
                af[mi][3] = As[kk + tig + 4][m + gid + 8];
            }
            unsigned bf[4][2];
#pragma unroll
            for (int ni = 0; ni < 4; ni++) {
                int n = wc + ni * 8;
                bf[ni][0] = Bs[kk + tig][n + gid];
                bf[ni][1] = Bs[kk + tig + 4][n + gid];
            }
#pragma unroll
            for (int mi = 0; mi < 2; mi++)
#pragma unroll
                for (int ni = 0; ni < 4; ni++) mma_tf32(acc[mi][ni], af[mi], bf[ni]);
        }
        __syncthreads();
    }
#pragma unroll
    for (int mi = 0; mi < 2; mi++) {
        int r0 = brow + wr + mi * 16 + gid;
#pragma unroll
        for (int ni = 0; ni < 4; ni++) {
            int c0 = bcol + wc + ni * 8 + tig * 2;
            if (r0 < M) {
                C[(long)r0 * ldc + c0] = acc[mi][ni][0];
                C[(long)r0 * ldc + c0 + 1] = acc[mi][ni][1];
            }
            if (r0 + 8 < M) {
                C[(long)(r0 + 8) * ldc + c0] = acc[mi][ni][2];
                C[(long)(r0 + 8) * ldc + c0 + 1] = acc[mi][ni][3];
            }
        }
    }
}

// ---------------- GAT: es/ed dot products ----------------
__global__ void esd_k(const float* __restrict__ hf, const float* __restrict__ as,
                      const float* __restrict__ ad, float* __restrict__ es,
                      float* __restrict__ ed) {
    int n = blockIdx.x;
    int h = threadIdx.x >> 5, lane = threadIdx.x & 31;
    const float* r = hf + ((long)h * NNODE + n) * DIM;
    float s = 0.f, t = 0.f;
#pragma unroll
    for (int d = lane; d < DIM; d += 32) {
        float v = r[d];
        s += v * as[h * DIM + d];
        t += v * ad[h * DIM + d];
    }
#pragma unroll
    for (int o = 16; o; o >>= 1) {
        s += __shfl_xor_sync(0xffffffffu, s, o);
        t += __shfl_xor_sync(0xffffffffu, t, o);
    }
    if (!lane) {
        es[h * NNODE + n] = s;
        ed[h * NNODE + n] = t;
    }
}

// ---------------- GAT: sparse softmax attention + aggregate + elu + norm ---
__global__ void gat_agg_k(const int* __restrict__ cols, const int* __restrict__ cnt,
                          const float* __restrict__ hf, const float* __restrict__ es,
                          const float* __restrict__ ed, float* __restrict__ outp, int ldo) {
    __shared__ int sc[KMAX];
    __shared__ float sw[NHEAD][KMAX];
    __shared__ float sh[8];
    int n = blockIdx.x, tid = threadIdx.x;
    int c = cnt[n];
    for (int j = tid; j < c; j += DIM) sc[j] = cols[(long)n * KMAX + j];
    __syncthreads();
    int w = tid >> 5, lane = tid & 31;
    if (w < NHEAD) {
        float e0 = es[w * NNODE + n];
        float m = -1e30f;
        for (int j = lane; j < c; j += 32) {
            float e = e0 + ed[w * NNODE + sc[j]];
            e = e > 0.f ? e : 0.2f * e;
            sw[w][j] = e;
            m = fmaxf(m, e);
        }
#pragma unroll
        for (int o = 16; o; o >>= 1) m = fmaxf(m, __shfl_xor_sync(0xffffffffu, m, o));
        float s = 0.f;
        for (int j = lane; j < c; j += 32) {
            float e = expf(sw[w][j] - m);
            sw[w][j] = e;
            s += e;
        }
#pragma unroll
        for (int o = 16; o; o >>= 1) s += __shfl_xor_sync(0xffffffffu, s, o);
        float inv = 1.f / s;
        for (int j = lane; j < c; j += 32) sw[w][j] *= inv;
    }
    __syncthreads();
    float a0 = 0.f, a1 = 0.f;
    for (int j = 0; j < c; j++) {
        long cc = sc[j];
        a0 += sw[0][j] * hf[cc * DIM + tid];
        a1 += sw[1][j] * hf[(long)NNODE * DIM + cc * DIM + tid];
    }
    float v = 0.5f * (a0 + a1);
    v = v > 0.f ? v : expm1f(v);
    float ss = bsum(v * v, sh);
    float nrm = fmaxf(sqrtf(ss), 1e-12f);
    outp[(long)n * ldo + tid] = v / nrm;
}

// ---------------- seq slot 0 copy ----------------
__global__ void copy_seq0_k(const float* __restrict__ x, float* __restrict__ seq) {
    int n = blockIdx.x, d = threadIdx.x;
    seq[(long)n * (LSEQ * DIM) + d] = x[(long)n * DIM + d];
}

// ---------------- MHA attention over LSEQ=3 ----------------
__global__ void mha_attn_k(const float* __restrict__ q, const float* __restrict__ k,
                           const float* __restrict__ v, float* __restrict__ o) {
    __shared__ float sq[LSEQ * 2 * DIM];
    __shared__ float sk[LSEQ * 2 * DIM];
    __shared__ float sv[LSEQ * 2 * DIM];
    __shared__ float se[NHEAD][LSEQ][LSEQ];
    int n = blockIdx.x, tid = threadIdx.x;
    long base = (long)n * LSEQ * 2 * DIM;
    for (int i = tid; i < LSEQ * 2 * DIM; i += 128) {
        sq[i] = q[base + i];
        sk[i] = k[base + i];
        sv[i] = v[base + i];
    }
    __syncthreads();
    if (tid < NHEAD * LSEQ * LSEQ) {
        int h = tid / 9, rem = tid % 9, l = rem / 3, m = rem % 3;
        const float* qp = sq + l * 2 * DIM + h * DIM;
        const float* kp = sk + m * 2 * DIM + h * DIM;
        float s = 0.f;
        for (int d = 0; d < DIM; d++) s += qp[d] * kp[d];
        se[h][l][m] = s / 11.313708498984761f;
    }
    __syncthreads();
    if (tid < NHEAD * LSEQ) {
        int h = tid / 3, l = tid % 3;
        float m = fmaxf(se[h][l][0], fmaxf(se[h][l][1], se[h][l][2]));
        float e0 = expf(se[h][l][0] - m), e1 = expf(se[h][l][1] - m), e2 = expf(se[h][l][2] - m);
        float inv = 1.f / (e0 + e1 + e2);
        se[h][l][0] = e0 * inv;
        se[h][l][1] = e1 * inv;
        se[h][l][2] = e2 * inv;
    }
    __syncthreads();
    int d = tid;
    for (int l = 0; l < LSEQ; l++)
#pragma unroll
        for (int h = 0; h < NHEAD; h++) {
            float a = se[h][l][0] * sv[0 * 2 * DIM + h * DIM + d] +
                      se[h][l][1] * sv[1 * 2 * DIM + h * DIM + d] +
                      se[h][l][2] * sv[2 * 2 * DIM + h * DIM + d];
            o[base + l * 2 * DIM + h * DIM + d] = a;
        }
}

// ---------------- MHA epilogue: residual + LayerNorm + mean over L ---------
__global__ void mha_epi_k(const float* __restrict__ op, const float* __restrict__ seq,
                          const float* __restrict__ relb, const float* __restrict__ lng,
                          const float* __restrict__ lnb, float* __restrict__ outsec) {
    __shared__ float sh[8];
    int n = blockIdx.x, d = threadIdx.x;
    float acc = 0.f;
    for (int l = 0; l < LSEQ; l++) {
        long idx = ((long)n * LSEQ + l) * DIM + d;
        float v = op[idx] + seq[idx];
        float mu = bsum(v, sh) * (1.f / DIM);
        float dv = v - mu;
        float var = bsum(dv * dv, sh) * (1.f / DIM);
        acc += lng[d] * dv * rsqrtf(var + 1e-6f) + lnb[d];
    }
    float* row = outsec + (long)n * (2 * DIM);
    row[d] = acc * (1.f / 3.f);
    row[DIM + d] = relb[(long)n * DIM + d];
}

// ---------------- Hyperbolic helpers ----------------
__global__ void expmap0_k(const float* __restrict__ x, float* __restrict__ out) {
    __shared__ float sh[8];
    int n = blockIdx.x, d = threadIdx.x;
    float v = x[(long)n * DIM + d];
    float ss = bsum(v * v, sh);
    float nn = fmaxf(sqrtf(ss), 1e-15f);
    float t = tanhf(nn);
    float a = t / nn;
    if (t > MAXNF) a *= MAXNF / t;
    out[(long)n * DIM + d] = a * v;
}

__global__ void logmap0_k(const float* __restrict__ x, float* __restrict__ out) {
    __shared__ float sh[8];
    int n = blockIdx.x, d = threadIdx.x;
    float v = x[(long)n * DIM + d];
    float ss = bsum(v * v, sh);
    float nn = fmaxf(sqrtf(ss), 1e-15f);
    float s = atanhf(fminf(nn, 1.0f - 1e-7f)) / nn;
    out[(long)n * DIM + d] = s * v;
}

__global__ void hgc_bias_k(const float* __restrict__ b, float* __restrict__ hb,
                           float* __restrict__ hbn2) {
    __shared__ float sh[8];
    int i = blockIdx.x, d = threadIdx.x;
    float v = b[i * DIM + d];
    float ss = bsum(v * v, sh);
    float nn = fmaxf(sqrtf(ss), 1e-15f);
    float t = tanhf(nn);
    float a = t / nn;
    if (t > MAXNF) a *= MAXNF / t;
    float h = a * v;
    hb[i * DIM + d] = h;
    float s2 = bsum(h * h, sh);
    if (!d) hbn2[i] = s2;
}

__global__ void transp_k(const float* __restrict__ W, float* __restrict__ WT) {
    int i = blockIdx.x, e = blockIdx.y, d = threadIdx.x;
    WT[(long)i * DIM * DIM + (long)d * DIM + e] = W[(long)i * DIM * DIM + (long)e * DIM + d];
}

__global__ void hgc_mid_k(const float* __restrict__ mv, const float* __restrict__ hb,
                          const float* __restrict__ hbn2, int layer, float* __restrict__ t2) {
    __shared__ float sh[8];
    int n = blockIdx.x, d = threadIdx.x;
    float x0 = mv[(long)n * DIM + d];
    float hbv = hb[layer * DIM + d];
    float y2 = hbn2[layer];
    float ss = bsum(x0 * x0, sh);
    float nn = fmaxf(sqrtf(ss), 1e-15f);
    float t = tanhf(nn);
    float a = t / nn;
    if (t > MAXNF) a *= MAXNF / t;
    float xd = a * x0;
    float x2, xy;
    bsum2(xd * xd, xd * hbv, sh, &x2, &xy);
    float num = (1.f + 2.f * xy + y2) * xd + (1.f - x2) * hbv;
    float den = fmaxf(1.f + 2.f * xy + x2 * y2, 1e-15f);
    float h2 = num / den;
    float ss2 = bsum(h2 * h2, sh);
    float nh = fmaxf(sqrtf(ss2), 1e-15f);
    float c = 1.f, npn = nh;
    if (nh > MAXNF) { c = MAXNF / nh; npn = MAXNF; }
    float p = fmaxf(npn, 1e-15f);
    float s = atanhf(fminf(p, 1.0f - 1e-7f)) / p;
    t2[(long)n * DIM + d] = s * c * h2;
}

__global__ void hgc_agg_k(const int* __restrict__ cols, const float* __restrict__ vals,
                          const int* __restrict__ cnt, const float* __restrict__ tin,
                          float* __restrict__ hout) {
    __shared__ int sc[KMAX];
    __shared__ float svv[KMAX];
    __shared__ float sh[8];
    int n = blockIdx.x, d = threadIdx.x;
    int c = cnt[n];
    for (int j = d; j < c; j += DIM) {
        sc[j] = cols[(long)n * KMAX + j];
        svv[j] = vals[(long)n * KMAX + j];
    }
    __syncthreads();
    float acc = 0.f;
    for (int j = 0; j < c; j++) acc += svv[j] * tin[(long)sc[j] * DIM + d];
    float ss = bsum(acc * acc, sh);
    float nn = fmaxf(sqrtf(ss), 1e-15f);
    float t = tanhf(nn);
    float a = t / nn;
    if (t > MAXNF) a *= MAXNF / t;
    float pd = a * acc;
    float rp = fmaxf(pd, 0.f);
    float p2, r2;
    bsum2(pd * pd, rp * rp, sh, &p2, &r2);
    float npn = fmaxf(sqrtf(p2), 1e-15f);
    float beta = atanhf(fminf(npn, 1.0f - 1e-7f)) / npn;
    float t3 = beta * rp;
    float ss3 = beta * beta * r2;
    float n3 = fmaxf(sqrtf(ss3), 1e-15f);
    float tt = tanhf(n3);
    float aa = tt / n3;
    if (tt > MAXNF) aa *= MAXNF / tt;
    hout[(long)n * DIM + d] = aa * t3;
}

__global__ void hgc_post_k(const float* __restrict__ ent, const float* __restrict__ h,
                           const float* __restrict__ relb, float* __restrict__ outsec) {
    __shared__ float sh[8];
    int n = blockIdx.x, d = threadIdx.x;
    float v = h[(long)n * DIM + d];
    float ss = bsum(v * v, sh);
    float nn = fmaxf(sqrtf(ss), 1e-15f);
    float s = atanhf(fminf(nn, 1.0f - 1e-7f)) / nn;
    float* row = outsec + (long)n * (2 * DIM);
    row[d] = ent[(long)n * DIM + d] + s * v;
    row[DIM + d] = relb[(long)n * DIM + d];
}

// ---------------- host ----------------
static void launch_gemm(const float* A, const float* B, float* C, int M, int Ncols, int K,
                        int lda, int ldb, int ldc, long sB, long sC, int batch) {
    dim3 grid(Ncols / 64, (M + 63) / 64, batch);
    gemm_tc_k<<<grid, 128>>>(A, B, C, M, Ncols, K, lda, ldb, ldc, sB, sC);
}

extern "C" void kernel_launch(void* const* d_in, const int* in_sizes, int n_in,
                              void* d_out, int out_size) {
    (void)in_sizes; (void)n_in; (void)out_size;
    const float* ent[2] = {(const float*)d_in[0], (const float*)d_in[1]};
    const float* rel[2] = {(const float*)d_in[2], (const float*)d_in[3]};
    const float* adj[2] = {(const float*)d_in[4], (const float*)d_in[5]};
    const float* radj[2] = {(const float*)d_in[6], (const float*)d_in[7]};
    const float* gatW = (const float*)d_in[8];
    const float* aS = (const float*)d_in[9];
    const float* aD = (const float*)d_in[10];
    const float* Wq = (const float*)d_in[11];
    const float* Wk = (const float*)d_in[12];
    const float* Wv = (const float*)d_in[13];
    const float* Wfc = (const float*)d_in[14];
    const float* lng = (const float*)d_in[15];
    const float* lnb = (const float*)d_in[16];
    const float* hgcW = (const float*)d_in[17];
    const float* hgcb = (const float*)d_in[18];
    float* out = (float*)d_out;

    float* base = nullptr;
    cudaGetSymbolAddress((void**)&base, g_buf);

    int* ecols = (int*)(base + O_ECOLS);
    float* evals = base + O_EVALS;
    int* ecnt = (int*)(base + O_ECNT);
    float* grel = base + O_REL;
    float* gseq = base + O_SEQ;
    float* ghf = base + O_HF;
    float* ges = base + O_ES;
    float* ged = base + O_ED;
    float* gq = base + O_Q;
    float* gk = base + O_K;
    float* gv = base + O_V;
    float* go = base + O_OU;
    float* gop = base + O_OP;
    float* ghh = base + O_HH;
    float* ght = base + O_HT;
    float* gmv = base + O_HMV;
    float* gwt = base + O_WT;
    float* ghb = base + O_HB;
    float* ghbn2 = base + O_HBN2;

    const long ELLG = (long)NNODE * KMAX;

    for (int b = 0; b < 2; b++)
        build_ell_k<<<(NNODE + 7) / 8, 256>>>(adj[b], ecols + b * ELLG, evals + b * ELLG,
                                              ecnt + b * NNODE);
    for (int b = 0; b < 2; b++)
        rel_agg_k<<<NNODE, 128>>>(radj[b], rel[b], grel + (long)b * NNODE * DIM);
    transp_k<<<dim3(2, DIM), DIM>>>(hgcW, gwt);
    hgc_bias_k<<<2, DIM>>>(hgcb, ghb, ghbn2);

    for (int b = 0; b < 2; b++) {
        const int* bcols = ecols + b * ELLG;
        const float* bvals = evals + b * ELLG;
        const int* bcnt = ecnt + b * NNODE;
        const float* brel = grel + (long)b * NNODE * DIM;

        // ---- attentive neighbor aggregator (GAT x2) into seq slots ----
        copy_seq0_k<<<NNODE, DIM>>>(ent[b], gseq);
        for (int layer = 0; layer < 2; layer++) {
            const float* A = (layer == 0) ? ent[b] : (gseq + layer * DIM);
            int lda = (layer == 0) ? DIM : LSEQ * DIM;
            launch_gemm(A, gatW + (long)layer * NHEAD * DIM * DIM, ghf, NNODE, DIM, DIM, lda,
                        DIM, DIM, (long)DIM * DIM, (long)NNODE * DIM, NHEAD);
            esd_k<<<NNODE, 64>>>(ghf, aS + layer * NHEAD * DIM, aD + layer * NHEAD * DIM, ges, ged);
            gat_agg_k<<<NNODE, DIM>>>(bcols, bcnt, ghf, ges, ged, gseq + (layer + 1) * DIM,
                                      LSEQ * DIM);
        }

        // ---- MHA over seq [N,3,128] ----
        launch_gemm(gseq, Wq, gq, NNODE * LSEQ, 2 * DIM, DIM, DIM, 2 * DIM, 2 * DIM, 0, 0, 1);
        launch_gemm(gseq, Wk, gk, NNODE * LSEQ, 2 * DIM, DIM, DIM, 2 * DIM, 2 * DIM, 0, 0, 1);
        launch_gemm(gseq, Wv, gv, NNODE * LSEQ, 2 * DIM, DIM, DIM, 2 * DIM, 2 * DIM, 0, 0, 1);
        mha_attn_k<<<NNODE, 128>>>(gq, gk, gv, go);
        launch_gemm(go, Wfc, gop, NNODE * LSEQ, DIM, 2 * DIM, 2 * DIM, DIM, DIM, 0, 0, 1);
        mha_epi_k<<<NNODE, DIM>>>(gop, gseq, brel, lng, lnb, out + (long)b * NNODE * 2 * DIM);

        // ---- hyperbolic encoder ----
        expmap0_k<<<NNODE, DIM>>>(ent[b], ghh);
        for (int i = 0; i < 2; i++) {
            logmap0_k<<<NNODE, DIM>>>(ghh, ght);
            launch_gemm(ght, gwt + (long)i * DIM * DIM, gmv, NNODE, DIM, DIM, DIM, DIM, DIM, 0,
                        0, 1);
            hgc_mid_k<<<NNODE, DIM>>>(gmv, ghb, ghbn2, i, ght);
            hgc_agg_k<<<NNODE, DIM>>>(bcols, bvals, bcnt, ght, ghh);
        }
        hgc_post_k<<<NNODE, DIM>>>(ent[b], ghh, brel, out + (long)(2 + b) * NNODE * 2 * DIM);
    }
}

// round 3
// speedup vs baseline: 1.6581x; 1.2182x over previous
#include <cuda_runtime.h>
#include <math.h>

#define NNODE 6000
#define DIM   128
#define RREL  1000
#define NHEAD 2
#define LSEQ  3
#define KMAX  128
#define MAXNF 0.996f

// ---------------- scratch pool ----------------
#define O_ECOLS 0L                            // int [2][NNODE][KMAX]
#define O_EVALS (O_ECOLS + 1536000L)
#define O_ECNT  (O_EVALS + 1536000L)          // int [2][NNODE]
#define O_REL   (O_ECNT + 12032L)             // float[2][NNODE][DIM]
#define O_SEQ   (O_REL + 1536000L)            // float[2][NNODE][LSEQ][DIM]
#define O_HF    (O_SEQ + 4608000L)            // float[2][NHEAD][NNODE][DIM]
#define O_ES    (O_HF + 3072000L)             // float[2*NHEAD*NNODE]
#define O_ED    (O_ES + 24064L)
#define O_QKV   (O_ED + 24064L)               // float[36000][768]
#define O_OU    (O_QKV + 27648000L)           // float[36000][256]
#define O_OP    (O_OU + 9216000L)             // float[36000][128]
#define O_MV    (O_OP + 4608000L)             // float[2][NNODE][DIM]
#define O_T2    (O_MV + 1536000L)
#define O_TOUT  (O_T2 + 1536000L)
#define O_WT    (O_TOUT + 1536000L)           // float[2*DIM*DIM]
#define O_HB    (O_WT + 32768L)
#define O_HBN2  (O_HB + 256L)
#define O_WQKV  (O_HBN2 + 32L)                // float[128*768]
#define TOTALF  (O_WQKV + 98304L)

__device__ __align__(256) float g_buf[TOTALF];

// ---------------- block reduction helpers (blockDim == 128) ----------------
__device__ __forceinline__ float bsum(float v, float* sh) {
#pragma unroll
    for (int o = 16; o; o >>= 1) v += __shfl_xor_sync(0xffffffffu, v, o);
    int w = threadIdx.x >> 5;
    if ((threadIdx.x & 31) == 0) sh[w] = v;
    __syncthreads();
    float r = sh[0] + sh[1] + sh[2] + sh[3];
    __syncthreads();
    return r;
}

__device__ __forceinline__ void bsum2(float a, float b, float* sh, float* ra, float* rb) {
#pragma unroll
    for (int o = 16; o; o >>= 1) {
        a += __shfl_xor_sync(0xffffffffu, a, o);
        b += __shfl_xor_sync(0xffffffffu, b, o);
    }
    int w = threadIdx.x >> 5;
    if ((threadIdx.x & 31) == 0) { sh[w] = a; sh[4 + w] = b; }
    __syncthreads();
    *ra = sh[0] + sh[1] + sh[2] + sh[3];
    *rb = sh[4] + sh[5] + sh[6] + sh[7];
    __syncthreads();
}

// ---------------- ELL build (batched over 2 graphs) ------------------------
__global__ void build_ell_k(const float* __restrict__ adj0, const float* __restrict__ adj1,
                            int* __restrict__ cols, float* __restrict__ vals,
                            int* __restrict__ cnt) {
    int b = blockIdx.y;
    const float* adj = b ? adj1 : adj0;
    long off = (long)b * NNODE;
    int row = blockIdx.x * 8 + (threadIdx.x >> 5);
    int lane = threadIdx.x & 31;
    const float* arow = adj + (long)row * NNODE;
    int c = 0;
    for (int base = 0; base < NNODE; base += 128) {
        int col = base + lane * 4;
        float4 v = make_float4(0.f, 0.f, 0.f, 0.f);
        if (col < NNODE) v = *reinterpret_cast<const float4*>(arow + col);
        float vv[4] = {v.x, v.y, v.z, v.w};
        int lc = (vv[0] != 0.f) + (vv[1] != 0.f) + (vv[2] != 0.f) + (vv[3] != 0.f);
        int pre = lc;
#pragma unroll
        for (int o = 1; o < 32; o <<= 1) {
            int t = __shfl_up_sync(0xffffffffu, pre, o);
            if (lane >= o) pre += t;
        }
        int tot = __shfl_sync(0xffffffffu, pre, 31);
        int p = c + pre - lc;
#pragma unroll
        for (int i = 0; i < 4; i++)
            if (vv[i] != 0.f && p < KMAX) {
                cols[(off + row) * KMAX + p] = col + i;
                vals[(off + row) * KMAX + p] = vv[i];
                p++;
            }
        c += tot;
    }
    if (!lane) cnt[off + row] = (c < KMAX) ? c : KMAX;
}

// ---------------- relation aggregation (batched) ---------------------------
__global__ void rel_agg_k(const float* __restrict__ radj0, const float* __restrict__ radj1,
                          const float* __restrict__ rel0, const float* __restrict__ rel1,
                          float* __restrict__ out) {
    __shared__ int sidx[256];
    __shared__ int wsum[4];
    int b = blockIdx.y;
    const float* radj = b ? radj1 : radj0;
    const float* rel = b ? rel1 : rel0;
    int row = blockIdx.x, t = threadIdx.x, lane = t & 31, w = t >> 5;
    int base = t * 8;
    float e[8];
#pragma unroll
    for (int i = 0; i < 8; i++) e[i] = 0.f;
    if (base < RREL) {
        float4 v0 = *reinterpret_cast<const float4*>(radj + (long)row * RREL + base);
        float4 v1 = *reinterpret_cast<const float4*>(radj + (long)row * RREL + base + 4);
        e[0] = v0.x; e[1] = v0.y; e[2] = v0.z; e[3] = v0.w;
        e[4] = v1.x; e[5] = v1.y; e[6] = v1.z; e[7] = v1.w;
    }
    int lc = 0;
#pragma unroll
    for (int i = 0; i < 8; i++) lc += (e[i] != 0.f);
    int pre = lc;
#pragma unroll
    for (int o = 1; o < 32; o <<= 1) {
        int s = __shfl_up_sync(0xffffffffu, pre, o);
        if (lane >= o) pre += s;
    }
    if (lane == 31) wsum[w] = pre;
    __syncthreads();
    int boff = 0;
    for (int k = 0; k < w; k++) boff += wsum[k];
    int total = wsum[0] + wsum[1] + wsum[2] + wsum[3];
    int p = boff + pre - lc;
#pragma unroll
    for (int i = 0; i < 8; i++)
        if (e[i] != 0.f && p < 256) sidx[p++] = base + i;
    __syncthreads();
    float acc = 0.f;
    for (int j = 0; j < total; j++) acc += rel[(long)sidx[j] * DIM + t];
    out[((long)b * NNODE + row) * DIM + t] = acc / (float)total;
}

// ---------------- tf32 tensor-core GEMM, 128x128x16 tiles ------------------
__device__ __forceinline__ unsigned cvt_tf32(float f) {
    unsigned r;
    asm("cvt.rna.tf32.f32 %0, %1;" : "=r"(r) : "f"(f));
    return r;
}

__device__ __forceinline__ void mma_tf32(float c[4], const unsigned a[4], const unsigned b[2]) {
    asm volatile(
        "mma.sync.aligned.m16n8k8.row.col.f32.tf32.tf32.f32 "
        "{%0,%1,%2,%3}, {%4,%5,%6,%7}, {%8,%9}, {%0,%1,%2,%3};"
        : "+f"(c[0]), "+f"(c[1]), "+f"(c[2]), "+f"(c[3])
        : "r"(a[0]), "r"(a[1]), "r"(a[2]), "r"(a[3]), "r"(b[0]), "r"(b[1]));
}

// Requires Ncols%128==0, K%16==0. M bounds-checked.
// Offsets: A += (z/divA)*sA; B += (z%modB)*sB; C += z*sC.
__global__ __launch_bounds__(256) void gemm_tc_k(
    const float* __restrict__ A, const float* __restrict__ B, float* __restrict__ C,
    int M, int Ncols, int K, int lda, int ldb, int ldc,
    long sA, int divA, long sB, int modB, long sC) {
    int z = blockIdx.z;
    A += (long)(z / divA) * sA;
    B += (long)(z % modB) * sB;
    C += (long)z * sC;
    __shared__ unsigned As[16][136];
    __shared__ unsigned Bs[16][136];
    int tid = threadIdx.x;
    int warp = tid >> 5, lane = tid & 31;
    int gid = lane >> 2, tig = lane & 3;
    int wr = (warp & 3) * 32;
    int wc = (warp >> 2) * 64;
    int brow = blockIdx.y * 128, bcol = blockIdx.x * 128;

    int am = tid & 127;   // A fill: m row
    int akg = tid >> 7;   // k-half (0/1)
    int bn4 = (tid & 31) * 4;  // B fill: n col (x4)
    int bkr = tid >> 5;        // k row 0..7

    float4 aR0, aR1, bR0, bR1;

    // prefetch k0 = 0
    {
        int gr = brow + am;
        if (gr < M) {
            const float* p = A + (long)gr * lda + akg * 8;
            aR0 = *reinterpret_cast<const float4*>(p);
            aR1 = *reinterpret_cast<const float4*>(p + 4);
        } else {
            aR0 = aR1 = make_float4(0.f, 0.f, 0.f, 0.f);
        }
        const float* q = B + (long)bkr * ldb + bcol + bn4;
        bR0 = *reinterpret_cast<const float4*>(q);
        bR1 = *reinterpret_cast<const float4*>(q + 8L * ldb);
    }

    float acc[2][8][4] = {};

    for (int k0 = 0; k0 < K; k0 += 16) {
        // store current tiles
        As[akg * 8 + 0][am] = cvt_tf32(aR0.x);
        As[akg * 8 + 1][am] = cvt_tf32(aR0.y);
        As[akg * 8 + 2][am] = cvt_tf32(aR0.z);
        As[akg * 8 + 3][am] = cvt_tf32(aR0.w);
        As[akg * 8 + 4][am] = cvt_tf32(aR1.x);
        As[akg * 8 + 5][am] = cvt_tf32(aR1.y);
        As[akg * 8 + 6][am] = cvt_tf32(aR1.z);
        As[akg * 8 + 7][am] = cvt_tf32(aR1.w);
        uint4 bb0 = make_uint4(cvt_tf32(bR0.x), cvt_tf32(bR0.y), cvt_tf32(bR0.z), cvt_tf32(bR0.w));
        uint4 bb1 = make_uint4(cvt_tf32(bR1.x), cvt_tf32(bR1.y), cvt_tf32(bR1.z), cvt_tf32(bR1.w));
        *reinterpret_cast<uint4*>(&Bs[bkr][bn4]) = bb0;
        *reinterpret_cast<uint4*>(&Bs[bkr + 8][bn4]) = bb1;
        __syncthreads();

        // prefetch next
        if (k0 + 16 < K) {
            int gr = brow + am;
            if (gr < M) {
                const float* p = A + (long)gr * lda + k0 + 16 + akg * 8;
                aR0 = *reinterpret_cast<const float4*>(p);
                aR1 = *reinterpret_cast<const float4*>(p + 4);
            }
            const float* q = B + (long)(k0 + 16 + bkr) * ldb + bcol + bn4;
            bR0 = *reinterpret_cast<const float4*>(q);
            bR1 = *reinterpret_cast<const float4*>(q + 8L * ldb);
        }

#pragma unroll
        for (int kk = 0; kk < 16; kk += 8) {
            unsigned af[2][4];
#pragma unroll
            for (int mi = 0; mi < 2; mi++) {
                int m = wr + mi * 16;
                af[mi][0] = As[kk + tig][m + gid];
                af[mi][1] = As[kk + tig][m + gid + 8];
                af[mi][2] = As[kk + tig + 4][m + gid];
                af[mi][3] = As[kk + tig + 4][m + gid + 8];
            }
            unsigned bf[8][2];
#pragma unroll
            for (int ni = 0; ni < 8; ni++) {
                int n = wc + ni * 8;
                bf[ni][0] = Bs[kk + tig][n + gid];
                bf[ni][1] = Bs[kk + tig + 4][n + gid];
            }
#pragma unroll
            for (int mi = 0; mi < 2; mi++)
#pragma unroll
                for (int ni = 0; ni < 8; ni++) mma_tf32(acc[mi][ni], af[mi], bf[ni]);
        }
        __syncthreads();
    }

#pragma unroll
    for (int mi = 0; mi < 2; mi++) {
        int r0 = brow + wr + mi * 16 + gid;
#pragma unroll
        for (int ni = 0; ni < 8; ni++) {
            int c0 = bcol + wc + ni * 8 + tig * 2;
            if (r0 < M)
                *reinterpret_cast<float2*>(C + (long)r0 * ldc + c0) =
                    make_float2(acc[mi][ni][0], acc[mi][ni][1]);
            if (r0 + 8 < M)
                *reinterpret_cast<float2*>(C + (long)(r0 + 8) * ldc + c0) =
                    make_float2(acc[mi][ni][2], acc[mi][ni][3]);
        }
    }
}

// ---------------- weight pack / transpose ----------------
__global__ void pack_qkv_k(const float* __restrict__ Wq, const float* __restrict__ Wk,
                           const float* __restrict__ Wv, float* __restrict__ o) {
    int k = blockIdx.x, t = threadIdx.x;
    o[(long)k * 768 + t] = Wq[(long)k * 256 + t];
    o[(long)k * 768 + 256 + t] = Wk[(long)k * 256 + t];
    o[(long)k * 768 + 512 + t] = Wv[(long)k * 256 + t];
}

__global__ void transp_k(const float* __restrict__ W, float* __restrict__ WT) {
    int i = blockIdx.x, e = blockIdx.y, d = threadIdx.x;
    WT[(long)i * DIM * DIM + (long)d * DIM + e] = W[(long)i * DIM * DIM + (long)e * DIM + d];
}

// ---------------- GAT: es/ed dot products (batched) ----------------
__global__ void esd_k(const float* __restrict__ hf, const float* __restrict__ as,
                      const float* __restrict__ ad, float* __restrict__ es,
                      float* __restrict__ ed) {
    int n = blockIdx.x, b = blockIdx.y;
    int h = threadIdx.x >> 5, lane = threadIdx.x & 31;
    const float* r = hf + ((long)(b * NHEAD + h) * NNODE + n) * DIM;
    float s = 0.f, t = 0.f;
#pragma unroll
    for (int d = lane; d < DIM; d += 32) {
        float v = r[d];
        s += v * as[h * DIM + d];
        t += v * ad[h * DIM + d];
    }
#pragma unroll
    for (int o = 16; o; o >>= 1) {
        s += __shfl_xor_sync(0xffffffffu, s, o);
        t += __shfl_xor_sync(0xffffffffu, t, o);
    }
    if (!lane) {
        es[(long)(b * NHEAD + h) * NNODE + n] = s;
        ed[(long)(b * NHEAD + h) * NNODE + n] = t;
    }
}

// ---------------- GAT aggregate + elu + normalize (batched) ----------------
__global__ void gat_agg_k(const int* __restrict__ cols, const int* __restrict__ cnt,
                          const float* __restrict__ hf, const float* __restrict__ es,
                          const float* __restrict__ ed, float* __restrict__ seq, int slot) {
    __shared__ int sc[KMAX];
    __shared__ float sw[NHEAD][KMAX];
    __shared__ float sh[8];
    int n = blockIdx.x, b = blockIdx.y, tid = threadIdx.x;
    long goff = (long)b * NNODE;
    int c = cnt[goff + n];
    for (int j = tid; j < c; j += DIM) sc[j] = cols[(goff + n) * KMAX + j];
    __syncthreads();
    int w = tid >> 5, lane = tid & 31;
    if (w < NHEAD) {
        const float* edp = ed + (long)(b * NHEAD + w) * NNODE;
        float e0 = es[(long)(b * NHEAD + w) * NNODE + n];
        float m = -1e30f;
        for (int j = lane; j < c; j += 32) {
            float e = e0 + edp[sc[j]];
            e = e > 0.f ? e : 0.2f * e;
            sw[w][j] = e;
            m = fmaxf(m, e);
        }
#pragma unroll
        for (int o = 16; o; o >>= 1) m = fmaxf(m, __shfl_xor_sync(0xffffffffu, m, o));
        float s = 0.f;
        for (int j = lane; j < c; j += 32) {
            float e = expf(sw[w][j] - m);
            sw[w][j] = e;
            s += e;
        }
#pragma unroll
        for (int o = 16; o; o >>= 1) s += __shfl_xor_sync(0xffffffffu, s, o);
        float inv = 1.f / s;
        for (int j = lane; j < c; j += 32) sw[w][j] *= inv;
    }
    __syncthreads();
    const float* hf0 = hf + (long)(b * NHEAD) * NNODE * DIM;
    const float* hf1 = hf0 + (long)NNODE * DIM;
    float a0 = 0.f, a1 = 0.f;
    for (int j = 0; j < c; j++) {
        long cc = sc[j];
        a0 += sw[0][j] * hf0[cc * DIM + tid];
        a1 += sw[1][j] * hf1[cc * DIM + tid];
    }
    float v = 0.5f * (a0 + a1);
    v = v > 0.f ? v : expm1f(v);
    float ss = bsum(v * v, sh);
    float nrm = fmaxf(sqrtf(ss), 1e-12f);
    seq[((goff + n) * LSEQ + slot) * DIM + tid] = v / nrm;
}

// ---------------- seq slot 0 copy (batched) ----------------
__global__ void copy_seq0_k(const float* __restrict__ e0, const float* __restrict__ e1,
                            float* __restrict__ seq) {
    int n = blockIdx.x, b = blockIdx.y, d = threadIdx.x;
    const float* x = b ? e1 : e0;
    seq[((long)(b * NNODE + n) * LSEQ) * DIM + d] = x[(long)n * DIM + d];
}

// ---------------- MHA attention (qkv fused layout) ----------------
__global__ void mha_attn_k(const float* __restrict__ qkv, float* __restrict__ o) {
    __shared__ float s[LSEQ][768];
    __shared__ float se[NHEAD][LSEQ][LSEQ];
    int r = blockIdx.x, tid = threadIdx.x;
    long base = (long)r * 3 * 768;
    for (int i = tid; i < 3 * 768; i += 128) s[i / 768][i % 768] = qkv[base + i];
    __syncthreads();
    if (tid < NHEAD * LSEQ * LSEQ) {
        int h = tid / 9, rem = tid % 9, l = rem / 3, m = rem % 3;
        const float* qp = s[l] + h * DIM;
        const float* kp = s[m] + 256 + h * DIM;
        float acc = 0.f;
        for (int d = 0; d < DIM; d++) acc += qp[d] * kp[d];
        se[h][l][m] = acc / 11.313708498984761f;
    }
    __syncthreads();
    if (tid < NHEAD * LSEQ) {
        int h = tid / 3, l = tid % 3;
        float m = fmaxf(se[h][l][0], fmaxf(se[h][l][1], se[h][l][2]));
        float e0 = expf(se[h][l][0] - m), e1 = expf(se[h][l][1] - m), e2 = expf(se[h][l][2] - m);
        float inv = 1.f / (e0 + e1 + e2);
        se[h][l][0] = e0 * inv;
        se[h][l][1] = e1 * inv;
        se[h][l][2] = e2 * inv;
    }
    __syncthreads();
    int d = tid;
    long obase = (long)r * 3 * 256;
    for (int l = 0; l < LSEQ; l++)
#pragma unroll
        for (int h = 0; h < NHEAD; h++) {
            float a = se[h][l][0] * s[0][512 + h * DIM + d] +
                      se[h][l][1] * s[1][512 + h * DIM + d] +
                      se[h][l][2] * s[2][512 + h * DIM + d];
            o[obase + l * 256 + h * DIM + d] = a;
        }
}

// ---------------- MHA epilogue (batched) ----------------
__global__ void mha_epi_k(const float* __restrict__ op, const float* __restrict__ seq,
                          const float* __restrict__ relb, const float* __restrict__ lng,
                          const float* __restrict__ lnb, float* __restrict__ out) {
    __shared__ float sh[8];
    int n = blockIdx.x, b = blockIdx.y, d = threadIdx.x;
    long r = (long)b * NNODE + n;
    float acc = 0.f;
    for (int l = 0; l < LSEQ; l++) {
        long idx = (r * LSEQ + l) * DIM + d;
        float v = op[idx] + seq[idx];
        float mu = bsum(v, sh) * (1.f / DIM);
        float dv = v - mu;
        float var = bsum(dv * dv, sh) * (1.f / DIM);
        acc += lng[d] * dv * rsqrtf(var + 1e-6f) + lnb[d];
    }
    float* row = out + (long)b * NNODE * 2 * DIM + (long)n * 2 * DIM;
    row[d] = acc * (1.f / 3.f);
    row[DIM + d] = relb[r * DIM + d];
}

// ---------------- hyperbolic: fused prologue t = logmap0(proj(expmap0(x))) -
__global__ void hgc_pre_k(const float* __restrict__ e0, const float* __restrict__ e1,
                          float* __restrict__ tout) {
    __shared__ float sh[8];
    int n = blockIdx.x, b = blockIdx.y, d = threadIdx.x;
    const float* x = b ? e1 : e0;
    float v = x[(long)n * DIM + d];
    float ss = bsum(v * v, sh);
    float nn = fmaxf(sqrtf(ss), 1e-15f);
    float t = tanhf(nn);
    float a = t / nn;
    if (t > MAXNF) a = MAXNF / nn;
    float np = fmaxf(a * nn, 1e-15f);
    float s = atanhf(fminf(np, 1.0f - 1e-7f)) / np;
    tout[((long)b * NNODE + n) * DIM + d] = s * a * v;
}

__global__ void hgc_bias_k(const float* __restrict__ b, float* __restrict__ hb,
                           float* __restrict__ hbn2) {
    __shared__ float sh[8];
    int i = blockIdx.x, d = threadIdx.x;
    float v = b[i * DIM + d];
    float ss = bsum(v * v, sh);
    float nn = fmaxf(sqrtf(ss), 1e-15f);
    float t = tanhf(nn);
    float a = t / nn;
    if (t > MAXNF) a *= MAXNF / t;
    float h = a * v;
    hb[i * DIM + d] = h;
    float s2 = bsum(h * h, sh);
    if (!d) hbn2[i] = s2;
}

// expmap0+proj, mobius_add(.,hb), proj, logmap0 (batched)
__global__ void hgc_mid_k(const float* __restrict__ mv, const float* __restrict__ hb,
                          const float* __restrict__ hbn2, int layer, float* __restrict__ t2) {
    __shared__ float sh[8];
    int n = blockIdx.x, b = blockIdx.y, d = threadIdx.x;
    long r = (long)b * NNODE + n;
    float x0 = mv[r * DIM + d];
    float hbv = hb[layer * DIM + d];
    float y2 = hbn2[layer];
    float ss = bsum(x0 * x0, sh);
    float nn = fmaxf(sqrtf(ss), 1e-15f);
    float t = tanhf(nn);
    float a = t / nn;
    if (t > MAXNF) a *= MAXNF / t;
    float xd = a * x0;
    float x2, xy;
    bsum2(xd * xd, xd * hbv, sh, &x2, &xy);
    float num = (1.f + 2.f * xy + y2) * xd + (1.f - x2) * hbv;
    float den = fmaxf(1.f + 2.f * xy + x2 * y2, 1e-15f);
    float h2 = num / den;
    float ss2 = bsum(h2 * h2, sh);
    float nh = fmaxf(sqrtf(ss2), 1e-15f);
    float c = 1.f, npn = nh;
    if (nh > MAXNF) { c = MAXNF / nh; npn = MAXNF; }
    float p = fmaxf(npn, 1e-15f);
    float s = atanhf(fminf(p, 1.0f - 1e-7f)) / p;
    t2[r * DIM + d] = s * c * h2;
}

// sparse agg + expmap0/proj + relu(logmap0) + expmap0/proj + logmap0, fused (batched)
__global__ void hgc_agg_k(const int* __restrict__ cols, const float* __restrict__ vals,
                          const int* __restrict__ cnt, const float* __restrict__ tin,
                          float* __restrict__ tout) {
    __shared__ int sc[KMAX];
    __shared__ float svv[KMAX];
    __shared__ float sh[8];
    int n = blockIdx.x, b = blockIdx.y, d = threadIdx.x;
    long goff = (long)b * NNODE;
    int c = cnt[goff + n];
    for (int j = d; j < c; j += DIM) {
        sc[j] = cols[(goff + n) * KMAX + j];
        svv[j] = vals[(goff + n) * KMAX + j];
    }
    __syncthreads();
    const float* tb = tin + goff * DIM;
    float acc = 0.f;
    for (int j = 0; j < c; j++) acc += svv[j] * tb[(long)sc[j] * DIM + d];
    float ss = bsum(acc * acc, sh);
    float nn = fmaxf(sqrtf(ss), 1e-15f);
    float t = tanhf(nn);
    float a = t / nn;
    if (t > MAXNF) a *= MAXNF / t;
    float pd = a * acc;
    float rp = fmaxf(pd, 0.f);
    float p2, r2;
    bsum2(pd * pd, rp * rp, sh, &p2, &r2);
    float npn = fmaxf(sqrtf(p2), 1e-15f);
    float beta = atanhf(fminf(npn, 1.0f - 1e-7f)) / npn;
    float t3 = beta * rp;
    float n3 = fmaxf(beta * sqrtf(r2), 1e-15f);
    float tt = tanhf(n3);
    float aa = tt / n3;
    if (tt > MAXNF) aa *= MAXNF / tt;
    // logmap0 of (aa * t3): norm = aa * n3
    float nh = fmaxf(aa * n3, 1e-15f);
    float s2 = atanhf(fminf(nh, 1.0f - 1e-7f)) / nh;
    tout[(goff + n) * DIM + d] = s2 * aa * t3;
}

__global__ void hgc_post_k(const float* __restrict__ e0, const float* __restrict__ e1,
                           const float* __restrict__ tout, const float* __restrict__ relb,
                           float* __restrict__ out) {
    int n = blockIdx.x, b = blockIdx.y, d = threadIdx.x;
    long r = (long)b * NNODE + n;
    const float* x = b ? e1 : e0;
    float* row = out + (long)b * NNODE * 2 * DIM + (long)n * 2 * DIM;
    row[d] = x[(long)n * DIM + d] + tout[r * DIM + d];
    row[DIM + d] = relb[r * DIM + d];
}

// ---------------- host ----------------
extern "C" void kernel_launch(void* const* d_in, const int* in_sizes, int n_in,
                              void* d_out, int out_size) {
    (void)in_sizes; (void)n_in; (void)out_size;
    const float* ent0 = (const float*)d_in[0];
    const float* ent1 = (const float*)d_in[1];
    const float* rel0 = (const float*)d_in[2];
    const float* rel1 = (const float*)d_in[3];
    const float* adj0 = (const float*)d_in[4];
    const float* adj1 = (const float*)d_in[5];
    const float* radj0 = (const float*)d_in[6];
    const float* radj1 = (const float*)d_in[7];
    const float* gatW = (const float*)d_in[8];
    const float* aS = (const float*)d_in[9];
    const float* aD = (const float*)d_in[10];
    const float* Wq = (const float*)d_in[11];
    const float* Wk = (const float*)d_in[12];
    const float* Wv = (const float*)d_in[13];
    const float* Wfc = (const float*)d_in[14];
    const float* lng = (const float*)d_in[15];
    const float* lnb = (const float*)d_in[16];
    const float* hgcW = (const float*)d_in[17];
    const float* hgcb = (const float*)d_in[18];
    float* out = (float*)d_out;

    float* base = nullptr;
    cudaGetSymbolAddress((void**)&base, g_buf);

    int* ecols = (int*)(base + O_ECOLS);
    float* evals = base + O_EVALS;
    int* ecnt = (int*)(base + O_ECNT);
    float* grel = base + O_REL;
    float* gseq = base + O_SEQ;
    float* ghf = base + O_HF;
    float* ges = base + O_ES;
    float* ged = base + O_ED;
    float* gqkv = base + O_QKV;
    float* go = base + O_OU;
    float* gop = base + O_OP;
    float* gmv = base + O_MV;
    float* gt2 = base + O_T2;
    float* gtout = base + O_TOUT;
    float* gwt = base + O_WT;
    float* ghb = base + O_HB;
    float* ghbn2 = base + O_HBN2;
    float* gwqkv = base + O_WQKV;

    const long BSEQ = (long)NNODE * LSEQ * DIM;   // branch stride of seq
    const long BND = (long)NNODE * DIM;

    // ---- preprocessing ----
    build_ell_k<<<dim3(NNODE / 8, 2), 256>>>(adj0, adj1, ecols, evals, ecnt);
    rel_agg_k<<<dim3(NNODE, 2), 128>>>(radj0, radj1, rel0, rel1, grel);
    transp_k<<<dim3(2, DIM), DIM>>>(hgcW, gwt);
    hgc_bias_k<<<2, DIM>>>(hgcb, ghb, ghbn2);
    pack_qkv_k<<<DIM, 256>>>(Wq, Wk, Wv, gwqkv);
    copy_seq0_k<<<dim3(NNODE, 2), DIM>>>(ent0, ent1, gseq);
    hgc_pre_k<<<dim3(NNODE, 2), DIM>>>(ent0, ent1, gtout);

    // ---- GAT x2 layers, both branches + both heads batched (z=4) ----
    for (int layer = 0; layer < 2; layer++) {
        gemm_tc_k<<<dim3(1, 47, 4), 256>>>(
            gseq + (long)layer * DIM, gatW + (long)layer * NHEAD * DIM * DIM, ghf,
            NNODE, DIM, DIM, LSEQ * DIM, DIM, DIM,
            BSEQ, NHEAD, (long)DIM * DIM, NHEAD, BND);
        esd_k<<<dim3(NNODE, 2), 64>>>(ghf, aS + layer * NHEAD * DIM, aD + layer * NHEAD * DIM,
                                      ges, ged);
        gat_agg_k<<<dim3(NNODE, 2), DIM>>>(ecols, ecnt, ghf, ges, ged, gseq, layer + 1);
    }

    // ---- MHA (both branches in one shot: 36000 rows) ----
    gemm_tc_k<<<dim3(6, 282, 1), 256>>>(gseq, gwqkv, gqkv, 2 * NNODE * LSEQ, 768, DIM,
                                        DIM, 768, 768, 0, 1, 0, 1, 0);
    mha_attn_k<<<2 * NNODE, 128>>>(gqkv, go);
    gemm_tc_k<<<dim3(1, 282, 1), 256>>>(go, Wfc, gop, 2 * NNODE * LSEQ, DIM, 2 * DIM,
                                        2 * DIM, DIM, DIM, 0, 1, 0, 1, 0);
    mha_epi_k<<<dim3(NNODE, 2), DIM>>>(gop, gseq, grel, lng, lnb, out);

    // ---- hyperbolic encoder (z=2 batched) ----
    for (int i = 0; i < 2; i++) {
        gemm_tc_k<<<dim3(1, 47, 2), 256>>>(gtout, gwt + (long)i * DIM * DIM, gmv,
                                           NNODE, DIM, DIM, DIM, DIM, DIM,
                                           BND, 1, 0, 1, BND);
        hgc_mid_k<<<dim3(NNODE, 2), DIM>>>(gmv, ghb, ghbn2, i, gt2);
        hgc_agg_k<<<dim3(NNODE, 2), DIM>>>(ecols, evals, ecnt, gt2, gtout);
    }
    hgc_post_k<<<dim3(NNODE, 2), DIM>>>(ent0, ent1, gtout, grel,
                                        out + 2L * NNODE * 2 * DIM);
}

// round 5
// speedup vs baseline: 1.9205x; 1.1583x over previous
#include <cuda_runtime.h>
#include <math.h>

#define NNODE 6000
#define DIM   128
#define RREL  1000
#define NHEAD 2
#define LSEQ  3
#define KMAX  128
#define MAXNF 0.996f

// ---------------- scratch pool ----------------
#define O_ECOLS 0L                            // int [2][NNODE][KMAX]
#define O_EVALS (O_ECOLS + 1536000L)
#define O_ECNT  (O_EVALS + 1536000L)          // int [2][NNODE]
#define O_REL   (O_ECNT + 12032L)             // float[2][NNODE][DIM]
#define O_SEQ   (O_REL + 1536000L)            // float[2][NNODE][LSEQ][DIM]
#define O_HF    (O_SEQ + 4608000L)            // float[2][NHEAD][NNODE][DIM]
#define O_ES    (O_HF + 3072000L)             // float[2*NHEAD*NNODE]
#define O_ED    (O_ES + 24064L)
#define O_Y     (O_ED + 24064L)               // float[2][36000][128]
#define O_Z     (O_Y + 9216000L)              // float[36000][256]
#define O_OP    (O_Z + 9216000L)              // float[36000][128]
#define O_MV    (O_OP + 4608000L)             // float[2][NNODE][DIM]
#define O_T2    (O_MV + 1536000L)
#define O_TOUT  (O_T2 + 1536000L)
#define O_WT    (O_TOUT + 1536000L)           // float[2*DIM*DIM]
#define O_HB    (O_WT + 32768L)
#define O_HBN2  (O_HB + 256L)
#define O_A     (O_HBN2 + 32L)                // float[2][128][128]
#define O_G     (O_A + 32768L)                // float[256][128]
#define TOTALF  (O_G + 32768L)

__device__ __align__(256) float g_buf[TOTALF];

// ---------------- block reduction helpers (blockDim == 128) ----------------
__device__ __forceinline__ float bsum(float v, float* sh) {
#pragma unroll
    for (int o = 16; o; o >>= 1) v += __shfl_xor_sync(0xffffffffu, v, o);
    int w = threadIdx.x >> 5;
    if ((threadIdx.x & 31) == 0) sh[w] = v;
    __syncthreads();
    float r = sh[0] + sh[1] + sh[2] + sh[3];
    __syncthreads();
    return r;
}

__device__ __forceinline__ void bsum2(float a, float b, float* sh, float* ra, float* rb) {
#pragma unroll
    for (int o = 16; o; o >>= 1) {
        a += __shfl_xor_sync(0xffffffffu, a, o);
        b += __shfl_xor_sync(0xffffffffu, b, o);
    }
    int w = threadIdx.x >> 5;
    if ((threadIdx.x & 31) == 0) { sh[w] = a; sh[4 + w] = b; }
    __syncthreads();
    *ra = sh[0] + sh[1] + sh[2] + sh[3];
    *rb = sh[4] + sh[5] + sh[6] + sh[7];
    __syncthreads();
}

// ---------------- ELL build (batched over 2 graphs) ------------------------
__global__ void build_ell_k(const float* __restrict__ adj0, const float* __restrict__ adj1,
                            int* __restrict__ cols, float* __restrict__ vals,
                            int* __restrict__ cnt) {
    int b = blockIdx.y;
    const float* adj = b ? adj1 : adj0;
    long off = (long)b * NNODE;
    int row = blockIdx.x * 8 + (threadIdx.x >> 5);
    int lane = threadIdx.x & 31;
    const float* arow = adj + (long)row * NNODE;
    int c = 0;
    for (int base = 0; base < NNODE; base += 128) {
        int col = base + lane * 4;
        float4 v = make_float4(0.f, 0.f, 0.f, 0.f);
        if (col < NNODE) v = *reinterpret_cast<const float4*>(arow + col);
        float vv[4] = {v.x, v.y, v.z, v.w};
        int lc = (vv[0] != 0.f) + (vv[1] != 0.f) + (vv[2] != 0.f) + (vv[3] != 0.f);
        int pre = lc;
#pragma unroll
        for (int o = 1; o < 32; o <<= 1) {
            int t = __shfl_up_sync(0xffffffffu, pre, o);
            if (lane >= o) pre += t;
        }
        int tot = __shfl_sync(0xffffffffu, pre, 31);
        int p = c + pre - lc;
#pragma unroll
        for (int i = 0; i < 4; i++)
            if (vv[i] != 0.f && p < KMAX) {
                cols[(off + row) * KMAX + p] = col + i;
                vals[(off + row) * KMAX + p] = vv[i];
                p++;
            }
        c += tot;
    }
    if (!lane) cnt[off + row] = (c < KMAX) ? c : KMAX;
}

// ---------------- relation aggregation (batched) ---------------------------
__global__ void rel_agg_k(const float* __restrict__ radj0, const float* __restrict__ radj1,
                          const float* __restrict__ rel0, const float* __restrict__ rel1,
                          float* __restrict__ out) {
    __shared__ int sidx[256];
    __shared__ int wsum[4];
    int b = blockIdx.y;
    const float* radj = b ? radj1 : radj0;
    const float* rel = b ? rel1 : rel0;
    int row = blockIdx.x, t = threadIdx.x, lane = t & 31, w = t >> 5;
    int base = t * 8;
    float e[8];
#pragma unroll
    for (int i = 0; i < 8; i++) e[i] = 0.f;
    if (base < RREL) {
        float4 v0 = *reinterpret_cast<const float4*>(radj + (long)row * RREL + base);
        float4 v1 = *reinterpret_cast<const float4*>(radj + (long)row * RREL + base + 4);
        e[0] = v0.x; e[1] = v0.y; e[2] = v0.z; e[3] = v0.w;
        e[4] = v1.x; e[5] = v1.y; e[6] = v1.z; e[7] = v1.w;
    }
    int lc = 0;
#pragma unroll
    for (int i = 0; i < 8; i++) lc += (e[i] != 0.f);
    int pre = lc;
#pragma unroll
    for (int o = 1; o < 32; o <<= 1) {
        int s = __shfl_up_sync(0xffffffffu, pre, o);
        if (lane >= o) pre += s;
    }
    if (lane == 31) wsum[w] = pre;
    __syncthreads();
    int boff = 0;
    for (int k = 0; k < w; k++) boff += wsum[k];
    int total = wsum[0] + wsum[1] + wsum[2] + wsum[3];
    int p = boff + pre - lc;
#pragma unroll
    for (int i = 0; i < 8; i++)
        if (e[i] != 0.f && p < 256) sidx[p++] = base + i;
    __syncthreads();
    float acc = 0.f;
    for (int j = 0; j < total; j++) acc += rel[(long)sidx[j] * DIM + t];
    out[((long)b * NNODE + row) * DIM + t] = acc / (float)total;
}

// ---------------- tf32 tensor-core GEMM, 128x128x16 tiles ------------------
__device__ __forceinline__ unsigned cvt_tf32(float f) {
    unsigned r;
    asm("cvt.rna.tf32.f32 %0, %1;" : "=r"(r) : "f"(f));
    return r;
}

__device__ __forceinline__ void mma_tf32(float c[4], const unsigned a[4], const unsigned b[2]) {
    asm volatile(
        "mma.sync.aligned.m16n8k8.row.col.f32.tf32.tf32.f32 "
        "{%0,%1,%2,%3}, {%4,%5,%6,%7}, {%8,%9}, {%0,%1,%2,%3};"
        : "+f"(c[0]), "+f"(c[1]), "+f"(c[2]), "+f"(c[3])
        : "r"(a[0]), "r"(a[1]), "r"(a[2]), "r"(a[3]), "r"(b[0]), "r"(b[1]));
}

// Requires Ncols%128==0, K%16==0. M bounds-checked.
// Offsets: A += (z/divA)*sA; B += (z%modB)*sB; C += z*sC.
__global__ __launch_bounds__(256) void gemm_tc_k(
    const float* __restrict__ A, const float* __restrict__ B, float* __restrict__ C,
    int M, int Ncols, int K, int lda, int ldb, int ldc,
    long sA, int divA, long sB, int modB, long sC) {
    int z = blockIdx.z;
    A += (long)(z / divA) * sA;
    B += (long)(z % modB) * sB;
    C += (long)z * sC;
    __shared__ unsigned As[16][136];
    __shared__ unsigned Bs[16][136];
    int tid = threadIdx.x;
    int warp = tid >> 5, lane = tid & 31;
    int gid = lane >> 2, tig = lane & 3;
    int wr = (warp & 3) * 32;
    int wc = (warp >> 2) * 64;
    int brow = blockIdx.y * 128, bcol = blockIdx.x * 128;

    int am = tid & 127;
    int akg = tid >> 7;
    int bn4 = (tid & 31) * 4;
    int bkr = tid >> 5;

    float4 aR0, aR1, bR0, bR1;

    {
        int gr = brow + am;
        if (gr < M) {
            const float* p = A + (long)gr * lda + akg * 8;
            aR0 = *reinterpret_cast<const float4*>(p);
            aR1 = *reinterpret_cast<const float4*>(p + 4);
        } else {
            aR0 = aR1 = make_float4(0.f, 0.f, 0.f, 0.f);
        }
        const float* q = B + (long)bkr * ldb + bcol + bn4;
        bR0 = *reinterpret_cast<const float4*>(q);
        bR1 = *reinterpret_cast<const float4*>(q + 8L * ldb);
    }

    float acc[2][8][4] = {};

    for (int k0 = 0; k0 < K; k0 += 16) {
        As[akg * 8 + 0][am] = cvt_tf32(aR0.x);
        As[akg * 8 + 1][am] = cvt_tf32(aR0.y);
        As[akg * 8 + 2][am] = cvt_tf32(aR0.z);
        As[akg * 8 + 3][am] = cvt_tf32(aR0.w);
        As[akg * 8 + 4][am] = cvt_tf32(aR1.x);
        As[akg * 8 + 5][am] = cvt_tf32(aR1.y);
        As[akg * 8 + 6][am] = cvt_tf32(aR1.z);
        As[akg * 8 + 7][am] = cvt_tf32(aR1.w);
        uint4 bb0 = make_uint4(cvt_tf32(bR0.x), cvt_tf32(bR0.y), cvt_tf32(bR0.z), cvt_tf32(bR0.w));
        uint4 bb1 = make_uint4(cvt_tf32(bR1.x), cvt_tf32(bR1.y), cvt_tf32(bR1.z), cvt_tf32(bR1.w));
        *reinterpret_cast<uint4*>(&Bs[bkr][bn4]) = bb0;
        *reinterpret_cast<uint4*>(&Bs[bkr + 8][bn4]) = bb1;
        __syncthreads();

        if (k0 + 16 < K) {
            int gr = brow + am;
            if (gr < M) {
                const float* p = A + (long)gr * lda + k0 + 16 + akg * 8;
                aR0 = *reinterpret_cast<const float4*>(p);
                aR1 = *reinterpret_cast<const float4*>(p + 4);
            }
            const float* q = B + (long)(k0 + 16 + bkr) * ldb + bcol + bn4;
            bR0 = *reinterpret_cast<const float4*>(q);
            bR1 = *reinterpret_cast<const float4*>(q + 8L * ldb);
        }

#pragma unroll
        for (int kk = 0; kk < 16; kk += 8) {
            unsigned af[2][4];
#pragma unroll
            for (int mi = 0; mi < 2; mi++) {
                int m = wr + mi * 16;
                af[mi][0] = As[kk + tig][m + gid];
                af[mi][1] = As[kk + tig][m + gid + 8];
                af[mi][2] = As[kk + tig + 4][m + gid];
                af[mi][3] = As[kk + tig + 4][m + gid + 8];
            }
            unsigned bf[8][2];
#pragma unroll
            for (int ni = 0; ni < 8; ni++) {
                int n = wc + ni * 8;
                bf[ni][0] = Bs[kk + tig][n + gid];
                bf[ni][1] = Bs[kk + tig + 4][n + gid];
            }
#pragma unroll
            for (int mi = 0; mi < 2; mi++)
#pragma unroll
                for (int ni = 0; ni < 8; ni++) mma_tf32(acc[mi][ni], af[mi], bf[ni]);
        }
        __syncthreads();
    }

#pragma unroll
    for (int mi = 0; mi < 2; mi++) {
        int r0 = brow + wr + mi * 16 + gid;
#pragma unroll
        for (int ni = 0; ni < 8; ni++) {
            int c0 = bcol + wc + ni * 8 + tig * 2;
            if (r0 < M)
                *reinterpret_cast<float2*>(C + (long)r0 * ldc + c0) =
                    make_float2(acc[mi][ni][0], acc[mi][ni][1]);
            if (r0 + 8 < M)
                *reinterpret_cast<float2*>(C + (long)(r0 + 8) * ldc + c0) =
                    make_float2(acc[mi][ni][2], acc[mi][ni][3]);
        }
    }
}

// ---------------- MHA weight folding (fp32): A_h = Wq_h Wk_h^T / sqrt(D); G = Wv_h Wfc_h ----
__global__ void prep_mha_k(const float* __restrict__ Wq, const float* __restrict__ Wk,
                           const float* __restrict__ Wv, const float* __restrict__ Wfc,
                           float* __restrict__ Am, float* __restrict__ G) {
    int d = blockIdx.x, mat = blockIdx.y, t = threadIdx.x;
    int h = mat & 1;
    float s = 0.f;
    if (mat < 2) {
        for (int j = 0; j < 128; j++)
            s += Wq[d * 256 + h * 128 + j] * Wk[t * 256 + h * 128 + j];
        Am[(h * 128 + d) * 128 + t] = s * 0.08838834764831845f;  // 1/sqrt(128)
    } else {
        for (int j = 0; j < 128; j++)
            s += Wv[d * 256 + h * 128 + j] * Wfc[(h * 128 + j) * 128 + t];
        G[(h * 128 + d) * 128 + t] = s;
    }
}

// ---------------- hgcW transpose + hyperbolic bias (merged) ----------------
__global__ void setup_w_k(const float* __restrict__ hgcW, const float* __restrict__ hgcb,
                          float* __restrict__ WT, float* __restrict__ hb,
                          float* __restrict__ hbn2) {
    __shared__ float sh[8];
    int i = blockIdx.x, d = threadIdx.x;
    if (blockIdx.y < 128) {
        int e = blockIdx.y;
        WT[(long)i * 16384 + (long)d * 128 + e] = hgcW[(long)i * 16384 + (long)e * 128 + d];
    } else {
        float v = hgcb[i * DIM + d];
        float ss = bsum(v * v, sh);
        float nn = fmaxf(sqrtf(ss), 1e-15f);
        float t = tanhf(nn);
        float a = t / nn;
        if (t > MAXNF) a *= MAXNF / t;
        float h = a * v;
        hb[i * DIM + d] = h;
        float s2 = bsum(h * h, sh);
        if (!d) hbn2[i] = s2;
    }
}

// ---------------- init: seq slot0 copy + hyperbolic prologue (merged) ------
__global__ void init_node_k(const float* __restrict__ e0, const float* __restrict__ e1,
                            float* __restrict__ seq, float* __restrict__ tout) {
    __shared__ float sh[8];
    int n = blockIdx.x, b = blockIdx.y, d = threadIdx.x;
    const float* x = b ? e1 : e0;
    float v = x[(long)n * DIM + d];
    long r = (long)b * NNODE + n;
    seq[r * LSEQ * DIM + d] = v;
    float ss = bsum(v * v, sh);
    float nn = fmaxf(sqrtf(ss), 1e-15f);
    float t = tanhf(nn);
    float a = t / nn;
    if (t > MAXNF) a = MAXNF / nn;
    float np = fmaxf(a * nn, 1e-15f);
    float s = atanhf(fminf(np, 1.0f - 1e-7f)) / np;
    tout[r * DIM + d] = s * a * v;
}

// ---------------- GAT: es/ed dot products (batched) ----------------
__global__ void esd_k(const float* __restrict__ hf, const float* __restrict__ as,
                      const float* __restrict__ ad, float* __restrict__ es,
                      float* __restrict__ ed) {
    int n = blockIdx.x, b = blockIdx.y;
    int h = threadIdx.x >> 5, lane = threadIdx.x & 31;
    const float* r = hf + ((long)(b * NHEAD + h) * NNODE + n) * DIM;
    float s = 0.f, t = 0.f;
#pragma unroll
    for (int d = lane; d < DIM; d += 32) {
        float v = r[d];
        s += v * as[h * DIM + d];
        t += v * ad[h * DIM + d];
    }
#pragma unroll
    for (int o = 16; o; o >>= 1) {
        s += __shfl_xor_sync(0xffffffffu, s, o);
        t += __shfl_xor_sync(0xffffffffu, t, o);
    }
    if (!lane) {
        es[(long)(b * NHEAD + h) * NNODE + n] = s;
        ed[(long)(b * NHEAD + h) * NNODE + n] = t;
    }
}

// ---------------- GAT aggregate + elu + normalize (batched) ----------------
__global__ void gat_agg_k(const int* __restrict__ cols, const int* __restrict__ cnt,
                          const float* __restrict__ hf, const float* __restrict__ es,
                          const float* __restrict__ ed, float* __restrict__ seq, int slot) {
    __shared__ int sc[KMAX];
    __shared__ float sw[NHEAD][KMAX];
    __shared__ float sh[8];
    int n = blockIdx.x, b = blockIdx.y, tid = threadIdx.x;
    long goff = (long)b * NNODE;
    int c = cnt[goff + n];
    for (int j = tid; j < c; j += DIM) sc[j] = cols[(goff + n) * KMAX + j];
    __syncthreads();
    int w = tid >> 5, lane = tid & 31;
    if (w < NHEAD) {
        const float* edp = ed + (long)(b * NHEAD + w) * NNODE;
        float e0 = es[(long)(b * NHEAD + w) * NNODE + n];
        float m = -1e30f;
        for (int j = lane; j < c; j += 32) {
            float e = e0 + edp[sc[j]];
            e = e > 0.f ? e : 0.2f * e;
            sw[w][j] = e;
            m = fmaxf(m, e);
        }
#pragma unroll
        for (int o = 16; o; o >>= 1) m = fmaxf(m, __shfl_xor_sync(0xffffffffu, m, o));
        float s = 0.f;
        for (int j = lane; j < c; j += 32) {
            float e = expf(sw[w][j] - m);
            sw[w][j] = e;
            s += e;
        }
#pragma unroll
        for (int o = 16; o; o >>= 1) s += __shfl_xor_sync(0xffffffffu, s, o);
        float inv = 1.f / s;
        for (int j = lane; j < c; j += 32) sw[w][j] *= inv;
    }
    __syncthreads();
    const float* hf0 = hf + (long)(b * NHEAD) * NNODE * DIM;
    const float* hf1 = hf0 + (long)NNODE * DIM;
    float a0 = 0.f, a1 = 0.f;
    for (int j = 0; j < c; j++) {
        long cc = sc[j];
        a0 += sw[0][j] * hf0[cc * DIM + tid];
        a1 += sw[1][j] * hf1[cc * DIM + tid];
    }
    float v = 0.5f * (a0 + a1);
    v = v > 0.f ? v : expm1f(v);
    float ss = bsum(v * v, sh);
    float nrm = fmaxf(sqrtf(ss), 1e-12f);
    seq[((goff + n) * LSEQ + slot) * DIM + tid] = v / nrm;
}

// ---------------- attention: e = y.x dots, softmax, z = attn @ x -----------
__global__ void attn_z_k(const float* __restrict__ seq, const float* __restrict__ y,
                         float* __restrict__ z) {
    __shared__ float sx[LSEQ][DIM];
    __shared__ float sy[NHEAD][LSEQ][DIM];
    __shared__ float se[NHEAD][LSEQ][LSEQ];
    int r = blockIdx.x, tid = threadIdx.x, w = tid >> 5, lane = tid & 31;
    long r3 = (long)r * LSEQ;
    for (int i = tid; i < LSEQ * DIM; i += 128) sx[i >> 7][i & 127] = seq[r3 * DIM + i];
    for (int i = tid; i < NHEAD * LSEQ * DIM; i += 128) {
        int h = i / (LSEQ * DIM), rem = i % (LSEQ * DIM);
        sy[h][rem >> 7][rem & 127] = y[(long)h * 4608000L + r3 * DIM + rem];
    }
    __syncthreads();
    for (int idx = w; idx < NHEAD * LSEQ * LSEQ; idx += 4) {
        int h = idx / 9, rem = idx % 9, l = rem / 3, m = rem % 3;
        float s = 0.f;
#pragma unroll
        for (int d = lane; d < DIM; d += 32) s += sy[h][l][d] * sx[m][d];
#pragma unroll
        for (int o = 16; o; o >>= 1) s += __shfl_xor_sync(0xffffffffu, s, o);
        if (!lane) se[h][l][m] = s;
    }
    __syncthreads();
    if (tid < NHEAD * LSEQ) {
        int h = tid / 3, l = tid % 3;
        float m = fmaxf(se[h][l][0], fmaxf(se[h][l][1], se[h][l][2]));
        float e0 = expf(se[h][l][0] - m), e1 = expf(se[h][l][1] - m), e2 = expf(se[h][l][2] - m);
        float inv = 1.f / (e0 + e1 + e2);
        se[h][l][0] = e0 * inv;
        se[h][l][1] = e1 * inv;
        se[h][l][2] = e2 * inv;
    }
    __syncthreads();
    int d = tid;
    for (int l = 0; l < LSEQ; l++)
#pragma unroll
        for (int h = 0; h < NHEAD; h++) {
            float a = se[h][l][0] * sx[0][d] + se[h][l][1] * sx[1][d] + se[h][l][2] * sx[2][d];
            z[(r3 + l) * 256 + h * DIM + d] = a;
        }
}

// ---------------- MHA epilogue (batched) ----------------
__global__ void mha_epi_k(const float* __restrict__ op, const float* __restrict__ seq,
                          const float* __restrict__ relb, const float* __restrict__ lng,
                          const float* __restrict__ lnb, float* __restrict__ out) {
    __shared__ float sh[8];
    int n = blockIdx.x, b = blockIdx.y, d = threadIdx.x;
    long r = (long)b * NNODE + n;
    float acc = 0.f;
    for (int l = 0; l < LSEQ; l++) {
        long idx = (r * LSEQ + l) * DIM + d;
        float v = op[idx] + seq[idx];
        float mu = bsum(v, sh) * (1.f / DIM);
        float dv = v - mu;
        float var = bsum(dv * dv, sh) * (1.f / DIM);
        acc += lng[d] * dv * rsqrtf(var + 1e-6f) + lnb[d];
    }
    float* row = out + (long)b * NNODE * 2 * DIM + (long)n * 2 * DIM;
    row[d] = acc * (1.f / 3.f);
    row[DIM + d] = relb[r * DIM + d];
}

// expmap0+proj, mobius_add(.,hb), proj, logmap0 (batched)
__global__ void hgc_mid_k(const float* __restrict__ mv, const float* __restrict__ hb,
                          const float* __restrict__ hbn2, int layer, float* __restrict__ t2) {
    __shared__ float sh[8];
    int n = blockIdx.x, b = blockIdx.y, d = threadIdx.x;
    long r = (long)b * NNODE + n;
    float x0 = mv[r * DIM + d];
    float hbv = hb[layer * DIM + d];
    float y2 = hbn2[layer];
    float ss = bsum(x0 * x0, sh);
    float nn = fmaxf(sqrtf(ss), 1e-15f);
    float t = tanhf(nn);
    float a = t / nn;
    if (t > MAXNF) a *= MAXNF / t;
    float xd = a * x0;
    float x2, xy;
    bsum2(xd * xd, xd * hbv, sh, &x2, &xy);
    float num = (1.f + 2.f * xy + y2) * xd + (1.f - x2) * hbv;
    float den = fmaxf(1.f + 2.f * xy + x2 * y2, 1e-15f);
    float h2 = num / den;
    float ss2 = bsum(h2 * h2, sh);
    float nh = fmaxf(sqrtf(ss2), 1e-15f);
    float c = 1.f, npn = nh;
    if (nh > MAXNF) { c = MAXNF / nh; npn = MAXNF; }
    float p = fmaxf(npn, 1e-15f);
    float s = atanhf(fminf(p, 1.0f - 1e-7f)) / p;
    t2[r * DIM + d] = s * c * h2;
}

// sparse agg + expmap0/proj + relu(logmap0) + expmap0/proj + logmap0 fused
__global__ void hgc_agg_k(const int* __restrict__ cols, const float* __restrict__ vals,
                          const int* __restrict__ cnt, const float* __restrict__ tin,
                          float* __restrict__ tout) {
    __shared__ int sc[KMAX];
    __shared__ float svv[KMAX];
    __shared__ float sh[8];
    int n = blockIdx.x, b = blockIdx.y, d = threadIdx.x;
    long goff = (long)b * NNODE;
    int c = cnt[goff + n];
    for (int j = d; j < c; j += DIM) {
        sc[j] = cols[(goff + n) * KMAX + j];
        svv[j] = vals[(goff + n) * KMAX + j];
    }
    __syncthreads();
    const float* tb = tin + goff * DIM;
    float acc = 0.f;
    for (int j = 0; j < c; j++) acc += svv[j] * tb[(long)sc[j] * DIM + d];
    float ss = bsum(acc * acc, sh);
    float nn = fmaxf(sqrtf(ss), 1e-15f);
    float t = tanhf(nn);
    float a = t / nn;
    if (t > MAXNF) a *= MAXNF / t;
    float pd = a * acc;
    float rp = fmaxf(pd, 0.f);
    float p2, r2;
    bsum2(pd * pd, rp * rp, sh, &p2, &r2);
    float npn = fmaxf(sqrtf(p2), 1e-15f);
    float beta = atanhf(fminf(npn, 1.0f - 1e-7f)) / npn;
    float t3 = beta * rp;
    float n3 = fmaxf(beta * sqrtf(r2), 1e-15f);
    float tt = tanhf(n3);
    float aa = tt / n3;
    if (tt > MAXNF) aa *= MAXNF / tt;
    float nh = fmaxf(aa * n3, 1e-15f);
    float s2 = atanhf(fminf(nh, 1.0f - 1e-7f)) / nh;
    tout[(goff + n) * DIM + d] = s2 * aa * t3;
}

__global__ void hgc_post_k(const float* __restrict__ e0, const float* __restrict__ e1,
                           const float* __restrict__ tout, const float* __restrict__ relb,
                           float* __restrict__ out) {
    int n = blockIdx.x, b = blockIdx.y, d = threadIdx.x;
    long r = (long)b * NNODE + n;
    const float* x = b ? e1 : e0;
    float* row = out + (long)b * NNODE * 2 * DIM + (long)n * 2 * DIM;
    row[d] = x[(long)n * DIM + d] + tout[r * DIM + d];
    row[DIM + d] = relb[r * DIM + d];
}

// ---------------- host ----------------
extern "C" void kernel_launch(void* const* d_in, const int* in_sizes, int n_in,
                              void* d_out, int out_size) {
    (void)in_sizes; (void)n_in; (void)out_size;
    const float* ent0 = (const float*)d_in[0];
    const float* ent1 = (const float*)d_in[1];
    const float* rel0 = (const float*)d_in[2];
    const float* rel1 = (const float*)d_in[3];
    const float* adj0 = (const float*)d_in[4];
    const float* adj1 = (const float*)d_in[5];
    const float* radj0 = (const float*)d_in[6];
    const float* radj1 = (const float*)d_in[7];
    const float* gatW = (const float*)d_in[8];
    const float* aS = (const float*)d_in[9];
    const float* aD = (const float*)d_in[10];
    const float* Wq = (const float*)d_in[11];
    const float* Wk = (const float*)d_in[12];
    const float* Wv = (const float*)d_in[13];
    const float* Wfc = (const float*)d_in[14];
    const float* lng = (const float*)d_in[15];
    const float* lnb = (const float*)d_in[16];
    const float* hgcW = (const float*)d_in[17];
    const float* hgcb = (const float*)d_in[18];
    float* out = (float*)d_out;

    float* base = nullptr;
    cudaGetSymbolAddress((void**)&base, g_buf);

    int* ecols = (int*)(base + O_ECOLS);
    float* evals = base + O_EVALS;
    int* ecnt = (int*)(base + O_ECNT);
    float* grel = base + O_REL;
    float* gseq = base + O_SEQ;
    float* ghf = base + O_HF;
    float* ges = base + O_ES;
    float* ged = base + O_ED;
    float* gy = base + O_Y;
    float* gz = base + O_Z;
    float* gop = base + O_OP;
    float* gmv = base + O_MV;
    float* gt2 = base + O_T2;
    float* gtout = base + O_TOUT;
    float* gwt = base + O_WT;
    float* ghb = base + O_HB;
    float* ghbn2 = base + O_HBN2;
    float* gA = base + O_A;
    float* gG = base + O_G;

    const long BSEQ = (long)NNODE * LSEQ * DIM;
    const long BND = (long)NNODE * DIM;

    // ---- preprocessing ----
    build_ell_k<<<dim3(NNODE / 8, 2), 256>>>(adj0, adj1, ecols, evals, ecnt);
    rel_agg_k<<<dim3(NNODE, 2), 128>>>(radj0, radj1, rel0, rel1, grel);
    setup_w_k<<<dim3(2, 129), DIM>>>(hgcW, hgcb, gwt, ghb, ghbn2);
    prep_mha_k<<<dim3(DIM, 4), DIM>>>(Wq, Wk, Wv, Wfc, gA, gG);
    init_node_k<<<dim3(NNODE, 2), DIM>>>(ent0, ent1, gseq, gtout);

    // ---- GAT x2 layers, both branches + both heads batched (z=4) ----
    for (int layer = 0; layer < 2; layer++) {
        gemm_tc_k<<<dim3(1, 47, 4), 256>>>(
            gseq + (long)layer * DIM, gatW + (long)layer * NHEAD * DIM * DIM, ghf,
            NNODE, DIM, DIM, LSEQ * DIM, DIM, DIM,
            BSEQ, NHEAD, (long)DIM * DIM, NHEAD, BND);
        esd_k<<<dim3(NNODE, 2), 64>>>(ghf, aS + layer * NHEAD * DIM, aD + layer * NHEAD * DIM,
                                      ges, ged);
        gat_agg_k<<<dim3(NNODE, 2), DIM>>>(ecols, ecnt, ghf, ges, ged, gseq, layer + 1);
    }

    // ---- MHA via folded weights ----
    gemm_tc_k<<<dim3(1, 282, 2), 256>>>(gseq, gA, gy, 2 * NNODE * LSEQ, DIM, DIM,
                                        DIM, DIM, DIM, 0, 1, (long)DIM * DIM, 2,
                                        (long)2 * NNODE * LSEQ * DIM);
    attn_z_k<<<2 * NNODE, 128>>>(gseq, gy, gz);
    gemm_tc_k<<<dim3(1, 282, 1), 256>>>(gz, gG, gop, 2 * NNODE * LSEQ, DIM, 2 * DIM,
                                        2 * DIM, DIM, DIM, 0, 1, 0, 1, 0);
    mha_epi_k<<<dim3(NNODE, 2), DIM>>>(gop, gseq, grel, lng, lnb, out);

    // ---- hyperbolic encoder (z=2 batched) ----
    for (int i = 0; i < 2; i++) {
        gemm_tc_k<<<dim3(1, 47, 2), 256>>>(gtout, gwt + (long)i * DIM * DIM, gmv,
                                           NNODE, DIM, DIM, DIM, DIM, DIM,
                                           BND, 1, 0, 1, BND);
        hgc_mid_k<<<dim3(NNODE, 2), DIM>>>(gmv, ghb, ghbn2, i, gt2);
        hgc_agg_k<<<dim3(NNODE, 2), DIM>>>(ecols, evals, ecnt, gt2, gtout);
    }
    hgc_post_k<<<dim3(NNODE, 2), DIM>>>(ent0, ent1, gtout, grel,
                                        out + 2L * NNODE * 2 * DIM);
}

// round 6
// speedup vs baseline: 1.9482x; 1.0144x over previous
#include <cuda_runtime.h>
#include <math.h>

#define NNODE 6000
#define DIM   128
#define RREL  1000
#define NHEAD 2
#define LSEQ  3
#define KMAX  128
#define MAXNF 0.996f

// ---------------- scratch pool ----------------
#define O_ECOLS 0L                            // int [2][NNODE][KMAX]
#define O_EVALS (O_ECOLS + 1536000L)
#define O_ECNT  (O_EVALS + 1536000L)          // int [2][NNODE]
#define O_REL   (O_ECNT + 12032L)             // float[2][NNODE][DIM]
#define O_SEQ   (O_REL + 1536000L)            // float[2][NNODE][LSEQ][DIM]
#define O_HF    (O_SEQ + 4608000L)            // float[2][NHEAD][NNODE][DIM]
#define O_ES    (O_HF + 3072000L)             // float[2*NHEAD*NNODE]
#define O_ED    (O_ES + 24064L)
#define O_Y     (O_ED + 24064L)               // float[2][36000][128]
#define O_Z     (O_Y + 9216000L)              // float[36000][256]
#define O_OP    (O_Z + 9216000L)              // float[36000][128]
#define O_MV    (O_OP + 4608000L)             // float[2][NNODE][DIM]
#define O_T2    (O_MV + 1536000L)
#define O_TOUT  (O_T2 + 1536000L)
#define O_WT    (O_TOUT + 1536000L)           // float[2*DIM*DIM]
#define O_HB    (O_WT + 32768L)
#define O_HBN2  (O_HB + 256L)
#define O_A     (O_HBN2 + 32L)                // float[2][128][128]
#define O_G     (O_A + 32768L)                // float[256][128]
#define TOTALF  (O_G + 32768L)

__device__ __align__(256) float g_buf[TOTALF];

// ---------------- block reduction helpers (blockDim == 128) ----------------
__device__ __forceinline__ float bsum(float v, float* sh) {
#pragma unroll
    for (int o = 16; o; o >>= 1) v += __shfl_xor_sync(0xffffffffu, v, o);
    int w = threadIdx.x >> 5;
    if ((threadIdx.x & 31) == 0) sh[w] = v;
    __syncthreads();
    float r = sh[0] + sh[1] + sh[2] + sh[3];
    __syncthreads();
    return r;
}

__device__ __forceinline__ void bsum2(float a, float b, float* sh, float* ra, float* rb) {
#pragma unroll
    for (int o = 16; o; o >>= 1) {
        a += __shfl_xor_sync(0xffffffffu, a, o);
        b += __shfl_xor_sync(0xffffffffu, b, o);
    }
    int w = threadIdx.x >> 5;
    if ((threadIdx.x & 31) == 0) { sh[w] = a; sh[4 + w] = b; }
    __syncthreads();
    *ra = sh[0] + sh[1] + sh[2] + sh[3];
    *rb = sh[4] + sh[5] + sh[6] + sh[7];
    __syncthreads();
}

// ---------------- ELL build (batched over 2 graphs) ------------------------
__global__ void build_ell_k(const float* __restrict__ adj0, const float* __restrict__ adj1,
                            int* __restrict__ cols, float* __restrict__ vals,
                            int* __restrict__ cnt) {
    int b = blockIdx.y;
    const float* adj = b ? adj1 : adj0;
    long off = (long)b * NNODE;
    int row = blockIdx.x * 8 + (threadIdx.x >> 5);
    int lane = threadIdx.x & 31;
    const float* arow = adj + (long)row * NNODE;
    int c = 0;
    for (int base = 0; base < NNODE; base += 128) {
        int col = base + lane * 4;
        float4 v = make_float4(0.f, 0.f, 0.f, 0.f);
        if (col < NNODE) v = *reinterpret_cast<const float4*>(arow + col);
        float vv[4] = {v.x, v.y, v.z, v.w};
        int lc = (vv[0] != 0.f) + (vv[1] != 0.f) + (vv[2] != 0.f) + (vv[3] != 0.f);
        int pre = lc;
#pragma unroll
        for (int o = 1; o < 32; o <<= 1) {
            int t = __shfl_up_sync(0xffffffffu, pre, o);
            if (lane >= o) pre += t;
        }
        int tot = __shfl_sync(0xffffffffu, pre, 31);
        int p = c + pre - lc;
#pragma unroll
        for (int i = 0; i < 4; i++)
            if (vv[i] != 0.f && p < KMAX) {
                cols[(off + row) * KMAX + p] = col + i;
                vals[(off + row) * KMAX + p] = vv[i];
                p++;
            }
        c += tot;
    }
    if (!lane) cnt[off + row] = (c < KMAX) ? c : KMAX;
}

// ---------------- relation aggregation (batched) ---------------------------
__global__ void rel_agg_k(const float* __restrict__ radj0, const float* __restrict__ radj1,
                          const float* __restrict__ rel0, const float* __restrict__ rel1,
                          float* __restrict__ out) {
    __shared__ int sidx[256];
    __shared__ int wsum[4];
    int b = blockIdx.y;
    const float* radj = b ? radj1 : radj0;
    const float* rel = b ? rel1 : rel0;
    int row = blockIdx.x, t = threadIdx.x, lane = t & 31, w = t >> 5;
    int base = t * 8;
    float e[8];
#pragma unroll
    for (int i = 0; i < 8; i++) e[i] = 0.f;
    if (base < RREL) {
        float4 v0 = *reinterpret_cast<const float4*>(radj + (long)row * RREL + base);
        float4 v1 = *reinterpret_cast<const float4*>(radj + (long)row * RREL + base + 4);
        e[0] = v0.x; e[1] = v0.y; e[2] = v0.z; e[3] = v0.w;
        e[4] = v1.x; e[5] = v1.y; e[6] = v1.z; e[7] = v1.w;
    }
    int lc = 0;
#pragma unroll
    for (int i = 0; i < 8; i++) lc += (e[i] != 0.f);
    int pre = lc;
#pragma unroll
    for (int o = 1; o < 32; o <<= 1) {
        int s = __shfl_up_sync(0xffffffffu, pre, o);
        if (lane >= o) pre += s;
    }
    if (lane == 31) wsum[w] = pre;
    __syncthreads();
    int boff = 0;
    for (int k = 0; k < w; k++) boff += wsum[k];
    int total = wsum[0] + wsum[1] + wsum[2] + wsum[3];
    int p = boff + pre - lc;
#pragma unroll
    for (int i = 0; i < 8; i++)
        if (e[i] != 0.f && p < 256) sidx[p++] = base + i;
    __syncthreads();
    float acc = 0.f;
    for (int j = 0; j < total; j++) acc += rel[(long)sidx[j] * DIM + t];
    out[((long)b * NNODE + row) * DIM + t] = acc / (float)total;
}

// ---------------- tf32 tensor-core GEMM, 128x128x16 tiles ------------------
__device__ __forceinline__ unsigned cvt_tf32(float f) {
    unsigned r;
    asm("cvt.rna.tf32.f32 %0, %1;" : "=r"(r) : "f"(f));
    return r;
}

__device__ __forceinline__ void mma_tf32(float c[4], const unsigned a[4], const unsigned b[2]) {
    asm volatile(
        "mma.sync.aligned.m16n8k8.row.col.f32.tf32.tf32.f32 "
        "{%0,%1,%2,%3}, {%4,%5,%6,%7}, {%8,%9}, {%0,%1,%2,%3};"
        : "+f"(c[0]), "+f"(c[1]), "+f"(c[2]), "+f"(c[3])
        : "r"(a[0]), "r"(a[1]), "r"(a[2]), "r"(a[3]), "r"(b[0]), "r"(b[1]));
}

// Requires Ncols%128==0, K%16==0. M bounds-checked.
// Offsets: A += (z/divA)*sA; B += (z%modB)*sB; C += z*sC.
__global__ __launch_bounds__(256) void gemm_tc_k(
    const float* __restrict__ A, const float* __restrict__ B, float* __restrict__ C,
    int M, int Ncols, int K, int lda, int ldb, int ldc,
    long sA, int divA, long sB, int modB, long sC) {
    int z = blockIdx.z;
    A += (long)(z / divA) * sA;
    B += (long)(z % modB) * sB;
    C += (long)z * sC;
    __shared__ unsigned As[16][136];
    __shared__ unsigned Bs[16][136];
    int tid = threadIdx.x;
    int warp = tid >> 5, lane = tid & 31;
    int gid = lane >> 2, tig = lane & 3;
    int wr = (warp & 3) * 32;
    int wc = (warp >> 2) * 64;
    int brow = blockIdx.y * 128, bcol = blockIdx.x * 128;

    int am = tid & 127;
    int akg = tid >> 7;
    int bn4 = (tid & 31) * 4;
    int bkr = tid >> 5;

    float4 aR0, aR1, bR0, bR1;

    {
        int gr = brow + am;
        if (gr < M) {
            const float* p = A + (long)gr * lda + akg * 8;
            aR0 = *reinterpret_cast<const float4*>(p);
            aR1 = *reinterpret_cast<const float4*>(p + 4);
        } else {
            aR0 = aR1 = make_float4(0.f, 0.f, 0.f, 0.f);
        }
        const float* q = B + (long)bkr * ldb + bcol + bn4;
        bR0 = *reinterpret_cast<const float4*>(q);
        bR1 = *reinterpret_cast<const float4*>(q + 8L * ldb);
    }

    float acc[2][8][4] = {};

    for (int k0 = 0; k0 < K; k0 += 16) {
        As[akg * 8 + 0][am] = cvt_tf32(aR0.x);
        As[akg * 8 + 1][am] = cvt_tf32(aR0.y);
        As[akg * 8 + 2][am] = cvt_tf32(aR0.z);
        As[akg * 8 + 3][am] = cvt_tf32(aR0.w);
        As[akg * 8 + 4][am] = cvt_tf32(aR1.x);
        As[akg * 8 + 5][am] = cvt_tf32(aR1.y);
        As[akg * 8 + 6][am] = cvt_tf32(aR1.z);
        As[akg * 8 + 7][am] = cvt_tf32(aR1.w);
        uint4 bb0 = make_uint4(cvt_tf32(bR0.x), cvt_tf32(bR0.y), cvt_tf32(bR0.z), cvt_tf32(bR0.w));
        uint4 bb1 = make_uint4(cvt_tf32(bR1.x), cvt_tf32(bR1.y), cvt_tf32(bR1.z), cvt_tf32(bR1.w));
        *reinterpret_cast<uint4*>(&Bs[bkr][bn4]) = bb0;
        *reinterpret_cast<uint4*>(&Bs[bkr + 8][bn4]) = bb1;
        __syncthreads();

        if (k0 + 16 < K) {
            int gr = brow + am;
            if (gr < M) {
                const float* p = A + (long)gr * lda + k0 + 16 + akg * 8;
                aR0 = *reinterpret_cast<const float4*>(p);
                aR1 = *reinterpret_cast<const float4*>(p + 4);
            }
            const float* q = B + (long)(k0 + 16 + bkr) * ldb + bcol + bn4;
            bR0 = *reinterpret_cast<const float4*>(q);
            bR1 = *reinterpret_cast<const float4*>(q + 8L * ldb);
        }

#pragma unroll
        for (int kk = 0; kk < 16; kk += 8) {
            unsigned af[2][4];
#pragma unroll
            for (int mi = 0; mi < 2; mi++) {
                int m = wr + mi * 16;
                af[mi][0] = As[kk + tig][m + gid];
                af[mi][1] = As[kk + tig][m + gid + 8];
                af[mi][2] = As[kk + tig + 4][m + gid];
                af[mi][3] = As[kk + tig + 4][m + gid + 8];
            }
            unsigned bf[8][2];
#pragma unroll
            for (int ni = 0; ni < 8; ni++) {
                int n = wc + ni * 8;
                bf[ni][0] = Bs[kk + tig][n + gid];
                bf[ni][1] = Bs[kk + tig + 4][n + gid];
            }
#pragma unroll
            for (int mi = 0; mi < 2; mi++)
#pragma unroll
                for (int ni = 0; ni < 8; ni++) mma_tf32(acc[mi][ni], af[mi], bf[ni]);
        }
        __syncthreads();
    }

#pragma unroll
    for (int mi = 0; mi < 2; mi++) {
        int r0 = brow + wr + mi * 16 + gid;
#pragma unroll
        for (int ni = 0; ni < 8; ni++) {
            int c0 = bcol + wc + ni * 8 + tig * 2;
            if (r0 < M)
                *reinterpret_cast<float2*>(C + (long)r0 * ldc + c0) =
                    make_float2(acc[mi][ni][0], acc[mi][ni][1]);
            if (r0 + 8 < M)
                *reinterpret_cast<float2*>(C + (long)(r0 + 8) * ldc + c0) =
                    make_float2(acc[mi][ni][2], acc[mi][ni][3]);
        }
    }
}

// ---------------- MHA weight folding v2: smem-tiled ----------------
// grid (8, 4): blockIdx.y = mat (0,1: A_h = Wq_h Wk_h^T / sqrt(D); 2,3: G_h = Wv_h Wfc_h)
// block 256 threads; 16x128 output tile, K=128 staged in 32-chunks.
__global__ __launch_bounds__(256) void prep_mha_k(
    const float* __restrict__ Wq, const float* __restrict__ Wk,
    const float* __restrict__ Wv, const float* __restrict__ Wfc,
    float* __restrict__ Am, float* __restrict__ G) {
    __shared__ float sA[16][33];
    __shared__ float sB[32][129];
    int mat = blockIdx.y;
    int h = mat & 1;
    int row0 = blockIdx.x * 16;
    int tid = threadIdx.x;
    int r = tid >> 4;        // 0..15
    int cb = tid & 15;       // col base; thread covers cols cb + 16*i
    float acc[8] = {};
    const float* Asrc = (mat < 2) ? Wq : Wv;

    for (int k0 = 0; k0 < 128; k0 += 32) {
        for (int i = tid; i < 16 * 32; i += 256) {
            int rr = i >> 5, jj = i & 31;
            sA[rr][jj] = Asrc[(row0 + rr) * 256 + h * 128 + k0 + jj];
        }
        if (mat < 2) {
            for (int i = tid; i < 32 * 128; i += 256) {
                int t = i >> 5, jj = i & 31;
                sB[jj][t] = Wk[t * 256 + h * 128 + k0 + jj];
            }
        } else {
            for (int i = tid; i < 32 * 128; i += 256) {
                int jj = i >> 7, t = i & 127;
                sB[jj][t] = Wfc[(h * 128 + k0 + jj) * 128 + t];
            }
        }
        __syncthreads();
#pragma unroll
        for (int j = 0; j < 32; j++) {
            float a = sA[r][j];
#pragma unroll
            for (int i = 0; i < 8; i++) acc[i] += a * sB[j][cb + 16 * i];
        }
        __syncthreads();
    }
    float scale = (mat < 2) ? 0.08838834764831845f : 1.f;
    float* dst = ((mat < 2) ? Am : G) + (long)(h * 128 + row0 + r) * 128;
#pragma unroll
    for (int i = 0; i < 8; i++) dst[cb + 16 * i] = acc[i] * scale;
}

// ---------------- hgcW transpose + hyperbolic bias (merged) ----------------
__global__ void setup_w_k(const float* __restrict__ hgcW, const float* __restrict__ hgcb,
                          float* __restrict__ WT, float* __restrict__ hb,
                          float* __restrict__ hbn2) {
    __shared__ float sh[8];
    int i = blockIdx.x, d = threadIdx.x;
    if (blockIdx.y < 128) {
        int e = blockIdx.y;
        WT[(long)i * 16384 + (long)d * 128 + e] = hgcW[(long)i * 16384 + (long)e * 128 + d];
    } else {
        float v = hgcb[i * DIM + d];
        float ss = bsum(v * v, sh);
        float nn = fmaxf(sqrtf(ss), 1e-15f);
        float t = tanhf(nn);
        float a = t / nn;
        if (t > MAXNF) a *= MAXNF / t;
        float h = a * v;
        hb[i * DIM + d] = h;
        float s2 = bsum(h * h, sh);
        if (!d) hbn2[i] = s2;
    }
}

// ---------------- init: seq slot0 copy + hyperbolic prologue (merged) ------
__global__ void init_node_k(const float* __restrict__ e0, const float* __restrict__ e1,
                            float* __restrict__ seq, float* __restrict__ tout) {
    __shared__ float sh[8];
    int n = blockIdx.x, b = blockIdx.y, d = threadIdx.x;
    const float* x = b ? e1 : e0;
    float v = x[(long)n * DIM + d];
    long r = (long)b * NNODE + n;
    seq[r * LSEQ * DIM + d] = v;
    float ss = bsum(v * v, sh);
    float nn = fmaxf(sqrtf(ss), 1e-15f);
    float t = tanhf(nn);
    float a = t / nn;
    if (t > MAXNF) a = MAXNF / nn;
    float np = fmaxf(a * nn, 1e-15f);
    float s = atanhf(fminf(np, 1.0f - 1e-7f)) / np;
    tout[r * DIM + d] = s * a * v;
}

// ---------------- GAT: es/ed dot products (batched) ----------------
__global__ void esd_k(const float* __restrict__ hf, const float* __restrict__ as,
                      const float* __restrict__ ad, float* __restrict__ es,
                      float* __restrict__ ed) {
    int n = blockIdx.x, b = blockIdx.y;
    int h = threadIdx.x >> 5, lane = threadIdx.x & 31;
    const float* r = hf + ((long)(b * NHEAD + h) * NNODE + n) * DIM;
    float s = 0.f, t = 0.f;
#pragma unroll
    for (int d = lane; d < DIM; d += 32) {
        float v = r[d];
        s += v * as[h * DIM + d];
        t += v * ad[h * DIM + d];
    }
#pragma unroll
    for (int o = 16; o; o >>= 1) {
        s += __shfl_xor_sync(0xffffffffu, s, o);
        t += __shfl_xor_sync(0xffffffffu, t, o);
    }
    if (!lane) {
        es[(long)(b * NHEAD + h) * NNODE + n] = s;
        ed[(long)(b * NHEAD + h) * NNODE + n] = t;
    }
}

// ---------------- GAT aggregate + elu + normalize (batched) ----------------
__global__ void gat_agg_k(const int* __restrict__ cols, const int* __restrict__ cnt,
                          const float* __restrict__ hf, const float* __restrict__ es,
                          const float* __restrict__ ed, float* __restrict__ seq, int slot) {
    __shared__ int sc[KMAX];
    __shared__ float sw[NHEAD][KMAX];
    __shared__ float sh[8];
    int n = blockIdx.x, b = blockIdx.y, tid = threadIdx.x;
    long goff = (long)b * NNODE;
    int c = cnt[goff + n];
    for (int j = tid; j < c; j += DIM) sc[j] = cols[(goff + n) * KMAX + j];
    __syncthreads();
    int w = tid >> 5, lane = tid & 31;
    if (w < NHEAD) {
        const float* edp = ed + (long)(b * NHEAD + w) * NNODE;
        float e0 = es[(long)(b * NHEAD + w) * NNODE + n];
        float m = -1e30f;
        for (int j = lane; j < c; j += 32) {
            float e = e0 + edp[sc[j]];
            e = e > 0.f ? e : 0.2f * e;
            sw[w][j] = e;
            m = fmaxf(m, e);
        }
#pragma unroll
        for (int o = 16; o; o >>= 1) m = fmaxf(m, __shfl_xor_sync(0xffffffffu, m, o));
        float s = 0.f;
        for (int j = lane; j < c; j += 32) {
            float e = expf(sw[w][j] - m);
            sw[w][j] = e;
            s += e;
        }
#pragma unroll
        for (int o = 16; o; o >>= 1) s += __shfl_xor_sync(0xffffffffu, s, o);
        float inv = 1.f / s;
        for (int j = lane; j < c; j += 32) sw[w][j] *= inv;
    }
    __syncthreads();
    const float* hf0 = hf + (long)(b * NHEAD) * NNODE * DIM;
    const float* hf1 = hf0 + (long)NNODE * DIM;
    float a0 = 0.f, a1 = 0.f;
    for (int j = 0; j < c; j++) {
        long cc = sc[j];
        a0 += sw[0][j] * hf0[cc * DIM + tid];
        a1 += sw[1][j] * hf1[cc * DIM + tid];
    }
    float v = 0.5f * (a0 + a1);
    v = v > 0.f ? v : expm1f(v);
    float ss = bsum(v * v, sh);
    float nrm = fmaxf(sqrtf(ss), 1e-12f);
    seq[((goff + n) * LSEQ + slot) * DIM + tid] = v / nrm;
}

// ---------------- attention: e = y.x dots, softmax, z = attn @ x -----------
__global__ void attn_z_k(const float* __restrict__ seq, const float* __restrict__ y,
                         float* __restrict__ z) {
    __shared__ float sx[LSEQ][DIM];
    __shared__ float sy[NHEAD][LSEQ][DIM];
    __shared__ float se[NHEAD][LSEQ][LSEQ];
    int r = blockIdx.x, tid = threadIdx.x, w = tid >> 5, lane = tid & 31;
    long r3 = (long)r * LSEQ;
    for (int i = tid; i < LSEQ * DIM; i += 128) sx[i >> 7][i & 127] = seq[r3 * DIM + i];
    for (int i = tid; i < NHEAD * LSEQ * DIM; i += 128) {
        int h = i / (LSEQ * DIM), rem = i % (LSEQ * DIM);
        sy[h][rem >> 7][rem & 127] = y[(long)h * 4608000L + r3 * DIM + rem];
    }
    __syncthreads();
    for (int idx = w; idx < NHEAD * LSEQ * LSEQ; idx += 4) {
        int h = idx / 9, rem = idx % 9, l = rem / 3, m = rem % 3;
        float s = 0.f;
#pragma unroll
        for (int d = lane; d < DIM; d += 32) s += sy[h][l][d] * sx[m][d];
#pragma unroll
        for (int o = 16; o; o >>= 1) s += __shfl_xor_sync(0xffffffffu, s, o);
        if (!lane) se[h][l][m] = s;
    }
    __syncthreads();
    if (tid < NHEAD * LSEQ) {
        int h = tid / 3, l = tid % 3;
        float m = fmaxf(se[h][l][0], fmaxf(se[h][l][1], se[h][l][2]));
        float e0 = expf(se[h][l][0] - m), e1 = expf(se[h][l][1] - m), e2 = expf(se[h][l][2] - m);
        float inv = 1.f / (e0 + e1 + e2);
        se[h][l][0] = e0 * inv;
        se[h][l][1] = e1 * inv;
        se[h][l][2] = e2 * inv;
    }
    __syncthreads();
    int d = tid;
    for (int l = 0; l < LSEQ; l++)
#pragma unroll
        for (int h = 0; h < NHEAD; h++) {
            float a = se[h][l][0] * sx[0][d] + se[h][l][1] * sx[1][d] + se[h][l][2] * sx[2][d];
            z[(r3 + l) * 256 + h * DIM + d] = a;
        }
}

// ---------------- MHA epilogue (batched) ----------------
__global__ void mha_epi_k(const float* __restrict__ op, const float* __restrict__ seq,
                          const float* __restrict__ relb, const float* __restrict__ lng,
                          const float* __restrict__ lnb, float* __restrict__ out) {
    __shared__ float sh[8];
    int n = blockIdx.x, b = blockIdx.y, d = threadIdx.x;
    long r = (long)b * NNODE + n;
    float acc = 0.f;
    for (int l = 0; l < LSEQ; l++) {
        long idx = (r * LSEQ + l) * DIM + d;
        float v = op[idx] + seq[idx];
        float mu = bsum(v, sh) * (1.f / DIM);
        float dv = v - mu;
        float var = bsum(dv * dv, sh) * (1.f / DIM);
        acc += lng[d] * dv * rsqrtf(var + 1e-6f) + lnb[d];
    }
    float* row = out + (long)b * NNODE * 2 * DIM + (long)n * 2 * DIM;
    row[d] = acc * (1.f / 3.f);
    row[DIM + d] = relb[r * DIM + d];
}

// expmap0+proj, mobius_add(.,hb), proj, logmap0 (batched)
__global__ void hgc_mid_k(const float* __restrict__ mv, const float* __restrict__ hb,
                          const float* __restrict__ hbn2, int layer, float* __restrict__ t2) {
    __shared__ float sh[8];
    int n = blockIdx.x, b = blockIdx.y, d = threadIdx.x;
    long r = (long)b * NNODE + n;
    float x0 = mv[r * DIM + d];
    float hbv = hb[layer * DIM + d];
    float y2 = hbn2[layer];
    float ss = bsum(x0 * x0, sh);
    float nn = fmaxf(sqrtf(ss), 1e-15f);
    float t = tanhf(nn);
    float a = t / nn;
    if (t > MAXNF) a *= MAXNF / t;
    float xd = a * x0;
    float x2, xy;
    bsum2(xd * xd, xd * hbv, sh, &x2, &xy);
    float num = (1.f + 2.f * xy + y2) * xd + (1.f - x2) * hbv;
    float den = fmaxf(1.f + 2.f * xy + x2 * y2, 1e-15f);
    float h2 = num / den;
    float ss2 = bsum(h2 * h2, sh);
    float nh = fmaxf(sqrtf(ss2), 1e-15f);
    float c = 1.f, npn = nh;
    if (nh > MAXNF) { c = MAXNF / nh; npn = MAXNF; }
    float p = fmaxf(npn, 1e-15f);
    float s = atanhf(fminf(p, 1.0f - 1e-7f)) / p;
    t2[r * DIM + d] = s * c * h2;
}

// sparse agg + expmap0/proj + relu(logmap0) + expmap0/proj + logmap0 fused.
// last != 0: write final output rows (ent + t, relb concat) instead of tout.
__global__ void hgc_agg_k(const int* __restrict__ cols, const float* __restrict__ vals,
                          const int* __restrict__ cnt, const float* __restrict__ tin,
                          float* __restrict__ tout, int last,
                          const float* __restrict__ e0, const float* __restrict__ e1,
                          const float* __restrict__ relb, float* __restrict__ out) {
    __shared__ int sc[KMAX];
    __shared__ float svv[KMAX];
    __shared__ float sh[8];
    int n = blockIdx.x, b = blockIdx.y, d = threadIdx.x;
    long goff = (long)b * NNODE;
    int c = cnt[goff + n];
    for (int j = d; j < c; j += DIM) {
        sc[j] = cols[(goff + n) * KMAX + j];
        svv[j] = vals[(goff + n) * KMAX + j];
    }
    __syncthreads();
    const float* tb = tin + goff * DIM;
    float acc = 0.f;
    for (int j = 0; j < c; j++) acc += svv[j] * tb[(long)sc[j] * DIM + d];
    float ss = bsum(acc * acc, sh);
    float nn = fmaxf(sqrtf(ss), 1e-15f);
    float t = tanhf(nn);
    float a = t / nn;
    if (t > MAXNF) a *= MAXNF / t;
    float pd = a * acc;
    float rp = fmaxf(pd, 0.f);
    float p2, r2;
    bsum2(pd * pd, rp * rp, sh, &p2, &r2);
    float npn = fmaxf(sqrtf(p2), 1e-15f);
    float beta = atanhf(fminf(npn, 1.0f - 1e-7f)) / npn;
    float t3 = beta * rp;
    float n3 = fmaxf(beta * sqrtf(r2), 1e-15f);
    float tt = tanhf(n3);
    float aa = tt / n3;
    if (tt > MAXNF) aa *= MAXNF / tt;
    float nh = fmaxf(aa * n3, 1e-15f);
    float s2 = atanhf(fminf(nh, 1.0f - 1e-7f)) / nh;
    float tv = s2 * aa * t3;
    if (!last) {
        tout[(goff + n) * DIM + d] = tv;
    } else {
        const float* x = b ? e1 : e0;
        float* row = out + (long)b * NNODE * 2 * DIM + (long)n * 2 * DIM;
        row[d] = x[(long)n * DIM + d] + tv;
        row[DIM + d] = relb[(goff + n) * DIM + d];
    }
}

// ---------------- host ----------------
extern "C" void kernel_launch(void* const* d_in, const int* in_sizes, int n_in,
                              void* d_out, int out_size) {
    (void)in_sizes; (void)n_in; (void)out_size;
    const float* ent0 = (const float*)d_in[0];
    const float* ent1 = (const float*)d_in[1];
    const float* rel0 = (const float*)d_in[2];
    const float* rel1 = (const float*)d_in[3];
    const float* adj0 = (const float*)d_in[4];
    const float* adj1 = (const float*)d_in[5];
    const float* radj0 = (const float*)d_in[6];
    const float* radj1 = (const float*)d_in[7];
    const float* gatW = (const float*)d_in[8];
    const float* aS = (const float*)d_in[9];
    const float* aD = (const float*)d_in[10];
    const float* Wq = (const float*)d_in[11];
    const float* Wk = (const float*)d_in[12];
    const float* Wv = (const float*)d_in[13];
    const float* Wfc = (const float*)d_in[14];
    const float* lng = (const float*)d_in[15];
    const float* lnb = (const float*)d_in[16];
    const float* hgcW = (const float*)d_in[17];
    const float* hgcb = (const float*)d_in[18];
    float* out = (float*)d_out;

    float* base = nullptr;
    cudaGetSymbolAddress((void**)&base, g_buf);

    int* ecols = (int*)(base + O_ECOLS);
    float* evals = base + O_EVALS;
    int* ecnt = (int*)(base + O_ECNT);
    float* grel = base + O_REL;
    float* gseq = base + O_SEQ;
    float* ghf = base + O_HF;
    float* ges = base + O_ES;
    float* ged = base + O_ED;
    float* gy = base + O_Y;
    float* gz = base + O_Z;
    float* gop = base + O_OP;
    float* gmv = base + O_MV;
    float* gt2 = base + O_T2;
    float* gtout = base + O_TOUT;
    float* gwt = base + O_WT;
    float* ghb = base + O_HB;
    float* ghbn2 = base + O_HBN2;
    float* gA = base + O_A;
    float* gG = base + O_G;

    const long BSEQ = (long)NNODE * LSEQ * DIM;
    const long BND = (long)NNODE * DIM;

    // ---- preprocessing ----
    build_ell_k<<<dim3(NNODE / 8, 2), 256>>>(adj0, adj1, ecols, evals, ecnt);
    rel_agg_k<<<dim3(NNODE, 2), 128>>>(radj0, radj1, rel0, rel1, grel);
    setup_w_k<<<dim3(2, 129), DIM>>>(hgcW, hgcb, gwt, ghb, ghbn2);
    prep_mha_k<<<dim3(8, 4), 256>>>(Wq, Wk, Wv, Wfc, gA, gG);
    init_node_k<<<dim3(NNODE, 2), DIM>>>(ent0, ent1, gseq, gtout);

    // ---- GAT x2 layers, both branches + both heads batched (z=4) ----
    for (int layer = 0; layer < 2; layer++) {
        gemm_tc_k<<<dim3(1, 47, 4), 256>>>(
            gseq + (long)layer * DIM, gatW + (long)layer * NHEAD * DIM * DIM, ghf,
            NNODE, DIM, DIM, LSEQ * DIM, DIM, DIM,
            BSEQ, NHEAD, (long)DIM * DIM, NHEAD, BND);
        esd_k<<<dim3(NNODE, 2), 64>>>(ghf, aS + layer * NHEAD * DIM, aD + layer * NHEAD * DIM,
                                      ges, ged);
        gat_agg_k<<<dim3(NNODE, 2), DIM>>>(ecols, ecnt, ghf, ges, ged, gseq, layer + 1);
    }

    // ---- MHA via folded weights ----
    gemm_tc_k<<<dim3(1, 282, 2), 256>>>(gseq, gA, gy, 2 * NNODE * LSEQ, DIM, DIM,
                                        DIM, DIM, DIM, 0, 1, (long)DIM * DIM, 2,
                                        (long)2 * NNODE * LSEQ * DIM);
    attn_z_k<<<2 * NNODE, 128>>>(gseq, gy, gz);
    gemm_tc_k<<<dim3(1, 282, 1), 256>>>(gz, gG, gop, 2 * NNODE * LSEQ, DIM, 2 * DIM,
                                        2 * DIM, DIM, DIM, 0, 1, 0, 1, 0);
    mha_epi_k<<<dim3(NNODE, 2), DIM>>>(gop, gseq, grel, lng, lnb, out);

    // ---- hyperbolic encoder (z=2 batched) ----
    for (int i = 0; i < 2; i++) {
        gemm_tc_k<<<dim3(1, 47, 2), 256>>>(gtout, gwt + (long)i * DIM * DIM, gmv,
                                           NNODE, DIM, DIM, DIM, DIM, DIM,
                                           BND, 1, 0, 1, BND);
        hgc_mid_k<<<dim3(NNODE, 2), DIM>>>(gmv, ghb, ghbn2, i, gt2);
        hgc_agg_k<<<dim3(NNODE, 2), DIM>>>(ecols, evals, ecnt, gt2, gtout, i == 1,
                                           ent0, ent1, grel, out + 2L * NNODE * 2 * DIM);
    }
}

// round 8
// speedup vs baseline: 2.0436x; 1.0489x over previous
#include <cuda_runtime.h>
#include <math.h>

#define NNODE 6000
#define DIM   128
#define RREL  1000
#define NHEAD 2
#define LSEQ  3
#define KMAX  128
#define MAXNF 0.996f

// ---------------- scratch pool ----------------
#define O_ECOLS 0L                            // int [2][NNODE][KMAX]
#define O_EVALS (O_ECOLS + 1536000L)
#define O_ECNT  (O_EVALS + 1536000L)          // int [2][NNODE]
#define O_REL   (O_ECNT + 12032L)             // float[2][NNODE][DIM]
#define O_SEQ   (O_REL + 1536000L)            // float[2][NNODE][LSEQ][DIM]
#define O_HF    (O_SEQ + 4608000L)            // float[2][NHEAD][NNODE][DIM]
#define O_ES    (O_HF + 3072000L)             // float[2*NHEAD*NNODE]
#define O_ED    (O_ES + 24064L)
#define O_Y     (O_ED + 24064L)               // float[2][36000][128]
#define O_Z     (O_Y + 9216000L)              // float[36000][256]
#define O_OP    (O_Z + 9216000L)              // float[36000][128]
#define O_MV    (O_OP + 4608000L)             // float[2][NNODE][DIM]
#define O_T2    (O_MV + 1536000L)
#define O_TOUT  (O_T2 + 1536000L)
#define O_WT    (O_TOUT + 1536000L)           // float[2*DIM*DIM]
#define O_HB    (O_WT + 32768L)
#define O_HBN2  (O_HB + 256L)
#define O_A     (O_HBN2 + 32L)                // float[2][128][128]
#define O_G     (O_A + 32768L)                // float[256][128]
#define TOTALF  (O_G + 32768L)

__device__ __align__(256) float g_buf[TOTALF];

// ---------------- block reduction helpers (128 active threads) -------------
__device__ __forceinline__ float bsum(float v, float* sh) {
#pragma unroll
    for (int o = 16; o; o >>= 1) v += __shfl_xor_sync(0xffffffffu, v, o);
    int w = threadIdx.x >> 5;
    if ((threadIdx.x & 31) == 0) sh[w] = v;
    __syncthreads();
    float r = sh[0] + sh[1] + sh[2] + sh[3];
    __syncthreads();
    return r;
}

__device__ __forceinline__ void bsum2(float a, float b, float* sh, float* ra, float* rb) {
#pragma unroll
    for (int o = 16; o; o >>= 1) {
        a += __shfl_xor_sync(0xffffffffu, a, o);
        b += __shfl_xor_sync(0xffffffffu, b, o);
    }
    int w = threadIdx.x >> 5;
    if ((threadIdx.x & 31) == 0) { sh[w] = a; sh[4 + w] = b; }
    __syncthreads();
    *ra = sh[0] + sh[1] + sh[2] + sh[3];
    *rb = sh[4] + sh[5] + sh[6] + sh[7];
    __syncthreads();
}

// ---------------- mega setup kernel: all independent preprocessing ---------
// block ranges: [0,32) prep_mha | [32,290) setup_w | [290,1790) build_ell
//               [1790,13790) rel_agg | [13790,25790) init_node
#define NB_PREP 32
#define NB_SETW 258
#define NB_ELL  1500
#define NB_REL  12000
#define NB_INIT 12000
#define NB_TOTAL (NB_PREP + NB_SETW + NB_ELL + NB_REL + NB_INIT)

__global__ __launch_bounds__(256) void setup_all_k(
    const float* __restrict__ adj0, const float* __restrict__ adj1,
    const float* __restrict__ radj0, const float* __restrict__ radj1,
    const float* __restrict__ rel0, const float* __restrict__ rel1,
    const float* __restrict__ hgcW, const float* __restrict__ hgcb,
    const float* __restrict__ Wq, const float* __restrict__ Wk,
    const float* __restrict__ Wv, const float* __restrict__ Wfc,
    const float* __restrict__ e0, const float* __restrict__ e1,
    int* __restrict__ ecols, float* __restrict__ evals, int* __restrict__ ecnt,
    float* __restrict__ grel, float* __restrict__ WT, float* __restrict__ hb,
    float* __restrict__ hbn2, float* __restrict__ Am, float* __restrict__ G,
    float* __restrict__ seq, float* __restrict__ tout) {
    __shared__ __align__(16) char smraw[18688];
    int bid = blockIdx.x;
    int tid = threadIdx.x;

    if (bid < NB_PREP) {
        // ---- MHA weight folding: 16x128 tile, K staged in 32-chunks ----
        float (*sA)[33] = reinterpret_cast<float(*)[33]>(smraw);
        float (*sB)[129] = reinterpret_cast<float(*)[129]>(smraw + 2112);
        int mat = bid >> 3;
        int h = mat & 1;
        int row0 = (bid & 7) * 16;
        int r = tid >> 4;
        int cb = tid & 15;
        float acc[8] = {};
        const float* Asrc = (mat < 2) ? Wq : Wv;
        for (int k0 = 0; k0 < 128; k0 += 32) {
            for (int i = tid; i < 16 * 32; i += 256) {
                int rr = i >> 5, jj = i & 31;
                sA[rr][jj] = Asrc[(row0 + rr) * 256 + h * 128 + k0 + jj];
            }
            if (mat < 2) {
                for (int i = tid; i < 32 * 128; i += 256) {
                    int t = i >> 5, jj = i & 31;
                    sB[jj][t] = Wk[t * 256 + h * 128 + k0 + jj];
                }
            } else {
                for (int i = tid; i < 32 * 128; i += 256) {
                    int jj = i >> 7, t = i & 127;
                    sB[jj][t] = Wfc[(h * 128 + k0 + jj) * 128 + t];
                }
            }
            __syncthreads();
#pragma unroll
            for (int j = 0; j < 32; j++) {
                float a = sA[r][j];
#pragma unroll
                for (int i = 0; i < 8; i++) acc[i] += a * sB[j][cb + 16 * i];
            }
            __syncthreads();
        }
        float scale = (mat < 2) ? 0.08838834764831845f : 1.f;
        float* dst = ((mat < 2) ? Am : G) + (long)(h * 128 + row0 + r) * 128;
#pragma unroll
        for (int i = 0; i < 8; i++) dst[cb + 16 * i] = acc[i] * scale;
        return;
    }
    bid -= NB_PREP;

    if (bid < NB_SETW) {
        // ---- hgcW transpose + hyperbolic bias ----
        if (tid >= 128) return;
        float* sh = (float*)smraw;
        int i = bid & 1, yy = bid >> 1, d = tid;
        if (yy < 128) {
            WT[(long)i * 16384 + (long)d * 128 + yy] = hgcW[(long)i * 16384 + (long)yy * 128 + d];
        } else {
            float v = hgcb[i * DIM + d];
            float ss = bsum(v * v, sh);
            float nn = fmaxf(sqrtf(ss), 1e-15f);
            float t = tanhf(nn);
            float a = t / nn;
            if (t > MAXNF) a *= MAXNF / t;
            float hv = a * v;
            hb[i * DIM + d] = hv;
            float s2 = bsum(hv * hv, sh);
            if (!d) hbn2[i] = s2;
        }
        return;
    }
    bid -= NB_SETW;

    if (bid < NB_ELL) {
        // ---- ELL adjacency build ----
        int b = bid / 750;
        const float* adj = b ? adj1 : adj0;
        long off = (long)b * NNODE;
        int row = (bid % 750) * 8 + (tid >> 5);
        int lane = tid & 31;
        const float* arow = adj + (long)row * NNODE;
        int c = 0;
        for (int base = 0; base < NNODE; base += 128) {
            int col = base + lane * 4;
            float4 v = make_float4(0.f, 0.f, 0.f, 0.f);
            if (col < NNODE) v = *reinterpret_cast<const float4*>(arow + col);
            float vv[4] = {v.x, v.y, v.z, v.w};
            int lc = (vv[0] != 0.f) + (vv[1] != 0.f) + (vv[2] != 0.f) + (vv[3] != 0.f);
            int pre = lc;
#pragma unroll
            for (int o = 1; o < 32; o <<= 1) {
                int t = __shfl_up_sync(0xffffffffu, pre, o);
                if (lane >= o) pre += t;
            }
            int tot = __shfl_sync(0xffffffffu, pre, 31);
            int p = c + pre - lc;
#pragma unroll
            for (int i = 0; i < 4; i++)
                if (vv[i] != 0.f && p < KMAX) {
                    ecols[(off + row) * KMAX + p] = col + i;
                    evals[(off + row) * KMAX + p] = vv[i];
                    p++;
                }
            c += tot;
        }
        if (!lane) ecnt[off + row] = (c < KMAX) ? c : KMAX;
        return;
    }
    bid -= NB_ELL;

    if (bid < NB_REL) {
        // ---- relation aggregation ----
        if (tid >= 128) return;
        int* sidx = (int*)smraw;
        int* wsum = (int*)(smraw + 1024);
        int b = bid / NNODE;
        const float* radj = b ? radj1 : radj0;
        const float* rel = b ? rel1 : rel0;
        int row = bid % NNODE, t = tid, lane = t & 31, w = t >> 5;
        int base = t * 8;
        float e[8];
#pragma unroll
        for (int i = 0; i < 8; i++) e[i] = 0.f;
        if (base < RREL) {
            float4 v0 = *reinterpret_cast<const float4*>(radj + (long)row * RREL + base);
            float4 v1 = *reinterpret_cast<const float4*>(radj + (long)row * RREL + base + 4);
            e[0] = v0.x; e[1] = v0.y; e[2] = v0.z; e[3] = v0.w;
            e[4] = v1.x; e[5] = v1.y; e[6] = v1.z; e[7] = v1.w;
        }
        int lc = 0;
#pragma unroll
        for (int i = 0; i < 8; i++) lc += (e[i] != 0.f);
        int pre = lc;
#pragma unroll
        for (int o = 1; o < 32; o <<= 1) {
            int s = __shfl_up_sync(0xffffffffu, pre, o);
            if (lane >= o) pre += s;
        }
        if (lane == 31) wsum[w] = pre;
        __syncthreads();
        int boff = 0;
        for (int k = 0; k < w; k++) boff += wsum[k];
        int total = wsum[0] + wsum[1] + wsum[2] + wsum[3];
        int p = boff + pre - lc;
#pragma unroll
        for (int i = 0; i < 8; i++)
            if (e[i] != 0.f && p < 256) sidx[p++] = base + i;
        __syncthreads();
        float acc = 0.f;
        for (int j = 0; j < total; j++) acc += rel[(long)sidx[j] * DIM + t];
        grel[((long)b * NNODE + row) * DIM + t] = acc / (float)total;
        return;
    }
    bid -= NB_REL;

    // ---- init: seq slot0 copy + hyperbolic prologue ----
    if (tid >= 128) return;
    {
        float* sh = (float*)smraw;
        int b = bid / NNODE;
        int n = bid % NNODE, d = tid;
        const float* x = b ? e1 : e0;
        float v = x[(long)n * DIM + d];
        long r = (long)b * NNODE + n;
        seq[r * LSEQ * DIM + d] = v;
        float ss = bsum(v * v, sh);
        float nn = fmaxf(sqrtf(ss), 1e-15f);
        float t = tanhf(nn);
        float a = t / nn;
        if (t > MAXNF) a = MAXNF / nn;
        float np = fmaxf(a * nn, 1e-15f);
        float s = atanhf(fminf(np, 1.0f - 1e-7f)) / np;
        tout[r * DIM + d] = s * a * v;
    }
}

// ---------------- tf32 tensor-core GEMM, 128x128x16 tiles ------------------
__device__ __forceinline__ unsigned cvt_tf32(float f) {
    unsigned r;
    asm("cvt.rna.tf32.f32 %0, %1;" : "=r"(r) : "f"(f));
    return r;
}

__device__ __forceinline__ void mma_tf32(float c[4], const unsigned a[4], const unsigned b[2]) {
    asm volatile(
        "mma.sync.aligned.m16n8k8.row.col.f32.tf32.tf32.f32 "
        "{%0,%1,%2,%3}, {%4,%5,%6,%7}, {%8,%9}, {%0,%1,%2,%3};"
        : "+f"(c[0]), "+f"(c[1]), "+f"(c[2]), "+f"(c[3])
        : "r"(a[0]), "r"(a[1]), "r"(a[2]), "r"(a[3]), "r"(b[0]), "r"(b[1]));
}

// Requires Ncols%128==0, K%16==0. M bounds-checked.
// Offsets: A += (z/divA)*sA; B += (z%modB)*sB; C += z*sC.
__global__ __launch_bounds__(256) void gemm_tc_k(
    const float* __restrict__ A, const float* __restrict__ B, float* __restrict__ C,
    int M, int Ncols, int K, int lda, int ldb, int ldc,
    long sA, int divA, long sB, int modB, long sC) {
    int z = blockIdx.z;
    A += (long)(z / divA) * sA;
    B += (long)(z % modB) * sB;
    C += (long)z * sC;
    __shared__ unsigned As[16][136];
    __shared__ unsigned Bs[16][136];
    int tid = threadIdx.x;
    int warp = tid >> 5, lane = tid & 31;
    int gid = lane >> 2, tig = lane & 3;
    int wr = (warp & 3) * 32;
    int wc = (warp >> 2) * 64;
    int brow = blockIdx.y * 128, bcol = blockIdx.x * 128;

    int am = tid & 127;
    int akg = tid >> 7;
    int bn4 = (tid & 31) * 4;
    int bkr = tid >> 5;

    float4 aR0, aR1, bR0, bR1;

    {
        int gr = brow + am;
        if (gr < M) {
            const float* p = A + (long)gr * lda + akg * 8;
            aR0 = *reinterpret_cast<const float4*>(p);
            aR1 = *reinterpret_cast<const float4*>(p + 4);
        } else {
            aR0 = aR1 = make_float4(0.f, 0.f, 0.f, 0.f);
        }
        const float* q = B + (long)bkr * ldb + bcol + bn4;
        bR0 = *reinterpret_cast<const float4*>(q);
        bR1 = *reinterpret_cast<const float4*>(q + 8L * ldb);
    }

    float acc[2][8][4] = {};

    for (int k0 = 0; k0 < K; k0 += 16) {
        As[akg * 8 + 0][am] = cvt_tf32(aR0.x);
        As[akg * 8 + 1][am] = cvt_tf32(aR0.y);
        As[akg * 8 + 2][am] = cvt_tf32(aR0.z);
        As[akg * 8 + 3][am] = cvt_tf32(aR0.w);
        As[akg * 8 + 4][am] = cvt_tf32(aR1.x);
        As[akg * 8 + 5][am] = cvt_tf32(aR1.y);
        As[akg * 8 + 6][am] = cvt_tf32(aR1.z);
        As[akg * 8 + 7][am] = cvt_tf32(aR1.w);
        uint4 bb0 = make_uint4(cvt_tf32(bR0.x), cvt_tf32(bR0.y), cvt_tf32(bR0.z), cvt_tf32(bR0.w));
        uint4 bb1 = make_uint4(cvt_tf32(bR1.x), cvt_tf32(bR1.y), cvt_tf32(bR1.z), cvt_tf32(bR1.w));
        *reinterpret_cast<uint4*>(&Bs[bkr][bn4]) = bb0;
        *reinterpret_cast<uint4*>(&Bs[bkr + 8][bn4]) = bb1;
        __syncthreads();

        if (k0 + 16 < K) {
            int gr = brow + am;
            if (gr < M) {
                const float* p = A + (long)gr * lda + k0 + 16 + akg * 8;
                aR0 = *reinterpret_cast<const float4*>(p);
                aR1 = *reinterpret_cast<const float4*>(p + 4);
            }
            const float* q = B + (long)(k0 + 16 + bkr) * ldb + bcol + bn4;
            bR0 = *reinterpret_cast<const float4*>(q);
            bR1 = *reinterpret_cast<const float4*>(q + 8L * ldb);
        }

#pragma unroll
        for (int kk = 0; kk < 16; kk += 8) {
            unsigned af[2][4];
#pragma unroll
            for (int mi = 0; mi < 2; mi++) {
                int m = wr + mi * 16;
                af[mi][0] = As[kk + tig][m + gid];
                af[mi][1] = As[kk + tig][m + gid + 8];
                af[mi][2] = As[kk + tig + 4][m + gid];
                af[mi][3] = As[kk + tig + 4][m + gid + 8];
            }
            unsigned bf[8][2];
#pragma unroll
            for (int ni = 0; ni < 8; ni++) {
                int n = wc + ni * 8;
                bf[ni][0] = Bs[kk + tig][n + gid];
                bf[ni][1] = Bs[kk + tig + 4][n + gid];
            }
#pragma unroll
            for (int mi = 0; mi < 2; mi++)
#pragma unroll
                for (int ni = 0; ni < 8; ni++) mma_tf32(acc[mi][ni], af[mi], bf[ni]);
        }
        __syncthreads();
    }

#pragma unroll
    for (int mi = 0; mi < 2; mi++) {
        int r0 = brow + wr + mi * 16 + gid;
#pragma unroll
        for (int ni = 0; ni < 8; ni++) {
            int c0 = bcol + wc + ni * 8 + tig * 2;
            if (r0 < M)
                *reinterpret_cast<float2*>(C + (long)r0 * ldc + c0) =
                    make_float2(acc[mi][ni][0], acc[mi][ni][1]);
            if (r0 + 8 < M)
                *reinterpret_cast<float2*>(C + (long)(r0 + 8) * ldc + c0) =
                    make_float2(acc[mi][ni][2], acc[mi][ni][3]);
        }
    }
}

// ---------------- GAT: es/ed dot products (batched) ----------------
__global__ void esd_k(const float* __restrict__ hf, const float* __restrict__ as,
                      const float* __restrict__ ad, float* __restrict__ es,
                      float* __restrict__ ed) {
    int n = blockIdx.x, b = blockIdx.y;
    int h = threadIdx.x >> 5, lane = threadIdx.x & 31;
    const float* r = hf + ((long)(b * NHEAD + h) * NNODE + n) * DIM;
    float s = 0.f, t = 0.f;
#pragma unroll
    for (int d = lane; d < DIM; d += 32) {
        float v = r[d];
        s += v * as[h * DIM + d];
        t += v * ad[h * DIM + d];
    }
#pragma unroll
    for (int o = 16; o; o >>= 1) {
        s += __shfl_xor_sync(0xffffffffu, s, o);
        t += __shfl_xor_sync(0xffffffffu, t, o);
    }
    if (!lane) {
        es[(long)(b * NHEAD + h) * NNODE + n] = s;
        ed[(long)(b * NHEAD + h) * NNODE + n] = t;
    }
}

// ---------------- GAT aggregate + elu + normalize (batched) ----------------
__global__ void gat_agg_k(const int* __restrict__ cols, const int* __restrict__ cnt,
                          const float* __restrict__ hf, const float* __restrict__ es,
                          const float* __restrict__ ed, float* __restrict__ seq, int slot) {
    __shared__ int sc[KMAX];
    __shared__ float sw[NHEAD][KMAX];
    __shared__ float sh[8];
    int n = blockIdx.x, b = blockIdx.y, tid = threadIdx.x;
    long goff = (long)b * NNODE;
    int c = cnt[goff + n];
    for (int j = tid; j < c; j += DIM) sc[j] = cols[(goff + n) * KMAX + j];
    __syncthreads();
    int w = tid >> 5, lane = tid & 31;
    if (w < NHEAD) {
        const float* edp = ed + (long)(b * NHEAD + w) * NNODE;
        float e0 = es[(long)(b * NHEAD + w) * NNODE + n];
        float m = -1e30f;
        for (int j = lane; j < c; j += 32) {
            float e = e0 + edp[sc[j]];
            e = e > 0.f ? e : 0.2f * e;
            sw[w][j] = e;
            m = fmaxf(m, e);
        }
#pragma unroll
        for (int o = 16; o; o >>= 1) m = fmaxf(m, __shfl_xor_sync(0xffffffffu, m, o));
        float s = 0.f;
        for (int j = lane; j < c; j += 32) {
            float e = expf(sw[w][j] - m);
            sw[w][j] = e;
            s += e;
        }
#pragma unroll
        for (int o = 16; o; o >>= 1) s += __shfl_xor_sync(0xffffffffu, s, o);
        float inv = 1.f / s;
        for (int j = lane; j < c; j += 32) sw[w][j] *= inv;
    }
    __syncthreads();
    const float* hf0 = hf + (long)(b * NHEAD) * NNODE * DIM;
    const float* hf1 = hf0 + (long)NNODE * DIM;
    float a0 = 0.f, a1 = 0.f;
    for (int j = 0; j < c; j++) {
        long cc = sc[j];
        a0 += sw[0][j] * hf0[cc * DIM + tid];
        a1 += sw[1][j] * hf1[cc * DIM + tid];
    }
    float v = 0.5f * (a0 + a1);
    v = v > 0.f ? v : expm1f(v);
    float ss = bsum(v * v, sh);
    float nrm = fmaxf(sqrtf(ss), 1e-12f);
    seq[((goff + n) * LSEQ + slot) * DIM + tid] = v / nrm;
}

// ---------------- attention: e = y.x dots, softmax, z = attn @ x -----------
__global__ void attn_z_k(const float* __restrict__ seq, const float* __restrict__ y,
                         float* __restrict__ z) {
    __shared__ float sx[LSEQ][DIM];
    __shared__ float sy[NHEAD][LSEQ][DIM];
    __shared__ float se[NHEAD][LSEQ][LSEQ];
    int r = blockIdx.x, tid = threadIdx.x, w = tid >> 5, lane = tid & 31;
    long r3 = (long)r * LSEQ;
    for (int i = tid; i < LSEQ * DIM; i += 128) sx[i >> 7][i & 127] = seq[r3 * DIM + i];
    for (int i = tid; i < NHEAD * LSEQ * DIM; i += 128) {
        int h = i / (LSEQ * DIM), rem = i % (LSEQ * DIM);
        sy[h][rem >> 7][rem & 127] = y[(long)h * 4608000L + r3 * DIM + rem];
    }
    __syncthreads();
    for (int idx = w; idx < NHEAD * LSEQ * LSEQ; idx += 4) {
        int h = idx / 9, rem = idx % 9, l = rem / 3, m = rem % 3;
        float s = 0.f;
#pragma unroll
        for (int d = lane; d < DIM; d += 32) s += sy[h][l][d] * sx[m][d];
#pragma unroll
        for (int o = 16; o; o >>= 1) s += __shfl_xor_sync(0xffffffffu, s, o);
        if (!lane) se[h][l][m] = s;
    }
    __syncthreads();
    if (tid < NHEAD * LSEQ) {
        int h = tid / 3, l = tid % 3;
        float m = fmaxf(se[h][l][0], fmaxf(se[h][l][1], se[h][l][2]));
        float e0 = expf(se[h][l][0] - m), e1 = expf(se[h][l][1] - m), e2 = expf(se[h][l][2] - m);
        float inv = 1.f / (e0 + e1 + e2);
        se[h][l][0] = e0 * inv;
        se[h][l][1] = e1 * inv;
        se[h][l][2] = e2 * inv;
    }
    __syncthreads();
    int d = tid;
    for (int l = 0; l < LSEQ; l++)
#pragma unroll
        for (int h = 0; h < NHEAD; h++) {
            float a = se[h][l][0] * sx[0][d] + se[h][l][1] * sx[1][d] + se[h][l][2] * sx[2][d];
            z[(r3 + l) * 256 + h * DIM + d] = a;
        }
}

// ---------------- MHA epilogue (batched) ----------------
__global__ void mha_epi_k(const float* __restrict__ op, const float* __restrict__ seq,
                          const float* __restrict__ relb, const float* __restrict__ lng,
                          const float* __restrict__ lnb, float* __restrict__ out) {
    __shared__ float sh[8];
    int n = blockIdx.x, b = blockIdx.y, d = threadIdx.x;
    long r = (long)b * NNODE + n;
    float acc = 0.f;
    for (int l = 0; l < LSEQ; l++) {
        long idx = (r * LSEQ + l) * DIM + d;
        float v = op[idx] + seq[idx];
        float mu = bsum(v, sh) * (1.f / DIM);
        float dv = v - mu;
        float var = bsum(dv * dv, sh) * (1.f / DIM);
        acc += lng[d] * dv * rsqrtf(var + 1e-6f) + lnb[d];
    }
    float* row = out + (long)b * NNODE * 2 * DIM + (long)n * 2 * DIM;
    row[d] = acc * (1.f / 3.f);
    row[DIM + d] = relb[r * DIM + d];
}

// expmap0+proj, mobius_add(.,hb), proj, logmap0 (batched)
__global__ void hgc_mid_k(const float* __restrict__ mv, const float* __restrict__ hb,
                          const float* __restrict__ hbn2, int layer, float* __restrict__ t2) {
    __shared__ float sh[8];
    int n = blockIdx.x, b = blockIdx.y, d = threadIdx.x;
    long r = (long)b * NNODE + n;
    float x0 = mv[r * DIM + d];
    float hbv = hb[layer * DIM + d];
    float y2 = hbn2[layer];
    float ss = bsum(x0 * x0, sh);
    float nn = fmaxf(sqrtf(ss), 1e-15f);
    float t = tanhf(nn);
    float a = t / nn;
    if (t > MAXNF) a *= MAXNF / t;
    float xd = a * x0;
    float x2, xy;
    bsum2(xd * xd, xd * hbv, sh, &x2, &xy);
    float num = (1.f + 2.f * xy + y2) * xd + (1.f - x2) * hbv;
    float den = fmaxf(1.f + 2.f * xy + x2 * y2, 1e-15f);
    float h2 = num / den;
    float ss2 = bsum(h2 * h2, sh);
    float nh = fmaxf(sqrtf(ss2), 1e-15f);
    float c = 1.f, npn = nh;
    if (nh > MAXNF) { c = MAXNF / nh; npn = MAXNF; }
    float p = fmaxf(npn, 1e-15f);
    float s = atanhf(fminf(p, 1.0f - 1e-7f)) / p;
    t2[r * DIM + d] = s * c * h2;
}

// sparse agg + expmap0/proj + relu(logmap0) + expmap0/proj + logmap0 fused.
// last != 0: write final output rows (ent + t, relb concat) instead of tout.
__global__ void hgc_agg_k(const int* __restrict__ cols, const float* __restrict__ vals,
                          const int* __restrict__ cnt, const float* __restrict__ tin,
                          float* __restrict__ tout, int last,
                          const float* __restrict__ e0, const float* __restrict__ e1,
                          const float* __restrict__ relb, float* __restrict__ out) {
    __shared__ int sc[KMAX];
    __shared__ float svv[KMAX];
    __shared__ float sh[8];
    int n = blockIdx.x, b = blockIdx.y, d = threadIdx.x;
    long goff = (long)b * NNODE;
    int c = cnt[goff + n];
    for (int j = d; j < c; j += DIM) {
        sc[j] = cols[(goff + n) * KMAX + j];
        svv[j] = vals[(goff + n) * KMAX + j];
    }
    __syncthreads();
    const float* tb = tin + goff * DIM;
    float acc = 0.f;
    for (int j = 0; j < c; j++) acc += svv[j] * tb[(long)sc[j] * DIM + d];
    float ss = bsum(acc * acc, sh);
    float nn = fmaxf(sqrtf(ss), 1e-15f);
    float t = tanhf(nn);
    float a = t / nn;
    if (t > MAXNF) a *= MAXNF / t;
    float pd = a * acc;
    float rp = fmaxf(pd, 0.f);
    float p2, r2;
    bsum2(pd * pd, rp * rp, sh, &p2, &r2);
    float npn = fmaxf(sqrtf(p2), 1e-15f);
    float beta = atanhf(fminf(npn, 1.0f - 1e-7f)) / npn;
    float t3 = beta * rp;
    float n3 = fmaxf(beta * sqrtf(r2), 1e-15f);
    float tt = tanhf(n3);
    float aa = tt / n3;
    if (tt > MAXNF) aa *= MAXNF / tt;
    float nh = fmaxf(aa * n3, 1e-15f);
    float s2 = atanhf(fminf(nh, 1.0f - 1e-7f)) / nh;
    float tv = s2 * aa * t3;
    if (!last) {
        tout[(goff + n) * DIM + d] = tv;
    } else {
        const float* x = b ? e1 : e0;
        float* row = out + (long)b * NNODE * 2 * DIM + (long)n * 2 * DIM;
        row[d] = x[(long)n * DIM + d] + tv;
        row[DIM + d] = relb[(goff + n) * DIM + d];
    }
}

// ---------------- host ----------------
extern "C" void kernel_launch(void* const* d_in, const int* in_sizes, int n_in,
                              void* d_out, int out_size) {
    (void)in_sizes; (void)n_in; (void)out_size;
    const float* ent0 = (const float*)d_in[0];
    const float* ent1 = (const float*)d_in[1];
    const float* rel0 = (const float*)d_in[2];
    const float* rel1 = (const float*)d_in[3];
    const float* adj0 = (const float*)d_in[4];
    const float* adj1 = (const float*)d_in[5];
    const float* radj0 = (const float*)d_in[6];
    const float* radj1 = (const float*)d_in[7];
    const float* gatW = (const float*)d_in[8];
    const float* aS = (const float*)d_in[9];
    const float* aD = (const float*)d_in[10];
    const float* Wq = (const float*)d_in[11];
    const float* Wk = (const float*)d_in[12];
    const float* Wv = (const float*)d_in[13];
    const float* Wfc = (const float*)d_in[14];
    const float* lng = (const float*)d_in[15];
    const float* lnb = (const float*)d_in[16];
    const float* hgcW = (const float*)d_in[17];
    const float* hgcb = (const float*)d_in[18];
    float* out = (float*)d_out;

    float* base = nullptr;
    cudaGetSymbolAddress((void**)&base, g_buf);

    int* ecols = (int*)(base + O_ECOLS);
    float* evals = base + O_EVALS;
    int* ecnt = (int*)(base + O_ECNT);
    float* grel = base + O_REL;
    float* gseq = base + O_SEQ;
    float* ghf = base + O_HF;
    float* ges = base + O_ES;
    float* ged = base + O_ED;
    float* gy = base + O_Y;
    float* gz = base + O_Z;
    float* gop = base + O_OP;
    float* gmv = base + O_MV;
    float* gt2 = base + O_T2;
    float* gtout = base + O_TOUT;
    float* gwt = base + O_WT;
    float* ghb = base + O_HB;
    float* ghbn2 = base + O_HBN2;
    float* gA = base + O_A;
    float* gG = base + O_G;

    const long BSEQ = (long)NNODE * LSEQ * DIM;
    const long BND = (long)NNODE * DIM;

    // ---- one mega preprocessing launch (all tasks independent) ----
    setup_all_k<<<NB_TOTAL, 256>>>(adj0, adj1, radj0, radj1, rel0, rel1, hgcW, hgcb,
                                   Wq, Wk, Wv, Wfc, ent0, ent1,
                                   ecols, evals, ecnt, grel, gwt, ghb, ghbn2,
                                   gA, gG, gseq, gtout);

    // ---- GAT x2 layers, both branches + both heads batched (z=4) ----
    for (int layer = 0; layer < 2; layer++) {
        gemm_tc_k<<<dim3(1, 47, 4), 256>>>(
            gseq + (long)layer * DIM, gatW + (long)layer * NHEAD * DIM * DIM, ghf,
            NNODE, DIM, DIM, LSEQ * DIM, DIM, DIM,
            BSEQ, NHEAD, (long)DIM * DIM, NHEAD, BND);
        esd_k<<<dim3(NNODE, 2), 64>>>(ghf, aS + layer * NHEAD * DIM, aD + layer * NHEAD * DIM,
                                      ges, ged);
        gat_agg_k<<<dim3(NNODE, 2), DIM>>>(ecols, ecnt, ghf, ges, ged, gseq, layer + 1);
    }

    // ---- MHA via folded weights ----
    gemm_tc_k<<<dim3(1, 282, 2), 256>>>(gseq, gA, gy, 2 * NNODE * LSEQ, DIM, DIM,
                                        DIM, DIM, DIM, 0, 1, (long)DIM * DIM, 2,
                                        (long)2 * NNODE * LSEQ * DIM);
    attn_z_k<<<2 * NNODE, 128>>>(gseq, gy, gz);
    gemm_tc_k<<<dim3(1, 282, 1), 256>>>(gz, gG, gop, 2 * NNODE * LSEQ, DIM, 2 * DIM,
                                        2 * DIM, DIM, DIM, 0, 1, 0, 1, 0);
    mha_epi_k<<<dim3(NNODE, 2), DIM>>>(gop, gseq, grel, lng, lnb, out);

    // ---- hyperbolic encoder (z=2 batched) ----
    for (int i = 0; i < 2; i++) {
        gemm_tc_k<<<dim3(1, 47, 2), 256>>>(gtout, gwt + (long)i * DIM * DIM, gmv,
                                           NNODE, DIM, DIM, DIM, DIM, DIM,
                                           BND, 1, 0, 1, BND);
        hgc_mid_k<<<dim3(NNODE, 2), DIM>>>(gmv, ghb, ghbn2, i, gt2);
        hgc_agg_k<<<dim3(NNODE, 2), DIM>>>(ecols, evals, ecnt, gt2, gtout, i == 1,
                                           ent0, ent1, grel, out + 2L * NNODE * 2 * DIM);
    }
}

// round 12
// speedup vs baseline: 2.0911x; 1.0233x over previous
#include <cuda_runtime.h>
#include <math.h>

#define NNODE 6000
#define DIM   128
#define RREL  1000
#define NHEAD 2
#define LSEQ  3
#define KMAX  128
#define MAXNF 0.996f

// ---------------- scratch pool ----------------
#define O_ECOLS 0L                            // int [2][NNODE][KMAX]
#define O_EVALS (O_ECOLS + 1536000L)
#define O_ECNT  (O_EVALS + 1536000L)          // int [2][NNODE]
#define O_REL   (O_ECNT + 12032L)             // float[2][NNODE][DIM]
#define O_SEQ   (O_REL + 1536000L)            // float[2][NNODE][LSEQ][DIM]
#define O_HF    (O_SEQ + 4608000L)            // float[2][NHEAD][NNODE][DIM]
#define O_ES    (O_HF + 3072000L)             // float[2*NHEAD*NNODE]
#define O_ED    (O_ES + 24064L)
#define O_Y     (O_ED + 24064L)               // float[2][36000][128]
#define O_Z     (O_Y + 9216000L)              // float[36000][256]
#define O_OP    (O_Z + 9216000L)              // float[36000][128]
#define O_MV    (O_OP + 4608000L)             // float[2][NNODE][DIM]
#define O_T2    (O_MV + 1536000L)
#define O_TOUT  (O_T2 + 1536000L)
#define O_WT    (O_TOUT + 1536000L)           // float[2*DIM*DIM]
#define O_HB    (O_WT + 32768L)
#define O_HBN2  (O_HB + 256L)
#define O_A     (O_HBN2 + 32L)                // float[2][128][128]
#define O_G     (O_A + 32768L)                // float[256][128]
#define TOTALF  (O_G + 32768L)

__device__ __align__(256) float g_buf[TOTALF];

// ---------------- block reduction helpers (128 active threads) -------------
__device__ __forceinline__ float bsum(float v, float* sh) {
#pragma unroll
    for (int o = 16; o; o >>= 1) v += __shfl_xor_sync(0xffffffffu, v, o);
    int w = threadIdx.x >> 5;
    if ((threadIdx.x & 31) == 0) sh[w] = v;
    __syncthreads();
    float r = sh[0] + sh[1] + sh[2] + sh[3];
    __syncthreads();
    return r;
}

__device__ __forceinline__ void bsum2(float a, float b, float* sh, float* ra, float* rb) {
#pragma unroll
    for (int o = 16; o; o >>= 1) {
        a += __shfl_xor_sync(0xffffffffu, a, o);
        b += __shfl_xor_sync(0xffffffffu, b, o);
    }
    int w = threadIdx.x >> 5;
    if ((threadIdx.x & 31) == 0) { sh[w] = a; sh[4 + w] = b; }
    __syncthreads();
    *ra = sh[0] + sh[1] + sh[2] + sh[3];
    *rb = sh[4] + sh[5] + sh[6] + sh[7];
    __syncthreads();
}

// ---------------- mega setup kernel: all independent preprocessing ---------
#define NB_PREP 32
#define NB_SETW 258
#define NB_ELL  1500
#define NB_REL  12000
#define NB_INIT 12000
#define NB_TOTAL (NB_PREP + NB_SETW + NB_ELL + NB_REL + NB_INIT)

__global__ __launch_bounds__(256) void setup_all_k(
    const float* __restrict__ adj0, const float* __restrict__ adj1,
    const float* __restrict__ radj0, const float* __restrict__ radj1,
    const float* __restrict__ rel0, const float* __restrict__ rel1,
    const float* __restrict__ hgcW, const float* __restrict__ hgcb,
    const float* __restrict__ Wq, const float* __restrict__ Wk,
    const float* __restrict__ Wv, const float* __restrict__ Wfc,
    const float* __restrict__ e0, const float* __restrict__ e1,
    int* __restrict__ ecols, float* __restrict__ evals, int* __restrict__ ecnt,
    float* __restrict__ grel, float* __restrict__ WT, float* __restrict__ hb,
    float* __restrict__ hbn2, float* __restrict__ Am, float* __restrict__ G,
    float* __restrict__ seq, float* __restrict__ tout) {
    __shared__ __align__(16) char smraw[18688];
    int bid = blockIdx.x;
    int tid = threadIdx.x;

    if (bid < NB_PREP) {
        float (*sA)[33] = reinterpret_cast<float(*)[33]>(smraw);
        float (*sB)[129] = reinterpret_cast<float(*)[129]>(smraw + 2112);
        int mat = bid >> 3;
        int h = mat & 1;
        int row0 = (bid & 7) * 16;
        int r = tid >> 4;
        int cb = tid & 15;
        float acc[8] = {};
        const float* Asrc = (mat < 2) ? Wq : Wv;
        for (int k0 = 0; k0 < 128; k0 += 32) {
            for (int i = tid; i < 16 * 32; i += 256) {
                int rr = i >> 5, jj = i & 31;
                sA[rr][jj] = Asrc[(row0 + rr) * 256 + h * 128 + k0 + jj];
            }
            if (mat < 2) {
                for (int i = tid; i < 32 * 128; i += 256) {
                    int t = i >> 5, jj = i & 31;
                    sB[jj][t] = Wk[t * 256 + h * 128 + k0 + jj];
                }
            } else {
                for (int i = tid; i < 32 * 128; i += 256) {
                    int jj = i >> 7, t = i & 127;
                    sB[jj][t] = Wfc[(h * 128 + k0 + jj) * 128 + t];
                }
            }
            __syncthreads();
#pragma unroll
            for (int j = 0; j < 32; j++) {
                float a = sA[r][j];
#pragma unroll
                for (int i = 0; i < 8; i++) acc[i] += a * sB[j][cb + 16 * i];
            }
            __syncthreads();
        }
        float scale = (mat < 2) ? 0.08838834764831845f : 1.f;
        float* dst = ((mat < 2) ? Am : G) + (long)(h * 128 + row0 + r) * 128;
#pragma unroll
        for (int i = 0; i < 8; i++) dst[cb + 16 * i] = acc[i] * scale;
        return;
    }
    bid -= NB_PREP;

    if (bid < NB_SETW) {
        if (tid >= 128) return;
        float* sh = (float*)smraw;
        int i = bid & 1, yy = bid >> 1, d = tid;
        if (yy < 128) {
            WT[(long)i * 16384 + (long)d * 128 + yy] = hgcW[(long)i * 16384 + (long)yy * 128 + d];
        } else {
            float v = hgcb[i * DIM + d];
            float ss = bsum(v * v, sh);
            float nn = fmaxf(sqrtf(ss), 1e-15f);
            float t = tanhf(nn);
            float a = t / nn;
            if (t > MAXNF) a *= MAXNF / t;
            float hv = a * v;
            hb[i * DIM + d] = hv;
            float s2 = bsum(hv * hv, sh);
            if (!d) hbn2[i] = s2;
        }
        return;
    }
    bid -= NB_SETW;

    if (bid < NB_ELL) {
        int b = bid / 750;
        const float* adj = b ? adj1 : adj0;
        long off = (long)b * NNODE;
        int row = (bid % 750) * 8 + (tid >> 5);
        int lane = tid & 31;
        const float* arow = adj + (long)row * NNODE;
        int c = 0;
        for (int base = 0; base < NNODE; base += 128) {
            int col = base + lane * 4;
            float4 v = make_float4(0.f, 0.f, 0.f, 0.f);
            if (col < NNODE) v = *reinterpret_cast<const float4*>(arow + col);
            float vv[4] = {v.x, v.y, v.z, v.w};
            int lc = (vv[0] != 0.f) + (vv[1] != 0.f) + (vv[2] != 0.f) + (vv[3] != 0.f);
            int pre = lc;
#pragma unroll
            for (int o = 1; o < 32; o <<= 1) {
                int t = __shfl_up_sync(0xffffffffu, pre, o);
                if (lane >= o) pre += t;
            }
            int tot = __shfl_sync(0xffffffffu, pre, 31);
            int p = c + pre - lc;
#pragma unroll
            for (int i = 0; i < 4; i++)
                if (vv[i] != 0.f && p < KMAX) {
                    ecols[(off + row) * KMAX + p] = col + i;
                    evals[(off + row) * KMAX + p] = vv[i];
                    p++;
                }
            c += tot;
        }
        if (!lane) ecnt[off + row] = (c < KMAX) ? c : KMAX;
        return;
    }
    bid -= NB_ELL;

    if (bid < NB_REL) {
        if (tid >= 128) return;
        int* sidx = (int*)smraw;
        int* wsum = (int*)(smraw + 1024);
        int b = bid / NNODE;
        const float* radj = b ? radj1 : radj0;
        const float* rel = b ? rel1 : rel0;
        int row = bid % NNODE, t = tid, lane = t & 31, w = t >> 5;
        int base = t * 8;
        float e[8];
#pragma unroll
        for (int i = 0; i < 8; i++) e[i] = 0.f;
        if (base < RREL) {
            float4 v0 = *reinterpret_cast<const float4*>(radj + (long)row * RREL + base);
            float4 v1 = *reinterpret_cast<const float4*>(radj + (long)row * RREL + base + 4);
            e[0] = v0.x; e[1] = v0.y; e[2] = v0.z; e[3] = v0.w;
            e[4] = v1.x; e[5] = v1.y; e[6] = v1.z; e[7] = v1.w;
        }
        int lc = 0;
#pragma unroll
        for (int i = 0; i < 8; i++) lc += (e[i] != 0.f);
        int pre = lc;
#pragma unroll
        for (int o = 1; o < 32; o <<= 1) {
            int s = __shfl_up_sync(0xffffffffu, pre, o);
            if (lane >= o) pre += s;
        }
        if (lane == 31) wsum[w] = pre;
        __syncthreads();
        int boff = 0;
        for (int k = 0; k < w; k++) boff += wsum[k];
        int total = wsum[0] + wsum[1] + wsum[2] + wsum[3];
        int p = boff + pre - lc;
#pragma unroll
        for (int i = 0; i < 8; i++)
            if (e[i] != 0.f && p < 256) sidx[p++] = base + i;
        __syncthreads();
        float acc = 0.f;
        for (int j = 0; j < total; j++) acc += rel[(long)sidx[j] * DIM + t];
        grel[((long)b * NNODE + row) * DIM + t] = acc / (float)total;
        return;
    }
    bid -= NB_REL;

    if (tid >= 128) return;
    {
        float* sh = (float*)smraw;
        int b = bid / NNODE;
        int n = bid % NNODE, d = tid;
        const float* x = b ? e1 : e0;
        float v = x[(long)n * DIM + d];
        long r = (long)b * NNODE + n;
        seq[r * LSEQ * DIM + d] = v;
        float ss = bsum(v * v, sh);
        float nn = fmaxf(sqrtf(ss), 1e-15f);
        float t = tanhf(nn);
        float a = t / nn;
        if (t > MAXNF) a = MAXNF / nn;
        float np = fmaxf(a * nn, 1e-15f);
        float s = atanhf(fminf(np, 1.0f - 1e-7f)) / np;
        tout[r * DIM + d] = s * a * v;
    }
}

// ---------------- tf32 tensor-core GEMM, 128x128x16 tiles ------------------
__device__ __forceinline__ unsigned cvt_tf32(float f) {
    unsigned r;
    asm("cvt.rna.tf32.f32 %0, %1;" : "=r"(r) : "f"(f));
    return r;
}

__device__ __forceinline__ void mma_tf32(float c[4], const unsigned a[4], const unsigned b[2]) {
    asm volatile(
        "mma.sync.aligned.m16n8k8.row.col.f32.tf32.tf32.f32 "
        "{%0,%1,%2,%3}, {%4,%5,%6,%7}, {%8,%9}, {%0,%1,%2,%3};"
        : "+f"(c[0]), "+f"(c[1]), "+f"(c[2]), "+f"(c[3])
        : "r"(a[0]), "r"(a[1]), "r"(a[2]), "r"(a[3]), "r"(b[0]), "r"(b[1]));
}

__global__ __launch_bounds__(256) void gemm_tc_k(
    const float* __restrict__ A, const float* __restrict__ B, float* __restrict__ C,
    int M, int Ncols, int K, int lda, int ldb, int ldc,
    long sA, int divA, long sB, int modB, long sC) {
    int z = blockIdx.z;
    A += (long)(z / divA) * sA;
    B += (long)(z % modB) * sB;
    C += (long)z * sC;
    __shared__ unsigned As[16][136];
    __shared__ unsigned Bs[16][136];
    int tid = threadIdx.x;
    int warp = tid >> 5, lane = tid & 31;
    int gid = lane >> 2, tig = lane & 3;
    int wr = (warp & 3) * 32;
    int wc = (warp >> 2) * 64;
    int brow = blockIdx.y * 128, bcol = blockIdx.x * 128;

    int am = tid & 127;
    int akg = tid >> 7;
    int bn4 = (tid & 31) * 4;
    int bkr = tid >> 5;

    float4 aR0, aR1, bR0, bR1;

    {
        int gr = brow + am;
        if (gr < M) {
            const float* p = A + (long)gr * lda + akg * 8;
            aR0 = *reinterpret_cast<const float4*>(p);
            aR1 = *reinterpret_cast<const float4*>(p + 4);
        } else {
            aR0 = aR1 = make_float4(0.f, 0.f, 0.f, 0.f);
        }
        const float* q = B + (long)bkr * ldb + bcol + bn4;
        bR0 = *reinterpret_cast<const float4*>(q);
        bR1 = *reinterpret_cast<const float4*>(q + 8L * ldb);
    }

    float acc[2][8][4] = {};

    for (int k0 = 0; k0 < K; k0 += 16) {
        As[akg * 8 + 0][am] = cvt_tf32(aR0.x);
        As[akg * 8 + 1][am] = cvt_tf32(aR0.y);
        As[akg * 8 + 2][am] = cvt_tf32(aR0.z);
        As[akg * 8 + 3][am] = cvt_tf32(aR0.w);
        As[akg * 8 + 4][am] = cvt_tf32(aR1.x);
        As[akg * 8 + 5][am] = cvt_tf32(aR1.y);
        As[akg * 8 + 6][am] = cvt_tf32(aR1.z);
        As[akg * 8 + 7][am] = cvt_tf32(aR1.w);
        uint4 bb0 = make_uint4(cvt_tf32(bR0.x), cvt_tf32(bR0.y), cvt_tf32(bR0.z), cvt_tf32(bR0.w));
        uint4 bb1 = make_uint4(cvt_tf32(bR1.x), cvt_tf32(bR1.y), cvt_tf32(bR1.z), cvt_tf32(bR1.w));
        *reinterpret_cast<uint4*>(&Bs[bkr][bn4]) = bb0;
        *reinterpret_cast<uint4*>(&Bs[bkr + 8][bn4]) = bb1;
        __syncthreads();

        if (k0 + 16 < K) {
            int gr = brow + am;
            if (gr < M) {
                const float* p = A + (long)gr * lda + k0 + 16 + akg * 8;
                aR0 = *reinterpret_cast<const float4*>(p);
                aR1 = *reinterpret_cast<const float4*>(p + 4);
            }
            const float* q = B + (long)(k0 + 16 + bkr) * ldb + bcol + bn4;
            bR0 = *reinterpret_cast<const float4*>(q);
            bR1 = *reinterpret_cast<const float4*>(q + 8L * ldb);
        }

#pragma unroll
        for (int kk = 0; kk < 16; kk += 8) {
            unsigned af[2][4];
#pragma unroll
            for (int mi = 0; mi < 2; mi++) {
                int m = wr + mi * 16;
                af[mi][0] = As[kk + tig][m + gid];
                af[mi][1] = As[kk + tig][m + gid + 8];
                af[mi][2] = As[kk + tig + 4][m + gid];
                af[mi][3] = As[kk + tig + 4][m + gid + 8];
            }
            unsigned bf[8][2];
#pragma unroll
            for (int ni = 0; ni < 8; ni++) {
                int n = wc + ni * 8;
                bf[ni][0] = Bs[kk + tig][n + gid];
                bf[ni][1] = Bs[kk + tig + 4][n + gid];
            }
#pragma unroll
            for (int mi = 0; mi < 2; mi++)
#pragma unroll
                for (int ni = 0; ni < 8; ni++) mma_tf32(acc[mi][ni], af[mi], bf[ni]);
        }
        __syncthreads();
    }

#pragma unroll
    for (int mi = 0; mi < 2; mi++) {
        int r0 = brow + wr + mi * 16 + gid;
#pragma unroll
        for (int ni = 0; ni < 8; ni++) {
            int c0 = bcol + wc + ni * 8 + tig * 2;
            if (r0 < M)
                *reinterpret_cast<float2*>(C + (long)r0 * ldc + c0) =
                    make_float2(acc[mi][ni][0], acc[mi][ni][1]);
            if (r0 + 8 < M)
                *reinterpret_cast<float2*>(C + (long)(r0 + 8) * ldc + c0) =
                    make_float2(acc[mi][ni][2], acc[mi][ni][3]);
        }
    }
}

// ---------------- GAT: es/ed dot products (batched, float4) ----------------
__global__ void esd_k(const float* __restrict__ hf, const float* __restrict__ as,
                      const float* __restrict__ ad, float* __restrict__ es,
                      float* __restrict__ ed) {
    int n = blockIdx.x, b = blockIdx.y;
    int h = threadIdx.x >> 5, lane = threadIdx.x & 31;
    const float4* r = reinterpret_cast<const float4*>(hf + ((long)(b * NHEAD + h) * NNODE + n) * DIM);
    const float4* a4 = reinterpret_cast<const float4*>(as + h * DIM);
    const float4* d4 = reinterpret_cast<const float4*>(ad + h * DIM);
    float4 v = r[lane];
    float4 av = a4[lane];
    float4 dv = d4[lane];
    float s = v.x * av.x + v.y * av.y + v.z * av.z + v.w * av.w;
    float t = v.x * dv.x + v.y * dv.y + v.z * dv.z + v.w * dv.w;
#pragma unroll
    for (int o = 16; o; o >>= 1) {
        s += __shfl_xor_sync(0xffffffffu, s, o);
        t += __shfl_xor_sync(0xffffffffu, t, o);
    }
    if (!lane) {
        es[(long)(b * NHEAD + h) * NNODE + n] = s;
        ed[(long)(b * NHEAD + h) * NNODE + n] = t;
    }
}

// ---------------- GAT aggregate + elu + normalize (unrolled gather) --------
__global__ void gat_agg_k(const int* __restrict__ cols, const int* __restrict__ cnt,
                          const float* __restrict__ hf, const float* __restrict__ es,
                          const float* __restrict__ ed, float* __restrict__ seq, int slot) {
    __shared__ int sc[KMAX];
    __shared__ float sw0[KMAX];
    __shared__ float sw1[KMAX];
    __shared__ float sh[8];
    int n = blockIdx.x, b = blockIdx.y, tid = threadIdx.x;
    long goff = (long)b * NNODE;
    int c = cnt[goff + n];
    for (int j = tid; j < c; j += DIM) sc[j] = cols[(goff + n) * KMAX + j];
    __syncthreads();
    int w = tid >> 5, lane = tid & 31;
    if (w < NHEAD) {
        float* sw = w ? sw1 : sw0;
        const float* edp = ed + (long)(b * NHEAD + w) * NNODE;
        float e0 = es[(long)(b * NHEAD + w) * NNODE + n];
        float m = -1e30f;
        for (int j = lane; j < c; j += 32) {
            float e = e0 + edp[sc[j]];
            e = e > 0.f ? e : 0.2f * e;
            sw[j] = e;
            m = fmaxf(m, e);
        }
#pragma unroll
        for (int o = 16; o; o >>= 1) m = fmaxf(m, __shfl_xor_sync(0xffffffffu, m, o));
        float s = 0.f;
        for (int j = lane; j < c; j += 32) {
            float e = expf(sw[j] - m);
            sw[j] = e;
            s += e;
        }
#pragma unroll
        for (int o = 16; o; o >>= 1) s += __shfl_xor_sync(0xffffffffu, s, o);
        float inv = 1.f / s;
        for (int j = lane; j < c; j += 32) sw[j] *= inv;
    }
    __syncthreads();
    const float* hf0 = hf + (long)(b * NHEAD) * NNODE * DIM + tid;
    const float* hf1 = hf0 + (long)NNODE * DIM;
    // 4-wide unrolled gather: 8 independent loads in flight
    float p00 = 0.f, p01 = 0.f, p02 = 0.f, p03 = 0.f;
    float p10 = 0.f, p11 = 0.f, p12 = 0.f, p13 = 0.f;
    int j = 0;
    for (; j + 4 <= c; j += 4) {
        long r0 = (long)sc[j] * DIM, r1 = (long)sc[j + 1] * DIM;
        long r2 = (long)sc[j + 2] * DIM, r3 = (long)sc[j + 3] * DIM;
        float v00 = hf0[r0], v01 = hf0[r1], v02 = hf0[r2], v03 = hf0[r3];
        float v10 = hf1[r0], v11 = hf1[r1], v12 = hf1[r2], v13 = hf1[r3];
        p00 += sw0[j] * v00;     p01 += sw0[j + 1] * v01;
        p02 += sw0[j + 2] * v02; p03 += sw0[j + 3] * v03;
        p10 += sw1[j] * v10;     p11 += sw1[j + 1] * v11;
        p12 += sw1[j + 2] * v12; p13 += sw1[j + 3] * v13;
    }
    for (; j < c; j++) {
        long rr = (long)sc[j] * DIM;
        p00 += sw0[j] * hf0[rr];
        p10 += sw1[j] * hf1[rr];
    }
    float a0 = (p00 + p01) + (p02 + p03);
    float a1 = (p10 + p11) + (p12 + p13);
    float v = 0.5f * (a0 + a1);
    v = v > 0.f ? v : expm1f(v);
    float ss = bsum(v * v, sh);
    float nrm = fmaxf(sqrtf(ss), 1e-12f);
    seq[((goff + n) * LSEQ + slot) * DIM + tid] = v / nrm;
}

// ---------------- attention: e = y.x dots, softmax, z = attn @ x -----------
__global__ void attn_z_k(const float* __restrict__ seq, const float* __restrict__ y,
                         float* __restrict__ z) {
    __shared__ float sx[LSEQ][DIM];
    __shared__ float sy[NHEAD][LSEQ][DIM];
    __shared__ float se[NHEAD][LSEQ][LSEQ];
    int r = blockIdx.x, tid = threadIdx.x, w = tid >> 5, lane = tid & 31;
    long r3 = (long)r * LSEQ;
    for (int i = tid; i < LSEQ * DIM; i += 128) sx[i >> 7][i & 127] = seq[r3 * DIM + i];
    for (int i = tid; i < NHEAD * LSEQ * DIM; i += 128) {
        int h = i / (LSEQ * DIM), rem = i % (LSEQ * DIM);
        sy[h][rem >> 7][rem & 127] = y[(long)h * 4608000L + r3 * DIM + rem];
    }
    __syncthreads();
    for (int idx = w; idx < NHEAD * LSEQ * LSEQ; idx += 4) {
        int h = idx / 9, rem = idx % 9, l = rem / 3, m = rem % 3;
        float s = 0.f;
#pragma unroll
        for (int d = lane; d < DIM; d += 32) s += sy[h][l][d] * sx[m][d];
#pragma unroll
        for (int o = 16; o; o >>= 1) s += __shfl_xor_sync(0xffffffffu, s, o);
        if (!lane) se[h][l][m] = s;
    }
    __syncthreads();
    if (tid < NHEAD * LSEQ) {
        int h = tid / 3, l = tid % 3;
        float m = fmaxf(se[h][l][0], fmaxf(se[h][l][1], se[h][l][2]));
        float e0 = expf(se[h][l][0] - m), e1 = expf(se[h][l][1] - m), e2 = expf(se[h][l][2] - m);
        float inv = 1.f / (e0 + e1 + e2);
        se[h][l][0] = e0 * inv;
        se[h][l][1] = e1 * inv;
        se[h][l][2] = e2 * inv;
    }
    __syncthreads();
    int d = tid;
    for (int l = 0; l < LSEQ; l++)
#pragma unroll
        for (int h = 0; h < NHEAD; h++) {
            float a = se[h][l][0] * sx[0][d] + se[h][l][1] * sx[1][d] + se[h][l][2] * sx[2][d];
            z[(r3 + l) * 256 + h * DIM + d] = a;
        }
}

// ---------------- MHA epilogue (batched) ----------------
__global__ void mha_epi_k(const float* __restrict__ op, const float* __restrict__ seq,
                          const float* __restrict__ relb, const float* __restrict__ lng,
                          const float* __restrict__ lnb, float* __restrict__ out) {
    __shared__ float sh[8];
    int n = blockIdx.x, b = blockIdx.y, d = threadIdx.x;
    long r = (long)b * NNODE + n;
    float acc = 0.f;
    for (int l = 0; l < LSEQ; l++) {
        long idx = (r * LSEQ + l) * DIM + d;
        float v = op[idx] + seq[idx];
        float mu = bsum(v, sh) * (1.f / DIM);
        float dv = v - mu;
        float var = bsum(dv * dv, sh) * (1.f / DIM);
        acc += lng[d] * dv * rsqrtf(var + 1e-6f) + lnb[d];
    }
    float* row = out + (long)b * NNODE * 2 * DIM + (long)n * 2 * DIM;
    row[d] = acc * (1.f / 3.f);
    row[DIM + d] = relb[r * DIM + d];
}

// expmap0+proj, mobius_add(.,hb), proj, logmap0 (batched)
__global__ void hgc_mid_k(const float* __restrict__ mv, const float* __restrict__ hb,
                          const float* __restrict__ hbn2, int layer, float* __restrict__ t2) {
    __shared__ float sh[8];
    int n = blockIdx.x, b = blockIdx.y, d = threadIdx.x;
    long r = (long)b * NNODE + n;
    float x0 = mv[r * DIM + d];
    float hbv = hb[layer * DIM + d];
    float y2 = hbn2[layer];
    float ss = bsum(x0 * x0, sh);
    float nn = fmaxf(sqrtf(ss), 1e-15f);
    float t = tanhf(nn);
    float a = t / nn;
    if (t > MAXNF) a *= MAXNF / t;
    float xd = a * x0;
    float x2, xy;
    bsum2(xd * xd, xd * hbv, sh, &x2, &xy);
    float num = (1.f + 2.f * xy + y2) * xd + (1.f - x2) * hbv;
    float den = fmaxf(1.f + 2.f * xy + x2 * y2, 1e-15f);
    float h2 = num / den;
    float ss2 = bsum(h2 * h2, sh);
    float nh = fmaxf(sqrtf(ss2), 1e-15f);
    float c = 1.f, npn = nh;
    if (nh > MAXNF) { c = MAXNF / nh; npn = MAXNF; }
    float p = fmaxf(npn, 1e-15f);
    float s = atanhf(fminf(p, 1.0f - 1e-7f)) / p;
    t2[r * DIM + d] = s * c * h2;
}

// sparse agg + hyperbolic chain fused; last writes final output rows
__global__ void hgc_agg_k(const int* __restrict__ cols, const float* __restrict__ vals,
                          const int* __restrict__ cnt, const float* __restrict__ tin,
                          float* __restrict__ tout, int last,
                          const float* __restrict__ e0, const float* __restrict__ e1,
                          const float* __restrict__ relb, float* __restrict__ out) {
    __shared__ int sc[KMAX];
    __shared__ float svv[KMAX];
    __shared__ float sh[8];
    int n = blockIdx.x, b = blockIdx.y, d = threadIdx.x;
    long goff = (long)b * NNODE;
    int c = cnt[goff + n];
    for (int j = d; j < c; j += DIM) {
        sc[j] = cols[(goff + n) * KMAX + j];
        svv[j] = vals[(goff + n) * KMAX + j];
    }
    __syncthreads();
    const float* tb = tin + goff * DIM + d;
    float q0 = 0.f, q1 = 0.f, q2 = 0.f, q3 = 0.f;
    int j = 0;
    for (; j + 4 <= c; j += 4) {
        long r0 = (long)sc[j] * DIM, r1 = (long)sc[j + 1] * DIM;
        long r2 = (long)sc[j + 2] * DIM, r3 = (long)sc[j + 3] * DIM;
        q0 += svv[j] * tb[r0];
        q1 += svv[j + 1] * tb[r1];
        q2 += svv[j + 2] * tb[r2];
        q3 += svv[j + 3] * tb[r3];
    }
    for (; j < c; j++) q0 += svv[j] * tb[(long)sc[j] * DIM];
    float acc = (q0 + q1) + (q2 + q3);
    float ss = bsum(acc * acc, sh);
    float nn = fmaxf(sqrtf(ss), 1e-15f);
    float t = tanhf(nn);
    float a = t / nn;
    if (t > MAXNF) a *= MAXNF / t;
    float pd = a * acc;
    float rp = fmaxf(pd, 0.f);
    float p2, r2;
    bsum2(pd * pd, rp * rp, sh, &p2, &r2);
    float npn = fmaxf(sqrtf(p2), 1e-15f);
    float beta = atanhf(fminf(npn, 1.0f - 1e-7f)) / npn;
    float t3 = beta * rp;
    float n3 = fmaxf(beta * sqrtf(r2), 1e-15f);
    float tt = tanhf(n3);
    float aa = tt / n3;
    if (tt > MAXNF) aa *= MAXNF / tt;
    float nh = fmaxf(aa * n3, 1e-15f);
    float s2 = atanhf(fminf(nh, 1.0f - 1e-7f)) / nh;
    float tv = s2 * aa * t3;
    if (!last) {
        tout[(goff + n) * DIM + d] = tv;
    } else {
        const float* x = b ? e1 : e0;
        float* row = out + (long)b * NNODE * 2 * DIM + (long)n * 2 * DIM;
        row[d] = x[(long)n * DIM + d] + tv;
        row[DIM + d] = relb[(goff + n) * DIM + d];
    }
}

// ---------------- host ----------------
extern "C" void kernel_launch(void* const* d_in, const int* in_sizes, int n_in,
                              void* d_out, int out_size) {
    (void)in_sizes; (void)n_in; (void)out_size;
    const float* ent0 = (const float*)d_in[0];
    const float* ent1 = (const float*)d_in[1];
    const float* rel0 = (const float*)d_in[2];
    const float* rel1 = (const float*)d_in[3];
    const float* adj0 = (const float*)d_in[4];
    const float* adj1 = (const float*)d_in[5];
    const float* radj0 = (const float*)d_in[6];
    const float* radj1 = (const float*)d_in[7];
    const float* gatW = (const float*)d_in[8];
    const float* aS = (const float*)d_in[9];
    const float* aD = (const float*)d_in[10];
    const float* Wq = (const float*)d_in[11];
    const float* Wk = (const float*)d_in[12];
    const float* Wv = (const float*)d_in[13];
    const float* Wfc = (const float*)d_in[14];
    const float* lng = (const float*)d_in[15];
    const float* lnb = (const float*)d_in[16];
    const float* hgcW = (const float*)d_in[17];
    const float* hgcb = (const float*)d_in[18];
    float* out = (float*)d_out;

    float* base = nullptr;
    cudaGetSymbolAddress((void**)&base, g_buf);

    int* ecols = (int*)(base + O_ECOLS);
    float* evals = base + O_EVALS;
    int* ecnt = (int*)(base + O_ECNT);
    float* grel = base + O_REL;
    float* gseq = base + O_SEQ;
    float* ghf = base + O_HF;
    float* ges = base + O_ES;
    float* ged = base + O_ED;
    float* gy = base + O_Y;
    float* gz = base + O_Z;
    float* gop = base + O_OP;
    float* gmv = base + O_MV;
    float* gt2 = base + O_T2;
    float* gtout = base + O_TOUT;
    float* gwt = base + O_WT;
    float* ghb = base + O_HB;
    float* ghbn2 = base + O_HBN2;
    float* gA = base + O_A;
    float* gG = base + O_G;

    const long BSEQ = (long)NNODE * LSEQ * DIM;
    const long BND = (long)NNODE * DIM;

    // ---- one mega preprocessing launch ----
    setup_all_k<<<NB_TOTAL, 256>>>(adj0, adj1, radj0, radj1, rel0, rel1, hgcW, hgcb,
                                   Wq, Wk, Wv, Wfc, ent0, ent1,
                                   ecols, evals, ecnt, grel, gwt, ghb, ghbn2,
                                   gA, gG, gseq, gtout);

    // ---- GAT x2 layers ----
    for (int layer = 0; layer < 2; layer++) {
        gemm_tc_k<<<dim3(1, 47, 4), 256>>>(
            gseq + (long)layer * DIM, gatW + (long)layer * NHEAD * DIM * DIM, ghf,
            NNODE, DIM, DIM, LSEQ * DIM, DIM, DIM,
            BSEQ, NHEAD, (long)DIM * DIM, NHEAD, BND);
        esd_k<<<dim3(NNODE, 2), 64>>>(ghf, aS + layer * NHEAD * DIM, aD + layer * NHEAD * DIM,
                                      ges, ged);
        gat_agg_k<<<dim3(NNODE, 2), DIM>>>(ecols, ecnt, ghf, ges, ged, gseq, layer + 1);
    }

    // ---- MHA via folded weights ----
    gemm_tc_k<<<dim3(1, 282, 2), 256>>>(gseq, gA, gy, 2 * NNODE * LSEQ, DIM, DIM,
                                        DIM, DIM, DIM, 0, 1, (long)DIM * DIM, 2,
                                        (long)2 * NNODE * LSEQ * DIM);
    attn_z_k<<<2 * NNODE, 128>>>(gseq, gy, gz);
    gemm_tc_k<<<dim3(1, 282, 1), 256>>>(gz, gG, gop, 2 * NNODE * LSEQ, DIM, 2 * DIM,
                                        2 * DIM, DIM, DIM, 0, 1, 0, 1, 0);
    mha_epi_k<<<dim3(NNODE, 2), DIM>>>(gop, gseq, grel, lng, lnb, out);

    // ---- hyperbolic encoder ----
    for (int i = 0; i < 2; i++) {
        gemm_tc_k<<<dim3(1, 47, 2), 256>>>(gtout, gwt + (long)i * DIM * DIM, gmv,
                                           NNODE, DIM, DIM, DIM, DIM, DIM,
                                           BND, 1, 0, 1, BND);
        hgc_mid_k<<<dim3(NNODE, 2), DIM>>>(gmv, ghb, ghbn2, i, gt2);
        hgc_agg_k<<<dim3(NNODE, 2), DIM>>>(ecols, evals, ecnt, gt2, gtout, i == 1,
                                           ent0, ent1, grel, out + 2L * NNODE * 2 * DIM);
    }
}